// round 1
// baseline (speedup 1.0000x reference)
#include <cuda_runtime.h>
#include <cstdint>

#define NN 50000
#define EE 800000
#define GG 100
#define HH 128
#define FF 128
#define NGAUSS 50
#define NLAYER 6

typedef unsigned long long u64;

// ---------------- scratch (static device globals; no allocation) ----------------
__device__ float g_eaT[(size_t)NGAUSS * EE];   // gaussian expansion, TRANSPOSED [g][e]
__device__ float g_C[EE];                      // cosine cutoff
__device__ float g_h[(size_t)NN * HH];         // node features
__device__ float g_xl[(size_t)NN * FF];        // h @ conv_w1
__device__ float g_agg[(size_t)NN * FF];       // scattered messages

// ---------------- helpers ----------------
__device__ __forceinline__ u64 pk2(float x, float y) {
    u64 r; asm("mov.b64 %0, {%1,%2};" : "=l"(r) : "f"(x), "f"(y)); return r;
}
__device__ __forceinline__ void fma2(u64& d, u64 a, u64 b) {
    asm("fma.rn.f32x2 %0, %1, %2, %0;" : "+l"(d) : "l"(a), "l"(b));
}
__device__ __forceinline__ float2 up2(u64 v) {
    float2 r; asm("mov.b64 {%0,%1}, %2;" : "=f"(r.x), "=f"(r.y) : "l"(v)); return r;
}
__device__ __forceinline__ void red4(float* p, float a, float b, float c, float d) {
    asm volatile("red.global.add.v4.f32 [%0], {%1,%2,%3,%4};"
                 :: "l"(p), "f"(a), "f"(b), "f"(c), "f"(d) : "memory");
}
__device__ __forceinline__ float ssp(float x) {
    // shifted softplus: softplus(x) - log(2), numerically stable
    return fmaxf(x, 0.0f) + __logf(1.0f + __expf(-fabsf(x))) - 0.69314718055994530942f;
}

// 128x128 output tile, 256 threads, 8x8 micro-tile per thread, f32x2-packed FMA.
// As: [K][132] (transposed, padded), Bs: [K][128] row-major.
template<int K>
__device__ __forceinline__ void gemm_tile(const float* __restrict__ As,
                                          const float* __restrict__ Bs,
                                          int ty, int tx, u64 acc[8][4]) {
    const float* ap = As + ty * 8;
    const float* bp = Bs + tx * 8;
#pragma unroll 4
    for (int k = 0; k < K; k++) {
        float4 a0 = *(const float4*)(ap + k * 132);
        float4 a1 = *(const float4*)(ap + k * 132 + 4);
        float4 b0 = *(const float4*)(bp + k * 128);
        float4 b1 = *(const float4*)(bp + k * 128 + 4);
        u64 bb0 = pk2(b0.x, b0.y), bb1 = pk2(b0.z, b0.w);
        u64 bb2 = pk2(b1.x, b1.y), bb3 = pk2(b1.z, b1.w);
        float a[8] = {a0.x, a0.y, a0.z, a0.w, a1.x, a1.y, a1.z, a1.w};
#pragma unroll
        for (int i = 0; i < 8; i++) {
            u64 aa = pk2(a[i], a[i]);
            fma2(acc[i][0], aa, bb0);
            fma2(acc[i][1], aa, bb1);
            fma2(acc[i][2], aa, bb2);
            fma2(acc[i][3], aa, bb3);
        }
    }
}

#define ZERO_ACC(acc) do { \
    _Pragma("unroll") for (int _i = 0; _i < 8; _i++) \
    _Pragma("unroll") for (int _j = 0; _j < 4; _j++) acc[_i][_j] = 0ull; } while (0)

// ---------------- kernels ----------------

__global__ void __launch_bounds__(256) k_geom(const float* __restrict__ pos,
                                              const int* __restrict__ ei) {
    int e = blockIdx.x * 256 + threadIdx.x;
    if (e >= EE) return;
    int s = ei[e], d = ei[EE + e];
    float dx = pos[3*s]   - pos[3*d];
    float dy = pos[3*s+1] - pos[3*d+1];
    float dz = pos[3*s+2] - pos[3*d+2];
    float dist = sqrtf(dx*dx + dy*dy + dz*dz);
    g_C[e] = 0.5f * (__cosf(dist * (3.14159265358979323846f / 10.0f)) + 1.0f);
    const float sp = 10.0f / 49.0f;
    const float coeff = -0.5f / (sp * sp);
#pragma unroll
    for (int g = 0; g < NGAUSS; g++) {
        float t = dist - (float)g * sp;
        g_eaT[(size_t)g * EE + e] = __expf(coeff * t * t);
    }
}

__global__ void __launch_bounds__(256) k_hinit(const int* __restrict__ atoms,
                                               const float* __restrict__ emb) {
    int idx = blockIdx.x * 256 + threadIdx.x;   // over NN*32 float4s
    if (idx >= NN * 32) return;
    int n = idx >> 5, q = idx & 31;
    ((float4*)g_h)[idx] = ((const float4*)emb)[atoms[n] * 32 + q];
}

__global__ void __launch_bounds__(256) k_zero_agg() {
    int idx = blockIdx.x * 256 + threadIdx.x;
    if (idx < NN * 32) ((float4*)g_agg)[idx] = make_float4(0.f, 0.f, 0.f, 0.f);
}

__global__ void k_zero_tail(float* out) {
    int t = threadIdx.x;
    if (t < 2 * GG) out[2 * NN + t] = 0.0f;
}

// xl = h @ conv_w1[l]   (no bias, no activation)
__global__ void __launch_bounds__(256) k_xl(const float* __restrict__ W) {
    extern __shared__ float sm[];
    float* As = sm;               // 128*132
    float* Bs = As + 128 * 132;   // 128*128
    int tid = threadIdx.x, ty = tid >> 4, tx = tid & 15;
    int row0 = blockIdx.x * 128;
    for (int i = tid; i < 128 * 32; i += 256) {
        int r = i & 127, kq = i >> 7;
        float4 v = make_float4(0.f, 0.f, 0.f, 0.f);
        int row = row0 + r;
        if (row < NN) v = *(const float4*)(g_h + (size_t)row * 128 + kq * 4);
        As[(kq*4+0)*132 + r] = v.x;
        As[(kq*4+1)*132 + r] = v.y;
        As[(kq*4+2)*132 + r] = v.z;
        As[(kq*4+3)*132 + r] = v.w;
    }
    for (int i = tid; i < 128 * 32; i += 256)
        ((float4*)Bs)[i] = ((const float4*)W)[i];
    __syncthreads();
    u64 acc[8][4]; ZERO_ACC(acc);
    gemm_tile<128>(As, Bs, ty, tx, acc);
#pragma unroll
    for (int i = 0; i < 8; i++) {
        int row = row0 + ty * 8 + i;
        if (row >= NN) continue;
        float v[8];
#pragma unroll
        for (int jp = 0; jp < 4; jp++) { float2 t2 = up2(acc[i][jp]); v[2*jp] = t2.x; v[2*jp+1] = t2.y; }
        *(float4*)(g_xl + (size_t)row * 128 + tx * 8)     = make_float4(v[0], v[1], v[2], v[3]);
        *(float4*)(g_xl + (size_t)row * 128 + tx * 8 + 4) = make_float4(v[4], v[5], v[6], v[7]);
    }
}

// Fused per-layer edge pipeline: W = (ssp(EA@w1+b1)@w2+b2)*C, then
// agg[dst] += xl[src] * W  (vector red, no W materialization)
__global__ void __launch_bounds__(256) k_edge(const int* __restrict__ ei,
        const float* __restrict__ w1, const float* __restrict__ b1,
        const float* __restrict__ w2, const float* __restrict__ b2) {
    extern __shared__ float sm[];
    float* As  = sm;                   // 128*132: EA_T then T1_T
    float* Bs  = As + 128 * 132;       // 128*128: w1 then w2
    float* sb1 = Bs + 128 * 128;
    float* sb2 = sb1 + 128;
    float* sct = sb2 + 128;
    int*   ssrc = (int*)(sct + 128);
    int*   sdst = ssrc + 128;
    int tid = threadIdx.x, ty = tid >> 4, tx = tid & 15;
    int e0 = blockIdx.x * 128;

    for (int i = tid; i < NGAUSS * 32; i += 256) {   // EA_T tile (coalesced along e)
        int g = i >> 5, q = i & 31;
        *(float4*)(As + g * 132 + q * 4) = *(const float4*)(g_eaT + (size_t)g * EE + e0 + q * 4);
    }
    for (int i = tid; i < NGAUSS * 32; i += 256)
        ((float4*)Bs)[i] = ((const float4*)w1)[i];
    if (tid < 128) {
        sb1[tid] = b1[tid]; sb2[tid] = b2[tid]; sct[tid] = g_C[e0 + tid];
        ssrc[tid] = ei[e0 + tid]; sdst[tid] = ei[EE + e0 + tid];
    }
    __syncthreads();

    u64 acc[8][4]; ZERO_ACC(acc);
    gemm_tile<NGAUSS>(As, Bs, ty, tx, acc);
    __syncthreads();   // everyone done reading As/Bs

    // T1 = ssp(acc + b1), stored transposed into As for GEMM2
#pragma unroll
    for (int i = 0; i < 8; i++) {
        int r = ty * 8 + i;
#pragma unroll
        for (int jp = 0; jp < 4; jp++) {
            float2 v = up2(acc[i][jp]);
            int c = tx * 8 + jp * 2;
            As[c * 132 + r]       = ssp(v.x + sb1[c]);
            As[(c + 1) * 132 + r] = ssp(v.y + sb1[c + 1]);
        }
    }
    for (int i = tid; i < 128 * 32; i += 256)
        ((float4*)Bs)[i] = ((const float4*)w2)[i];
    __syncthreads();

    ZERO_ACC(acc);
    gemm_tile<128>(As, Bs, ty, tx, acc);

    // epilogue: finish W, gather xl[src], vector-red into agg[dst]
#pragma unroll
    for (int i = 0; i < 8; i++) {
        int r = ty * 8 + i;
        float ct = sct[r];
        int srow = ssrc[r], drow = sdst[r];
        float w[8];
#pragma unroll
        for (int jp = 0; jp < 4; jp++) {
            float2 v = up2(acc[i][jp]);
            int c = tx * 8 + jp * 2;
            w[2*jp]   = (v.x + sb2[c]) * ct;
            w[2*jp+1] = (v.y + sb2[c + 1]) * ct;
        }
        float4 x0 = *(const float4*)(g_xl + (size_t)srow * 128 + tx * 8);
        float4 x1 = *(const float4*)(g_xl + (size_t)srow * 128 + tx * 8 + 4);
        float* dp = g_agg + (size_t)drow * 128 + tx * 8;
        red4(dp,     w[0]*x0.x, w[1]*x0.y, w[2]*x0.z, w[3]*x0.w);
        red4(dp + 4, w[4]*x1.x, w[5]*x1.y, w[6]*x1.z, w[7]*x1.w);
    }
}

// Fused node update: h += (ssp(agg@cw2 + cb2)) @ iw + ib
__global__ void __launch_bounds__(256) k_node(const float* __restrict__ W2, const float* __restrict__ b2,
                                              const float* __restrict__ Wi, const float* __restrict__ bi) {
    extern __shared__ float sm[];
    float* As  = sm;
    float* Bs  = As + 128 * 132;
    float* sb2 = Bs + 128 * 128;
    float* sbi = sb2 + 128;
    int tid = threadIdx.x, ty = tid >> 4, tx = tid & 15;
    int row0 = blockIdx.x * 128;

    for (int i = tid; i < 128 * 32; i += 256) {
        int r = i & 127, kq = i >> 7;
        float4 v = make_float4(0.f, 0.f, 0.f, 0.f);
        int row = row0 + r;
        if (row < NN) v = *(const float4*)(g_agg + (size_t)row * 128 + kq * 4);
        As[(kq*4+0)*132 + r] = v.x;
        As[(kq*4+1)*132 + r] = v.y;
        As[(kq*4+2)*132 + r] = v.z;
        As[(kq*4+3)*132 + r] = v.w;
    }
    for (int i = tid; i < 128 * 32; i += 256)
        ((float4*)Bs)[i] = ((const float4*)W2)[i];
    if (tid < 128) { sb2[tid] = b2[tid]; sbi[tid] = bi[tid]; }
    __syncthreads();

    u64 acc[8][4]; ZERO_ACC(acc);
    gemm_tile<128>(As, Bs, ty, tx, acc);
    __syncthreads();

#pragma unroll
    for (int i = 0; i < 8; i++) {
        int r = ty * 8 + i;
#pragma unroll
        for (int jp = 0; jp < 4; jp++) {
            float2 v = up2(acc[i][jp]);
            int c = tx * 8 + jp * 2;
            As[c * 132 + r]       = ssp(v.x + sb2[c]);
            As[(c + 1) * 132 + r] = ssp(v.y + sb2[c + 1]);
        }
    }
    for (int i = tid; i < 128 * 32; i += 256)
        ((float4*)Bs)[i] = ((const float4*)Wi)[i];
    __syncthreads();

    ZERO_ACC(acc);
    gemm_tile<128>(As, Bs, ty, tx, acc);

#pragma unroll
    for (int i = 0; i < 8; i++) {
        int row = row0 + ty * 8 + i;
        if (row >= NN) continue;
        float v[8];
#pragma unroll
        for (int jp = 0; jp < 4; jp++) {
            float2 t2 = up2(acc[i][jp]);
            int c = tx * 8 + jp * 2;
            v[2*jp]   = t2.x + sbi[c];
            v[2*jp+1] = t2.y + sbi[c + 1];
        }
        float* hp = g_h + (size_t)row * 128 + tx * 8;
        float4 h0 = *(float4*)hp;
        float4 h1 = *(float4*)(hp + 4);
        h0.x += v[0]; h0.y += v[1]; h0.z += v[2]; h0.w += v[3];
        h1.x += v[4]; h1.y += v[5]; h1.z += v[6]; h1.w += v[7];
        *(float4*)hp = h0;
        *(float4*)(hp + 4) = h1;
    }
}

// readout: hh = ssp(h@lin1_w + lin1_b); e/q dots; segment sums via atomics
__global__ void __launch_bounds__(128) k_read(const int* __restrict__ batch,
        const float* __restrict__ lw, const float* __restrict__ lb,
        const float* __restrict__ ew, const float* __restrict__ ebp,
        const float* __restrict__ qw, const float* __restrict__ qbp,
        float* __restrict__ out) {
    extern __shared__ float sm[];
    float* Hs  = sm;                 // 128*129
    float* Ws  = Hs + 128 * 129;     // 128*64
    float* sb  = Ws + 128 * 64;      // 64
    float* sew = sb + 64;
    float* sqw = sew + 64;
    int tid = threadIdx.x;
    int row0 = blockIdx.x * 128;
    for (int i = tid; i < 128 * 128; i += 128) {
        int r = i >> 7, c = i & 127;
        int row = row0 + r;
        Hs[r * 129 + c] = (row < NN) ? g_h[(size_t)row * 128 + c] : 0.f;
    }
    for (int i = tid; i < 128 * 64; i += 128) Ws[i] = lw[i];
    if (tid < 64) { sb[tid] = lb[tid]; sew[tid] = ew[tid]; sqw[tid] = qw[tid]; }
    __syncthreads();
    int row = row0 + tid;
    if (row >= NN) return;
    float e = ebp[0], q = qbp[0];
    const float* hr = Hs + tid * 129;
#pragma unroll 2
    for (int j = 0; j < 64; j++) {
        float a = sb[j];
#pragma unroll 8
        for (int k = 0; k < 128; k++) a += hr[k] * Ws[k * 64 + j];
        float hh = ssp(a);
        e += hh * sew[j];
        q += hh * sqw[j];
    }
    out[row] = e;
    out[NN + row] = q;
    int b = batch[row];
    atomicAdd(out + 2 * NN + b, e);
    atomicAdd(out + 2 * NN + GG + b, q);
}

// ---------------- host ----------------
extern "C" void kernel_launch(void* const* d_in, const int* in_sizes, int n_in,
                              void* d_out, int out_size) {
    const int*   atoms = (const int*)d_in[0];
    const float* pos   = (const float*)d_in[1];
    const int*   batch = (const int*)d_in[2];
    const int*   ei    = (const int*)d_in[3];
    const float* emb   = (const float*)d_in[4];
    const float* mw1   = (const float*)d_in[5];
    const float* mb1   = (const float*)d_in[6];
    const float* mw2   = (const float*)d_in[7];
    const float* mb2   = (const float*)d_in[8];
    const float* cw1   = (const float*)d_in[9];
    const float* cw2   = (const float*)d_in[10];
    const float* cb2   = (const float*)d_in[11];
    const float* iw    = (const float*)d_in[12];
    const float* ib    = (const float*)d_in[13];
    const float* l1w   = (const float*)d_in[14];
    const float* l1b   = (const float*)d_in[15];
    const float* ew    = (const float*)d_in[16];
    const float* eb    = (const float*)d_in[17];
    const float* qw    = (const float*)d_in[18];
    const float* qb    = (const float*)d_in[19];
    float* out = (float*)d_out;

    constexpr int SMEM_GEMM = (128 * 132 + 128 * 128) * 4;
    constexpr int SMEM_NODE = SMEM_GEMM + 256 * 4;
    constexpr int SMEM_EDGE = SMEM_GEMM + 5 * 128 * 4;
    constexpr int SMEM_READ = (128 * 129 + 128 * 64 + 192) * 4;

    cudaFuncSetAttribute(k_xl,   cudaFuncAttributeMaxDynamicSharedMemorySize, SMEM_GEMM);
    cudaFuncSetAttribute(k_node, cudaFuncAttributeMaxDynamicSharedMemorySize, SMEM_NODE);
    cudaFuncSetAttribute(k_edge, cudaFuncAttributeMaxDynamicSharedMemorySize, SMEM_EDGE);
    cudaFuncSetAttribute(k_read, cudaFuncAttributeMaxDynamicSharedMemorySize, SMEM_READ);

    const int NODE_BLOCKS = (NN + 127) / 128;   // 391

    k_zero_tail<<<1, 256>>>(out);
    k_geom<<<(EE + 255) / 256, 256>>>(pos, ei);
    k_hinit<<<(NN * 32 + 255) / 256, 256>>>(atoms, emb);
    for (int l = 0; l < NLAYER; l++) {
        k_zero_agg<<<(NN * 32 + 255) / 256, 256>>>();
        k_xl<<<NODE_BLOCKS, 256, SMEM_GEMM>>>(cw1 + (size_t)l * HH * FF);
        k_edge<<<EE / 128, 256, SMEM_EDGE>>>(ei,
                mw1 + (size_t)l * NGAUSS * FF, mb1 + (size_t)l * FF,
                mw2 + (size_t)l * FF * FF,     mb2 + (size_t)l * FF);
        k_node<<<NODE_BLOCKS, 256, SMEM_NODE>>>(cw2 + (size_t)l * FF * HH, cb2 + (size_t)l * HH,
                                                iw  + (size_t)l * HH * HH, ib  + (size_t)l * HH);
    }
    k_read<<<NODE_BLOCKS, 128, SMEM_READ>>>(batch, l1w, l1b, ew, eb, qw, qb, out);
}

// round 3
// speedup vs baseline: 1.7844x; 1.7844x over previous
#include <cuda_runtime.h>
#include <cuda_bf16.h>
#include <cstdint>

#define NN 50000
#define EE 800000
#define GG 100
#define HH 128
#define FF 128
#define NGAUSS 50
#define NLAYER 6
#define NTILES (EE / 128)   // 6250

typedef unsigned long long u64;
typedef unsigned int u32;

// ---------------- scratch (static device globals; no allocation) ----------------
__device__ __nv_bfloat16 g_eaH[(size_t)EE * 64];   // gaussian expansion hi, [e][64] (padded 50->64)
__device__ __nv_bfloat16 g_eaL[(size_t)EE * 64];   // gaussian expansion lo
__device__ float g_C[EE];                          // cosine cutoff
__device__ float g_h[(size_t)NN * HH];             // node features
__device__ float g_xl[(size_t)NN * FF];            // h @ conv_w1
__device__ float g_agg[(size_t)NN * FF];           // scattered messages
// prepped transposed weights (per layer), bf16 hi/lo, [n][k] layout
__device__ __nv_bfloat16 g_w1tH[NLAYER * 128 * 64];
__device__ __nv_bfloat16 g_w1tL[NLAYER * 128 * 64];
__device__ __nv_bfloat16 g_w2tH[NLAYER * 128 * 128];
__device__ __nv_bfloat16 g_w2tL[NLAYER * 128 * 128];

// ---------------- generic helpers ----------------
__device__ __forceinline__ u64 pk2(float x, float y) {
    u64 r; asm("mov.b64 %0, {%1,%2};" : "=l"(r) : "f"(x), "f"(y)); return r;
}
__device__ __forceinline__ void fma2(u64& d, u64 a, u64 b) {
    asm("fma.rn.f32x2 %0, %1, %2, %0;" : "+l"(d) : "l"(a), "l"(b));
}
__device__ __forceinline__ float2 up2(u64 v) {
    float2 r; asm("mov.b64 {%0,%1}, %2;" : "=f"(r.x), "=f"(r.y) : "l"(v)); return r;
}
__device__ __forceinline__ void red4(float* p, float a, float b, float c, float d) {
    asm volatile("red.global.add.v4.f32 [%0], {%1,%2,%3,%4};"
                 :: "l"(p), "f"(a), "f"(b), "f"(c), "f"(d) : "memory");
}
__device__ __forceinline__ float ssp(float x) {
    return fmaxf(x, 0.0f) + __logf(1.0f + __expf(-fabsf(x))) - 0.69314718055994530942f;
}
__device__ __forceinline__ u32 smem_u32(const void* p) {
    u32 a; asm("{ .reg .u64 t; cvta.to.shared.u64 t, %1; cvt.u32.u64 %0, t; }" : "=r"(a) : "l"(p));
    return a;
}
__device__ __forceinline__ u32 pkbf(__nv_bfloat16 a, __nv_bfloat16 b) {
    __nv_bfloat162 t(a, b); return *(u32*)&t;
}
__device__ __forceinline__ void split2(float f0, float f1, u32& hi, u32& lo) {
    __nv_bfloat16 h0 = __float2bfloat16(f0), h1 = __float2bfloat16(f1);
    __nv_bfloat16 l0 = __float2bfloat16(f0 - __bfloat162float(h0));
    __nv_bfloat16 l1 = __float2bfloat16(f1 - __bfloat162float(h1));
    hi = pkbf(h0, h1); lo = pkbf(l0, l1);
}

// ---------------- mma.sync helpers (sm_80-era PTX, valid on base sm_100) ----------------
__device__ __forceinline__ void ldmx4(u32* r, u32 addr) {
    asm volatile("ldmatrix.sync.aligned.m8n8.x4.shared.b16 {%0,%1,%2,%3}, [%4];"
                 : "=r"(r[0]), "=r"(r[1]), "=r"(r[2]), "=r"(r[3]) : "r"(addr));
}
__device__ __forceinline__ void mma16816(float* c, const u32* a, const u32* b) {
    asm volatile("mma.sync.aligned.m16n8k16.row.col.f32.bf16.bf16.f32 "
                 "{%0,%1,%2,%3}, {%4,%5,%6,%7}, {%8,%9}, {%0,%1,%2,%3};"
                 : "+f"(c[0]), "+f"(c[1]), "+f"(c[2]), "+f"(c[3])
                 : "r"(a[0]), "r"(a[1]), "r"(a[2]), "r"(a[3]), "r"(b[0]), "r"(b[1]));
}

// ---------------- prep kernels ----------------
__global__ void k_prep1(const float* __restrict__ mw1) {
    int idx = blockIdx.x * 256 + threadIdx.x;          // L*128*64
    if (idx >= NLAYER * 128 * 64) return;
    int l = idx >> 13, r = idx & 8191, n = r >> 6, k = r & 63;
    float v = (k < NGAUSS) ? mw1[(l * NGAUSS + k) * 128 + n] : 0.0f;
    __nv_bfloat16 hi = __float2bfloat16(v);
    g_w1tH[idx] = hi;
    g_w1tL[idx] = __float2bfloat16(v - __bfloat162float(hi));
}
__global__ void k_prep2(const float* __restrict__ mw2) {
    int idx = blockIdx.x * 256 + threadIdx.x;          // L*128*128
    if (idx >= NLAYER * 128 * 128) return;
    int l = idx >> 14, r = idx & 16383, n = r >> 7, k = r & 127;
    float v = mw2[(l * 128 + k) * 128 + n];
    __nv_bfloat16 hi = __float2bfloat16(v);
    g_w2tH[idx] = hi;
    g_w2tL[idx] = __float2bfloat16(v - __bfloat162float(hi));
}

// ---------------- geometry ----------------
__global__ void __launch_bounds__(256) k_geom(const float* __restrict__ pos,
                                              const int* __restrict__ ei) {
    int e = blockIdx.x * 256 + threadIdx.x;
    if (e >= EE) return;
    int s = ei[e], d = ei[EE + e];
    float dx = pos[3*s]   - pos[3*d];
    float dy = pos[3*s+1] - pos[3*d+1];
    float dz = pos[3*s+2] - pos[3*d+2];
    float dist = sqrtf(dx*dx + dy*dy + dz*dz);
    g_C[e] = 0.5f * (__cosf(dist * (3.14159265358979323846f / 10.0f)) + 1.0f);
    const float sp = 10.0f / 49.0f;
    const float coeff = -0.5f / (sp * sp);
    u32* ph = (u32*)(g_eaH + (size_t)e * 64);
    u32* pl = (u32*)(g_eaL + (size_t)e * 64);
#pragma unroll
    for (int g2 = 0; g2 < 32; g2++) {
        int g = g2 * 2;
        float t0 = dist - (float)g * sp;
        float t1 = dist - (float)(g + 1) * sp;
        float v0 = (g < NGAUSS)     ? __expf(coeff * t0 * t0) : 0.0f;
        float v1 = (g + 1 < NGAUSS) ? __expf(coeff * t1 * t1) : 0.0f;
        u32 hi, lo;
        split2(v0, v1, hi, lo);
        ph[g2] = hi;
        pl[g2] = lo;
    }
}

__global__ void __launch_bounds__(256) k_hinit(const int* __restrict__ atoms,
                                               const float* __restrict__ emb) {
    int idx = blockIdx.x * 256 + threadIdx.x;
    if (idx >= NN * 32) return;
    int n = idx >> 5, q = idx & 31;
    ((float4*)g_h)[idx] = ((const float4*)emb)[atoms[n] * 32 + q];
}

__global__ void __launch_bounds__(256) k_zero_agg() {
    int idx = blockIdx.x * 256 + threadIdx.x;
    if (idx < NN * 32) ((float4*)g_agg)[idx] = make_float4(0.f, 0.f, 0.f, 0.f);
}

__global__ void k_zero_tail(float* out) {
    int t = threadIdx.x;
    if (t < 2 * GG) out[2 * NN + t] = 0.0f;
}

// ---------------- fp32 f32x2 GEMM microkernel (node-side) ----------------
template<int K>
__device__ __forceinline__ void gemm_tile(const float* __restrict__ As,
                                          const float* __restrict__ Bs,
                                          int ty, int tx, u64 acc[8][4]) {
    const float* ap = As + ty * 8;
    const float* bp = Bs + tx * 8;
#pragma unroll 4
    for (int k = 0; k < K; k++) {
        float4 a0 = *(const float4*)(ap + k * 132);
        float4 a1 = *(const float4*)(ap + k * 132 + 4);
        float4 b0 = *(const float4*)(bp + k * 128);
        float4 b1 = *(const float4*)(bp + k * 128 + 4);
        u64 bb0 = pk2(b0.x, b0.y), bb1 = pk2(b0.z, b0.w);
        u64 bb2 = pk2(b1.x, b1.y), bb3 = pk2(b1.z, b1.w);
        float a[8] = {a0.x, a0.y, a0.z, a0.w, a1.x, a1.y, a1.z, a1.w};
#pragma unroll
        for (int i = 0; i < 8; i++) {
            u64 aa = pk2(a[i], a[i]);
            fma2(acc[i][0], aa, bb0);
            fma2(acc[i][1], aa, bb1);
            fma2(acc[i][2], aa, bb2);
            fma2(acc[i][3], aa, bb3);
        }
    }
}
#define ZERO_ACC(acc) do { \
    _Pragma("unroll") for (int _i = 0; _i < 8; _i++) \
    _Pragma("unroll") for (int _j = 0; _j < 4; _j++) acc[_i][_j] = 0ull; } while (0)

__global__ void __launch_bounds__(256) k_xl(const float* __restrict__ W) {
    extern __shared__ float sm[];
    float* As = sm;
    float* Bs = As + 128 * 132;
    int tid = threadIdx.x, ty = tid >> 4, tx = tid & 15;
    int row0 = blockIdx.x * 128;
    for (int i = tid; i < 128 * 32; i += 256) {
        int r = i & 127, kq = i >> 7;
        float4 v = make_float4(0.f, 0.f, 0.f, 0.f);
        int row = row0 + r;
        if (row < NN) v = *(const float4*)(g_h + (size_t)row * 128 + kq * 4);
        As[(kq*4+0)*132 + r] = v.x;
        As[(kq*4+1)*132 + r] = v.y;
        As[(kq*4+2)*132 + r] = v.z;
        As[(kq*4+3)*132 + r] = v.w;
    }
    for (int i = tid; i < 128 * 32; i += 256)
        ((float4*)Bs)[i] = ((const float4*)W)[i];
    __syncthreads();
    u64 acc[8][4]; ZERO_ACC(acc);
    gemm_tile<128>(As, Bs, ty, tx, acc);
#pragma unroll
    for (int i = 0; i < 8; i++) {
        int row = row0 + ty * 8 + i;
        if (row >= NN) continue;
        float v[8];
#pragma unroll
        for (int jp = 0; jp < 4; jp++) { float2 t2 = up2(acc[i][jp]); v[2*jp] = t2.x; v[2*jp+1] = t2.y; }
        *(float4*)(g_xl + (size_t)row * 128 + tx * 8)     = make_float4(v[0], v[1], v[2], v[3]);
        *(float4*)(g_xl + (size_t)row * 128 + tx * 8 + 4) = make_float4(v[4], v[5], v[6], v[7]);
    }
}

// ---------------- edge pipeline on mma.sync bf16x3 (persistent) ----------------
// SMEM byte offsets
#define O_A1H 0
#define O_A1L 18432
#define O_A2H 36864            // 128 x 136 bf16 (stride 272B); aliased by msg after GEMM2
#define O_A2L 71680
#define O_B1H 106496
#define O_B1L 124928
#define O_B2H 143360
#define O_B2L 178176
#define O_SB1 212992
#define O_SB2 213504
#define O_SCT 214016
#define O_SRC 214528
#define O_SDST 215040
#define SMEM_EDGE 215552

__global__ void __launch_bounds__(256, 1) k_edge_mma(const int* __restrict__ ei,
        int layer, const float* __restrict__ b1, const float* __restrict__ b2) {
    extern __shared__ char sp[];
    const u32 sbase = smem_u32(sp);
    int tid = threadIdx.x, lane = tid & 31, wid = tid >> 5;
    int wm = wid & 3, wn = wid >> 2;    // warp tile: rows 32*wm, cols 64*wn

    float* sb1f = (float*)(sp + O_SB1);
    float* sb2f = (float*)(sp + O_SB2);
    float* sct  = (float*)(sp + O_SCT);
    int*   ssrc = (int*)(sp + O_SRC);
    int*   sdst = (int*)(sp + O_SDST);
    float* msg  = (float*)(sp + O_A2H);   // [128][132] f32, alias of A2 region

    // ---- load weights (once per launch) ----
    {
        const uint4* w1h = (const uint4*)(g_w1tH + layer * 8192);
        const uint4* w1l = (const uint4*)(g_w1tL + layer * 8192);
        for (int i = tid; i < 1024; i += 256) {
            int n = i >> 3, ch = i & 7;
            *(uint4*)(sp + O_B1H + n * 144 + ch * 16) = w1h[i];
            *(uint4*)(sp + O_B1L + n * 144 + ch * 16) = w1l[i];
        }
        const uint4* w2h = (const uint4*)(g_w2tH + layer * 16384);
        const uint4* w2l = (const uint4*)(g_w2tL + layer * 16384);
        for (int i = tid; i < 2048; i += 256) {
            int n = i >> 4, ch = i & 15;
            *(uint4*)(sp + O_B2H + n * 272 + ch * 16) = w2h[i];
            *(uint4*)(sp + O_B2L + n * 272 + ch * 16) = w2l[i];
        }
        if (tid < 128) { sb1f[tid] = b1[tid]; sb2f[tid] = b2[tid]; }
    }
    __syncthreads();

    // ldmatrix lane-address components
    int a_r = (lane & 7) + ((lane >> 3) & 1) * 8;   // row within 16
    int a_k = (lane >> 4) * 8;                       // k within 16
    int b_r = (lane & 7) + (lane >> 4) * 8;          // n within 16
    int b_k = ((lane >> 3) & 1) * 8;                 // k within 16

    // per-warp ldmatrix base addresses
    u32 A1H_b = sbase + O_A1H + (u32)(wm * 32 + a_r) * 144 + (u32)a_k * 2;
    u32 A1L_b = sbase + O_A1L + (u32)(wm * 32 + a_r) * 144 + (u32)a_k * 2;
    u32 B1H_b = sbase + O_B1H + (u32)(wn * 64 + b_r) * 144 + (u32)b_k * 2;
    u32 B1L_b = sbase + O_B1L + (u32)(wn * 64 + b_r) * 144 + (u32)b_k * 2;
    u32 A2H_b = sbase + O_A2H + (u32)(wm * 32 + a_r) * 272 + (u32)a_k * 2;
    u32 A2L_b = sbase + O_A2L + (u32)(wm * 32 + a_r) * 272 + (u32)a_k * 2;
    u32 B2H_b = sbase + O_B2H + (u32)(wn * 64 + b_r) * 272 + (u32)b_k * 2;
    u32 B2L_b = sbase + O_B2L + (u32)(wn * 64 + b_r) * 272 + (u32)b_k * 2;

    int r0base  = wm * 32 + (lane >> 2);
    int colbase = wn * 64 + (lane & 3) * 2;

    for (int t = blockIdx.x; t < NTILES; t += gridDim.x) {
        // ---- fill A1 tile + per-edge metadata ----
        {
            int e0 = t * 128;
            for (int i = tid; i < 1024; i += 256) {
                int r = i >> 3, ch = i & 7;
                *(uint4*)(sp + O_A1H + r * 144 + ch * 16) =
                    ((const uint4*)(g_eaH + (size_t)(e0 + r) * 64))[ch];
                *(uint4*)(sp + O_A1L + r * 144 + ch * 16) =
                    ((const uint4*)(g_eaL + (size_t)(e0 + r) * 64))[ch];
            }
            if (tid < 128) {
                int e = e0 + tid;
                ssrc[tid] = ei[e];
                sdst[tid] = ei[EE + e];
                sct[tid]  = g_C[e];
            }
        }
        __syncthreads();

        float acc[2][8][4];
#pragma unroll
        for (int mi = 0; mi < 2; mi++)
#pragma unroll
            for (int ni = 0; ni < 8; ni++)
#pragma unroll
                for (int q = 0; q < 4; q++) acc[mi][ni][q] = 0.0f;

        // ---- GEMM1: K = 64, 4 k-steps, 3 passes (HH, HL, LH) ----
#pragma unroll
        for (int ks = 0; ks < 4; ks++) {
            u32 ah[2][4], al[2][4], bh[4][4], bl[4][4];
            ldmx4(ah[0], A1H_b + ks * 32);
            ldmx4(ah[1], A1H_b + 16 * 144 + ks * 32);
            ldmx4(al[0], A1L_b + ks * 32);
            ldmx4(al[1], A1L_b + 16 * 144 + ks * 32);
#pragma unroll
            for (int nb = 0; nb < 4; nb++) {
                ldmx4(bh[nb], B1H_b + nb * 16 * 144 + ks * 32);
                ldmx4(bl[nb], B1L_b + nb * 16 * 144 + ks * 32);
            }
#pragma unroll
            for (int mi = 0; mi < 2; mi++)
#pragma unroll
                for (int nb = 0; nb < 4; nb++) {
                    mma16816(acc[mi][2*nb],   ah[mi], &bh[nb][0]);
                    mma16816(acc[mi][2*nb+1], ah[mi], &bh[nb][2]);
                    mma16816(acc[mi][2*nb],   ah[mi], &bl[nb][0]);
                    mma16816(acc[mi][2*nb+1], ah[mi], &bl[nb][2]);
                    mma16816(acc[mi][2*nb],   al[mi], &bh[nb][0]);
                    mma16816(acc[mi][2*nb+1], al[mi], &bh[nb][2]);
                }
        }

        // ---- epilogue1: T1 = ssp(acc + b1) -> bf16 hi/lo -> A2 SMEM ----
#pragma unroll
        for (int mi = 0; mi < 2; mi++) {
            int r0 = r0base + mi * 16;
#pragma unroll
            for (int ni = 0; ni < 8; ni++) {
                int c = colbase + ni * 8;
                float bb0 = sb1f[c], bb1 = sb1f[c + 1];
                u32 hi, lo;
                split2(ssp(acc[mi][ni][0] + bb0), ssp(acc[mi][ni][1] + bb1), hi, lo);
                *(u32*)(sp + O_A2H + (r0 * 136 + c) * 2) = hi;
                *(u32*)(sp + O_A2L + (r0 * 136 + c) * 2) = lo;
                split2(ssp(acc[mi][ni][2] + bb0), ssp(acc[mi][ni][3] + bb1), hi, lo);
                *(u32*)(sp + O_A2H + ((r0 + 8) * 136 + c) * 2) = hi;
                *(u32*)(sp + O_A2L + ((r0 + 8) * 136 + c) * 2) = lo;
            }
        }
        __syncthreads();

#pragma unroll
        for (int mi = 0; mi < 2; mi++)
#pragma unroll
            for (int ni = 0; ni < 8; ni++)
#pragma unroll
                for (int q = 0; q < 4; q++) acc[mi][ni][q] = 0.0f;

        // ---- GEMM2: K = 128, 8 k-steps, 3 passes ----
#pragma unroll
        for (int ks = 0; ks < 8; ks++) {
            u32 ah[2][4], al[2][4], bh[4][4], bl[4][4];
            ldmx4(ah[0], A2H_b + ks * 32);
            ldmx4(ah[1], A2H_b + 16 * 272 + ks * 32);
            ldmx4(al[0], A2L_b + ks * 32);
            ldmx4(al[1], A2L_b + 16 * 272 + ks * 32);
#pragma unroll
            for (int nb = 0; nb < 4; nb++) {
                ldmx4(bh[nb], B2H_b + nb * 16 * 272 + ks * 32);
                ldmx4(bl[nb], B2L_b + nb * 16 * 272 + ks * 32);
            }
#pragma unroll
            for (int mi = 0; mi < 2; mi++)
#pragma unroll
                for (int nb = 0; nb < 4; nb++) {
                    mma16816(acc[mi][2*nb],   ah[mi], &bh[nb][0]);
                    mma16816(acc[mi][2*nb+1], ah[mi], &bh[nb][2]);
                    mma16816(acc[mi][2*nb],   ah[mi], &bl[nb][0]);
                    mma16816(acc[mi][2*nb+1], ah[mi], &bl[nb][2]);
                    mma16816(acc[mi][2*nb],   al[mi], &bh[nb][0]);
                    mma16816(acc[mi][2*nb+1], al[mi], &bh[nb][2]);
                }
        }
        __syncthreads();   // all warps done reading A2 before msg overwrites it

        // ---- epilogue2: msg = (acc + b2) * C  (staged in SMEM) ----
#pragma unroll
        for (int mi = 0; mi < 2; mi++) {
            int r0 = r0base + mi * 16;
            float c0 = sct[r0], c1 = sct[r0 + 8];
#pragma unroll
            for (int ni = 0; ni < 8; ni++) {
                int c = colbase + ni * 8;
                float bb0 = sb2f[c], bb1 = sb2f[c + 1];
                float2 v0 = make_float2((acc[mi][ni][0] + bb0) * c0,
                                        (acc[mi][ni][1] + bb1) * c0);
                float2 v1 = make_float2((acc[mi][ni][2] + bb0) * c1,
                                        (acc[mi][ni][3] + bb1) * c1);
                *(float2*)(msg + r0 * 132 + c)       = v0;
                *(float2*)(msg + (r0 + 8) * 132 + c) = v1;
            }
        }
        __syncthreads();

        // ---- scatter: agg[dst] += xl[src] * msg ----
        for (int i = tid; i < 128 * 32; i += 256) {
            int r = i >> 5, c4 = i & 31;
            float4 m = *(const float4*)(msg + r * 132 + c4 * 4);
            const float4* xr = (const float4*)(g_xl + (size_t)ssrc[r] * 128);
            float4 x = xr[c4];
            red4(g_agg + (size_t)sdst[r] * 128 + c4 * 4,
                 m.x * x.x, m.y * x.y, m.z * x.z, m.w * x.w);
        }
        // next iteration's __syncthreads (after A1 fill) orders scatter reads
        // of msg vs. epilogue1 writes of A2 region
    }
}

// ---------------- node update (fp32 path) ----------------
__global__ void __launch_bounds__(256) k_node(const float* __restrict__ W2, const float* __restrict__ b2,
                                              const float* __restrict__ Wi, const float* __restrict__ bi) {
    extern __shared__ float sm[];
    float* As  = sm;
    float* Bs  = As + 128 * 132;
    float* sb2 = Bs + 128 * 128;
    float* sbi = sb2 + 128;
    int tid = threadIdx.x, ty = tid >> 4, tx = tid & 15;
    int row0 = blockIdx.x * 128;

    for (int i = tid; i < 128 * 32; i += 256) {
        int r = i & 127, kq = i >> 7;
        float4 v = make_float4(0.f, 0.f, 0.f, 0.f);
        int row = row0 + r;
        if (row < NN) v = *(const float4*)(g_agg + (size_t)row * 128 + kq * 4);
        As[(kq*4+0)*132 + r] = v.x;
        As[(kq*4+1)*132 + r] = v.y;
        As[(kq*4+2)*132 + r] = v.z;
        As[(kq*4+3)*132 + r] = v.w;
    }
    for (int i = tid; i < 128 * 32; i += 256)
        ((float4*)Bs)[i] = ((const float4*)W2)[i];
    if (tid < 128) { sb2[tid] = b2[tid]; sbi[tid] = bi[tid]; }
    __syncthreads();

    u64 acc[8][4]; ZERO_ACC(acc);
    gemm_tile<128>(As, Bs, ty, tx, acc);
    __syncthreads();

#pragma unroll
    for (int i = 0; i < 8; i++) {
        int r = ty * 8 + i;
#pragma unroll
        for (int jp = 0; jp < 4; jp++) {
            float2 v = up2(acc[i][jp]);
            int c = tx * 8 + jp * 2;
            As[c * 132 + r]       = ssp(v.x + sb2[c]);
            As[(c + 1) * 132 + r] = ssp(v.y + sb2[c + 1]);
        }
    }
    for (int i = tid; i < 128 * 32; i += 256)
        ((float4*)Bs)[i] = ((const float4*)Wi)[i];
    __syncthreads();

    ZERO_ACC(acc);
    gemm_tile<128>(As, Bs, ty, tx, acc);

#pragma unroll
    for (int i = 0; i < 8; i++) {
        int row = row0 + ty * 8 + i;
        if (row >= NN) continue;
        float v[8];
#pragma unroll
        for (int jp = 0; jp < 4; jp++) {
            float2 t2 = up2(acc[i][jp]);
            int c = tx * 8 + jp * 2;
            v[2*jp]   = t2.x + sbi[c];
            v[2*jp+1] = t2.y + sbi[c + 1];
        }
        float* hp = g_h + (size_t)row * 128 + tx * 8;
        float4 h0 = *(float4*)hp;
        float4 h1 = *(float4*)(hp + 4);
        h0.x += v[0]; h0.y += v[1]; h0.z += v[2]; h0.w += v[3];
        h1.x += v[4]; h1.y += v[5]; h1.z += v[6]; h1.w += v[7];
        *(float4*)hp = h0;
        *(float4*)(hp + 4) = h1;
    }
}

// ---------------- readout ----------------
__global__ void __launch_bounds__(128) k_read(const int* __restrict__ batch,
        const float* __restrict__ lw, const float* __restrict__ lb,
        const float* __restrict__ ew, const float* __restrict__ ebp,
        const float* __restrict__ qw, const float* __restrict__ qbp,
        float* __restrict__ out) {
    extern __shared__ float sm[];
    float* Hs  = sm;
    float* Ws  = Hs + 128 * 129;
    float* sb  = Ws + 128 * 64;
    float* sew = sb + 64;
    float* sqw = sew + 64;
    int tid = threadIdx.x;
    int row0 = blockIdx.x * 128;
    for (int i = tid; i < 128 * 128; i += 128) {
        int r = i >> 7, c = i & 127;
        int row = row0 + r;
        Hs[r * 129 + c] = (row < NN) ? g_h[(size_t)row * 128 + c] : 0.f;
    }
    for (int i = tid; i < 128 * 64; i += 128) Ws[i] = lw[i];
    if (tid < 64) { sb[tid] = lb[tid]; sew[tid] = ew[tid]; sqw[tid] = qw[tid]; }
    __syncthreads();
    int row = row0 + tid;
    if (row >= NN) return;
    float e = ebp[0], q = qbp[0];
    const float* hr = Hs + tid * 129;
#pragma unroll 2
    for (int j = 0; j < 64; j++) {
        float a = sb[j];
#pragma unroll 8
        for (int k = 0; k < 128; k++) a += hr[k] * Ws[k * 64 + j];
        float hh = ssp(a);
        e += hh * sew[j];
        q += hh * sqw[j];
    }
    out[row] = e;
    out[NN + row] = q;
    int b = batch[row];
    atomicAdd(out + 2 * NN + b, e);
    atomicAdd(out + 2 * NN + GG + b, q);
}

// ---------------- host ----------------
extern "C" void kernel_launch(void* const* d_in, const int* in_sizes, int n_in,
                              void* d_out, int out_size) {
    const int*   atoms = (const int*)d_in[0];
    const float* pos   = (const float*)d_in[1];
    const int*   batch = (const int*)d_in[2];
    const int*   ei    = (const int*)d_in[3];
    const float* emb   = (const float*)d_in[4];
    const float* mw1   = (const float*)d_in[5];
    const float* mb1   = (const float*)d_in[6];
    const float* mw2   = (const float*)d_in[7];
    const float* mb2   = (const float*)d_in[8];
    const float* cw1   = (const float*)d_in[9];
    const float* cw2   = (const float*)d_in[10];
    const float* cb2   = (const float*)d_in[11];
    const float* iw    = (const float*)d_in[12];
    const float* ib    = (const float*)d_in[13];
    const float* l1w   = (const float*)d_in[14];
    const float* l1b   = (const float*)d_in[15];
    const float* ew    = (const float*)d_in[16];
    const float* eb    = (const float*)d_in[17];
    const float* qw    = (const float*)d_in[18];
    const float* qb    = (const float*)d_in[19];
    float* out = (float*)d_out;

    constexpr int SMEM_GEMM = (128 * 132 + 128 * 128) * 4;
    constexpr int SMEM_NODE = SMEM_GEMM + 256 * 4;
    constexpr int SMEM_READ = (128 * 129 + 128 * 64 + 192) * 4;

    cudaFuncSetAttribute(k_xl,       cudaFuncAttributeMaxDynamicSharedMemorySize, SMEM_GEMM);
    cudaFuncSetAttribute(k_node,     cudaFuncAttributeMaxDynamicSharedMemorySize, SMEM_NODE);
    cudaFuncSetAttribute(k_edge_mma, cudaFuncAttributeMaxDynamicSharedMemorySize, SMEM_EDGE);
    cudaFuncSetAttribute(k_read,     cudaFuncAttributeMaxDynamicSharedMemorySize, SMEM_READ);

    const int NODE_BLOCKS = (NN + 127) / 128;   // 391

    k_zero_tail<<<1, 256>>>(out);
    k_prep1<<<(NLAYER * 128 * 64 + 255) / 256, 256>>>(mw1);
    k_prep2<<<(NLAYER * 128 * 128 + 255) / 256, 256>>>(mw2);
    k_geom<<<(EE + 255) / 256, 256>>>(pos, ei);
    k_hinit<<<(NN * 32 + 255) / 256, 256>>>(atoms, emb);
    for (int l = 0; l < NLAYER; l++) {
        k_zero_agg<<<(NN * 32 + 255) / 256, 256>>>();
        k_xl<<<NODE_BLOCKS, 256, SMEM_GEMM>>>(cw1 + (size_t)l * HH * FF);
        k_edge_mma<<<148, 256, SMEM_EDGE>>>(ei, l, mb1 + (size_t)l * FF, mb2 + (size_t)l * FF);
        k_node<<<NODE_BLOCKS, 256, SMEM_NODE>>>(cw2 + (size_t)l * FF * HH, cb2 + (size_t)l * HH,
                                                iw  + (size_t)l * HH * HH, ib  + (size_t)l * HH);
    }
    k_read<<<NODE_BLOCKS, 128, SMEM_READ>>>(batch, l1w, l1b, ew, eb, qw, qb, out);
}

// round 4
// speedup vs baseline: 2.2675x; 1.2707x over previous
#include <cuda_runtime.h>
#include <cuda_bf16.h>
#include <cstdint>

#define NN 50000
#define EE 800000
#define GG 100
#define HH 128
#define FF 128
#define NGAUSS 50
#define NLAYER 6
#define NTILES (EE / 128)   // 6250

typedef unsigned long long u64;
typedef unsigned int u32;

// ---------------- scratch (static device globals; no allocation) ----------------
__device__ float g_dist[EE];                       // edge distances
__device__ float g_C[EE];                          // cosine cutoff
__device__ float g_h[(size_t)NN * HH];             // node features
__device__ float g_xl[(size_t)NN * FF];            // h @ conv_w1
__device__ float g_agg[(size_t)NN * FF];           // scattered messages
// prepped transposed weights (per layer), bf16 hi/lo, [n][k] layout
__device__ __nv_bfloat16 g_w1tH[NLAYER * 128 * 64];
__device__ __nv_bfloat16 g_w1tL[NLAYER * 128 * 64];
__device__ __nv_bfloat16 g_w2tH[NLAYER * 128 * 128];
__device__ __nv_bfloat16 g_w2tL[NLAYER * 128 * 128];
__device__ __nv_bfloat16 g_cw2tH[NLAYER * 128 * 128];
__device__ __nv_bfloat16 g_cw2tL[NLAYER * 128 * 128];
__device__ __nv_bfloat16 g_iwtH[NLAYER * 128 * 128];
__device__ __nv_bfloat16 g_iwtL[NLAYER * 128 * 128];
__device__ __nv_bfloat16 g_cw1tH[NLAYER * 128 * 128];
__device__ __nv_bfloat16 g_cw1tL[NLAYER * 128 * 128];

// ---------------- generic helpers ----------------
__device__ __forceinline__ u64 pk2(float x, float y) {
    u64 r; asm("mov.b64 %0, {%1,%2};" : "=l"(r) : "f"(x), "f"(y)); return r;
}
__device__ __forceinline__ void fma2(u64& d, u64 a, u64 b) {
    asm("fma.rn.f32x2 %0, %1, %2, %0;" : "+l"(d) : "l"(a), "l"(b));
}
__device__ __forceinline__ float2 up2(u64 v) {
    float2 r; asm("mov.b64 {%0,%1}, %2;" : "=f"(r.x), "=f"(r.y) : "l"(v)); return r;
}
__device__ __forceinline__ void red4(float* p, float a, float b, float c, float d) {
    asm volatile("red.global.add.v4.f32 [%0], {%1,%2,%3,%4};"
                 :: "l"(p), "f"(a), "f"(b), "f"(c), "f"(d) : "memory");
}
__device__ __forceinline__ float ssp(float x) {
    return fmaxf(x, 0.0f) + __logf(1.0f + __expf(-fabsf(x))) - 0.69314718055994530942f;
}
__device__ __forceinline__ u32 smem_u32(const void* p) {
    u32 a; asm("{ .reg .u64 t; cvta.to.shared.u64 t, %1; cvt.u32.u64 %0, t; }" : "=r"(a) : "l"(p));
    return a;
}
__device__ __forceinline__ u32 pkbf(__nv_bfloat16 a, __nv_bfloat16 b) {
    __nv_bfloat162 t(a, b); return *(u32*)&t;
}
__device__ __forceinline__ void split2(float f0, float f1, u32& hi, u32& lo) {
    __nv_bfloat16 h0 = __float2bfloat16(f0), h1 = __float2bfloat16(f1);
    __nv_bfloat16 l0 = __float2bfloat16(f0 - __bfloat162float(h0));
    __nv_bfloat16 l1 = __float2bfloat16(f1 - __bfloat162float(h1));
    hi = pkbf(h0, h1); lo = pkbf(l0, l1);
}

// ---------------- mma.sync helpers ----------------
__device__ __forceinline__ void ldmx4(u32* r, u32 addr) {
    asm volatile("ldmatrix.sync.aligned.m8n8.x4.shared.b16 {%0,%1,%2,%3}, [%4];"
                 : "=r"(r[0]), "=r"(r[1]), "=r"(r[2]), "=r"(r[3]) : "r"(addr));
}
__device__ __forceinline__ void mma16816(float* c, const u32* a, const u32* b) {
    asm volatile("mma.sync.aligned.m16n8k16.row.col.f32.bf16.bf16.f32 "
                 "{%0,%1,%2,%3}, {%4,%5,%6,%7}, {%8,%9}, {%0,%1,%2,%3};"
                 : "+f"(c[0]), "+f"(c[1]), "+f"(c[2]), "+f"(c[3])
                 : "r"(a[0]), "r"(a[1]), "r"(a[2]), "r"(a[3]), "r"(b[0]), "r"(b[1]));
}

#define ZACC(acc) do { \
    _Pragma("unroll") for (int _m = 0; _m < 2; _m++) \
    _Pragma("unroll") for (int _n = 0; _n < 8; _n++) \
    _Pragma("unroll") for (int _q = 0; _q < 4; _q++) acc[_m][_n][_q] = 0.0f; } while (0)

// 3-pass (HH + HL + LH) bf16x3 GEMM over K with ldmatrix row stride STRIDE bytes
template<int KS, int STRIDE>
__device__ __forceinline__ void gemm_3p(float acc[2][8][4],
        u32 AHb, u32 ALb, u32 BHb, u32 BLb) {
#pragma unroll
    for (int ks = 0; ks < KS; ks++) {
        u32 ah[2][4], al[2][4], bh[4][4], bl[4][4];
        ldmx4(ah[0], AHb + ks * 32);
        ldmx4(ah[1], AHb + 16 * STRIDE + ks * 32);
        ldmx4(al[0], ALb + ks * 32);
        ldmx4(al[1], ALb + 16 * STRIDE + ks * 32);
#pragma unroll
        for (int nb = 0; nb < 4; nb++) {
            ldmx4(bh[nb], BHb + nb * 16 * STRIDE + ks * 32);
            ldmx4(bl[nb], BLb + nb * 16 * STRIDE + ks * 32);
        }
#pragma unroll
        for (int mi = 0; mi < 2; mi++)
#pragma unroll
            for (int nb = 0; nb < 4; nb++) {
                mma16816(acc[mi][2*nb],   ah[mi], &bh[nb][0]);
                mma16816(acc[mi][2*nb+1], ah[mi], &bh[nb][2]);
                mma16816(acc[mi][2*nb],   ah[mi], &bl[nb][0]);
                mma16816(acc[mi][2*nb+1], ah[mi], &bl[nb][2]);
                mma16816(acc[mi][2*nb],   al[mi], &bh[nb][0]);
                mma16816(acc[mi][2*nb+1], al[mi], &bh[nb][2]);
            }
    }
}

// epilogue: ssp(acc + bias) -> bf16 hi/lo into 272B-stride A buffers
__device__ __forceinline__ void epi_ssp_split(const float acc[2][8][4],
        const float* bias, char* aH, char* aL, int r0base, int colbase) {
#pragma unroll
    for (int mi = 0; mi < 2; mi++) {
        int r0 = r0base + mi * 16;
#pragma unroll
        for (int ni = 0; ni < 8; ni++) {
            int c = colbase + ni * 8;
            float bb0 = bias[c], bb1 = bias[c + 1];
            u32 hi, lo;
            split2(ssp(acc[mi][ni][0] + bb0), ssp(acc[mi][ni][1] + bb1), hi, lo);
            *(u32*)(aH + r0 * 272 + c * 2) = hi;
            *(u32*)(aL + r0 * 272 + c * 2) = lo;
            split2(ssp(acc[mi][ni][2] + bb0), ssp(acc[mi][ni][3] + bb1), hi, lo);
            *(u32*)(aH + (r0 + 8) * 272 + c * 2) = hi;
            *(u32*)(aL + (r0 + 8) * 272 + c * 2) = lo;
        }
    }
}

// ---------------- prep kernels ----------------
__global__ void k_prep1(const float* __restrict__ mw1) {
    int idx = blockIdx.x * 256 + threadIdx.x;          // L*128*64
    if (idx >= NLAYER * 128 * 64) return;
    int l = idx >> 13, r = idx & 8191, n = r >> 6, k = r & 63;
    float v = (k < NGAUSS) ? mw1[(l * NGAUSS + k) * 128 + n] : 0.0f;
    __nv_bfloat16 hi = __float2bfloat16(v);
    g_w1tH[idx] = hi;
    g_w1tL[idx] = __float2bfloat16(v - __bfloat162float(hi));
}
__global__ void k_prepT(const float* __restrict__ src,
                        __nv_bfloat16* __restrict__ dH, __nv_bfloat16* __restrict__ dL) {
    int idx = blockIdx.x * 256 + threadIdx.x;          // L*128*128
    if (idx >= NLAYER * 128 * 128) return;
    int l = idx >> 14, r = idx & 16383, n = r >> 7, k = r & 127;
    float v = src[(l * 128 + k) * 128 + n];
    __nv_bfloat16 hi = __float2bfloat16(v);
    dH[idx] = hi;
    dL[idx] = __float2bfloat16(v - __bfloat162float(hi));
}

// ---------------- geometry: distances + cutoff only ----------------
__global__ void __launch_bounds__(256) k_dist(const float* __restrict__ pos,
                                              const int* __restrict__ ei) {
    int e = blockIdx.x * 256 + threadIdx.x;
    if (e >= EE) return;
    int s = ei[e], d = ei[EE + e];
    float dx = pos[3*s]   - pos[3*d];
    float dy = pos[3*s+1] - pos[3*d+1];
    float dz = pos[3*s+2] - pos[3*d+2];
    float dist = sqrtf(dx*dx + dy*dy + dz*dz);
    g_dist[e] = dist;
    g_C[e] = 0.5f * (__cosf(dist * (3.14159265358979323846f / 10.0f)) + 1.0f);
}

__global__ void __launch_bounds__(256) k_hinit(const int* __restrict__ atoms,
                                               const float* __restrict__ emb) {
    int idx = blockIdx.x * 256 + threadIdx.x;
    if (idx >= NN * 32) return;
    int n = idx >> 5, q = idx & 31;
    ((float4*)g_h)[idx] = ((const float4*)emb)[atoms[n] * 32 + q];
}

__global__ void __launch_bounds__(256) k_zero_agg() {
    int idx = blockIdx.x * 256 + threadIdx.x;
    if (idx < NN * 32) ((float4*)g_agg)[idx] = make_float4(0.f, 0.f, 0.f, 0.f);
}

__global__ void k_zero_tail(float* out) {
    int t = threadIdx.x;
    if (t < 2 * GG) out[2 * NN + t] = 0.0f;
}

// ---------------- fp32 f32x2 GEMM (layer-0 xl only) ----------------
template<int K>
__device__ __forceinline__ void gemm_tile(const float* __restrict__ As,
                                          const float* __restrict__ Bs,
                                          int ty, int tx, u64 acc[8][4]) {
    const float* ap = As + ty * 8;
    const float* bp = Bs + tx * 8;
#pragma unroll 4
    for (int k = 0; k < K; k++) {
        float4 a0 = *(const float4*)(ap + k * 132);
        float4 a1 = *(const float4*)(ap + k * 132 + 4);
        float4 b0 = *(const float4*)(bp + k * 128);
        float4 b1 = *(const float4*)(bp + k * 128 + 4);
        u64 bb0 = pk2(b0.x, b0.y), bb1 = pk2(b0.z, b0.w);
        u64 bb2 = pk2(b1.x, b1.y), bb3 = pk2(b1.z, b1.w);
        float a[8] = {a0.x, a0.y, a0.z, a0.w, a1.x, a1.y, a1.z, a1.w};
#pragma unroll
        for (int i = 0; i < 8; i++) {
            u64 aa = pk2(a[i], a[i]);
            fma2(acc[i][0], aa, bb0);
            fma2(acc[i][1], aa, bb1);
            fma2(acc[i][2], aa, bb2);
            fma2(acc[i][3], aa, bb3);
        }
    }
}
#define ZERO_ACC8(acc) do { \
    _Pragma("unroll") for (int _i = 0; _i < 8; _i++) \
    _Pragma("unroll") for (int _j = 0; _j < 4; _j++) acc[_i][_j] = 0ull; } while (0)

__global__ void __launch_bounds__(256) k_xl(const float* __restrict__ W) {
    extern __shared__ float sm[];
    float* As = sm;
    float* Bs = As + 128 * 132;
    int tid = threadIdx.x, ty = tid >> 4, tx = tid & 15;
    int row0 = blockIdx.x * 128;
    for (int i = tid; i < 128 * 32; i += 256) {
        int r = i & 127, kq = i >> 7;
        float4 v = make_float4(0.f, 0.f, 0.f, 0.f);
        int row = row0 + r;
        if (row < NN) v = *(const float4*)(g_h + (size_t)row * 128 + kq * 4);
        As[(kq*4+0)*132 + r] = v.x;
        As[(kq*4+1)*132 + r] = v.y;
        As[(kq*4+2)*132 + r] = v.z;
        As[(kq*4+3)*132 + r] = v.w;
    }
    for (int i = tid; i < 128 * 32; i += 256)
        ((float4*)Bs)[i] = ((const float4*)W)[i];
    __syncthreads();
    u64 acc[8][4]; ZERO_ACC8(acc);
    gemm_tile<128>(As, Bs, ty, tx, acc);
#pragma unroll
    for (int i = 0; i < 8; i++) {
        int row = row0 + ty * 8 + i;
        if (row >= NN) continue;
        float v[8];
#pragma unroll
        for (int jp = 0; jp < 4; jp++) { float2 t2 = up2(acc[i][jp]); v[2*jp] = t2.x; v[2*jp+1] = t2.y; }
        *(float4*)(g_xl + (size_t)row * 128 + tx * 8)     = make_float4(v[0], v[1], v[2], v[3]);
        *(float4*)(g_xl + (size_t)row * 128 + tx * 8 + 4) = make_float4(v[4], v[5], v[6], v[7]);
    }
}

// ---------------- edge pipeline (persistent, EA computed in-kernel) ----------------
#define O_A1H 0
#define O_A1L 18432
#define O_A2H 36864            // stride 272B; aliased by msg after GEMM2
#define O_A2L 71680
#define O_B1H 106496
#define O_B1L 124928
#define O_B2H 143360
#define O_B2L 178176
#define O_SB1 212992
#define O_SB2 213504
#define O_SCT 214016
#define O_SRC 214528
#define O_SDST 215040
#define SMEM_EDGE 215552

__global__ void __launch_bounds__(256, 1) k_edge_mma(const int* __restrict__ ei,
        int layer, const float* __restrict__ b1, const float* __restrict__ b2) {
    extern __shared__ char sp[];
    const u32 sbase = smem_u32(sp);
    int tid = threadIdx.x, lane = tid & 31, wid = tid >> 5;
    int wm = wid & 3, wn = wid >> 2;

    float* sb1f = (float*)(sp + O_SB1);
    float* sb2f = (float*)(sp + O_SB2);
    float* sct  = (float*)(sp + O_SCT);
    int*   ssrc = (int*)(sp + O_SRC);
    int*   sdst = (int*)(sp + O_SDST);
    float* msg  = (float*)(sp + O_A2H);   // [128][132] f32, alias of A2 region

    // ---- weights to SMEM (once per launch) ----
    {
        const uint4* w1h = (const uint4*)(g_w1tH + layer * 8192);
        const uint4* w1l = (const uint4*)(g_w1tL + layer * 8192);
        for (int i = tid; i < 1024; i += 256) {
            int n = i >> 3, ch = i & 7;
            *(uint4*)(sp + O_B1H + n * 144 + ch * 16) = w1h[i];
            *(uint4*)(sp + O_B1L + n * 144 + ch * 16) = w1l[i];
        }
        const uint4* w2h = (const uint4*)(g_w2tH + layer * 16384);
        const uint4* w2l = (const uint4*)(g_w2tL + layer * 16384);
        for (int i = tid; i < 2048; i += 256) {
            int n = i >> 4, ch = i & 15;
            *(uint4*)(sp + O_B2H + n * 272 + ch * 16) = w2h[i];
            *(uint4*)(sp + O_B2L + n * 272 + ch * 16) = w2l[i];
        }
        if (tid < 128) { sb1f[tid] = b1[tid]; sb2f[tid] = b2[tid]; }
    }
    __syncthreads();

    int a_r = (lane & 7) + ((lane >> 3) & 1) * 8;
    int a_k = (lane >> 4) * 8;
    int b_r = (lane & 7) + (lane >> 4) * 8;
    int b_k = ((lane >> 3) & 1) * 8;

    u32 A1H_b = sbase + O_A1H + (u32)(wm * 32 + a_r) * 144 + (u32)a_k * 2;
    u32 A1L_b = sbase + O_A1L + (u32)(wm * 32 + a_r) * 144 + (u32)a_k * 2;
    u32 B1H_b = sbase + O_B1H + (u32)(wn * 64 + b_r) * 144 + (u32)b_k * 2;
    u32 B1L_b = sbase + O_B1L + (u32)(wn * 64 + b_r) * 144 + (u32)b_k * 2;
    u32 A2H_b = sbase + O_A2H + (u32)(wm * 32 + a_r) * 272 + (u32)a_k * 2;
    u32 A2L_b = sbase + O_A2L + (u32)(wm * 32 + a_r) * 272 + (u32)a_k * 2;
    u32 B2H_b = sbase + O_B2H + (u32)(wn * 64 + b_r) * 272 + (u32)b_k * 2;
    u32 B2L_b = sbase + O_B2L + (u32)(wn * 64 + b_r) * 272 + (u32)b_k * 2;

    int r0base  = wm * 32 + (lane >> 2);
    int colbase = wn * 64 + (lane & 3) * 2;

    const float spc = 10.0f / 49.0f;
    const float coeff = -0.5f / (spc * spc);

    for (int t = blockIdx.x; t < NTILES; t += gridDim.x) {
        int e0 = t * 128;
        // ---- compute gaussian expansion hi/lo directly into A1 ----
        {
            int r = tid >> 1, half = tid & 1;
            float dv = g_dist[e0 + r];
            u32 hi[16], lo[16];
#pragma unroll
            for (int jj = 0; jj < 16; jj++) {
                int g = half * 32 + 2 * jj;
                float t0 = dv - (float)g * spc;
                float t1 = dv - (float)(g + 1) * spc;
                float v0 = (g < NGAUSS)     ? __expf(coeff * t0 * t0) : 0.0f;
                float v1 = (g + 1 < NGAUSS) ? __expf(coeff * t1 * t1) : 0.0f;
                split2(v0, v1, hi[jj], lo[jj]);
            }
            char* rowH = sp + O_A1H + r * 144 + half * 64;
            char* rowL = sp + O_A1L + r * 144 + half * 64;
#pragma unroll
            for (int q = 0; q < 4; q++) {
                *(uint4*)(rowH + q * 16) = make_uint4(hi[4*q], hi[4*q+1], hi[4*q+2], hi[4*q+3]);
                *(uint4*)(rowL + q * 16) = make_uint4(lo[4*q], lo[4*q+1], lo[4*q+2], lo[4*q+3]);
            }
            if (tid < 128) {
                int e = e0 + tid;
                ssrc[tid] = ei[e];
                sdst[tid] = ei[EE + e];
                sct[tid]  = g_C[e];
            }
        }
        __syncthreads();

        float acc[2][8][4];
        ZACC(acc);
        gemm_3p<4, 144>(acc, A1H_b, A1L_b, B1H_b, B1L_b);

        // T1 = ssp(acc + b1) -> A2
        epi_ssp_split(acc, sb1f, sp + O_A2H, sp + O_A2L, r0base, colbase);
        __syncthreads();

        ZACC(acc);
        gemm_3p<8, 272>(acc, A2H_b, A2L_b, B2H_b, B2L_b);
        __syncthreads();   // all warps done reading A2 before msg overwrites it

        // msg = (acc + b2) * C
#pragma unroll
        for (int mi = 0; mi < 2; mi++) {
            int r0 = r0base + mi * 16;
            float c0 = sct[r0], c1 = sct[r0 + 8];
#pragma unroll
            for (int ni = 0; ni < 8; ni++) {
                int c = colbase + ni * 8;
                float bb0 = sb2f[c], bb1 = sb2f[c + 1];
                *(float2*)(msg + r0 * 132 + c) =
                    make_float2((acc[mi][ni][0] + bb0) * c0, (acc[mi][ni][1] + bb1) * c0);
                *(float2*)(msg + (r0 + 8) * 132 + c) =
                    make_float2((acc[mi][ni][2] + bb0) * c1, (acc[mi][ni][3] + bb1) * c1);
            }
        }
        __syncthreads();

        // scatter: agg[dst] += xl[src] * msg
        for (int i = tid; i < 128 * 32; i += 256) {
            int r = i >> 5, c4 = i & 31;
            float4 m = *(const float4*)(msg + r * 132 + c4 * 4);
            const float4* xr = (const float4*)(g_xl + (size_t)ssrc[r] * 128);
            float4 x = xr[c4];
            red4(g_agg + (size_t)sdst[r] * 128 + c4 * 4,
                 m.x * x.x, m.y * x.y, m.z * x.z, m.w * x.w);
        }
    }
}

// ---------------- fused node update on mma (agg->cw2->ssp->iw->h; xl = h@cw1[l+1]) ----------------
#define N_AH 0
#define N_AL 34816
#define N_BH 69632
#define N_BL 104448
#define SMEM_NODEM 139264

__global__ void __launch_bounds__(256, 1) k_node_mma(
        const float* __restrict__ cb2, const float* __restrict__ ib,
        int layer, int has_next) {
    extern __shared__ char sp[];
    const u32 sbase = smem_u32(sp);
    int tid = threadIdx.x, lane = tid & 31, wid = tid >> 5;
    int wm = wid & 3, wn = wid >> 2;
    int row0 = blockIdx.x * 128;

    int a_r = (lane & 7) + ((lane >> 3) & 1) * 8;
    int a_k = (lane >> 4) * 8;
    int b_r = (lane & 7) + (lane >> 4) * 8;
    int b_k = ((lane >> 3) & 1) * 8;
    u32 AH_b = sbase + N_AH + (u32)(wm * 32 + a_r) * 272 + (u32)a_k * 2;
    u32 AL_b = sbase + N_AL + (u32)(wm * 32 + a_r) * 272 + (u32)a_k * 2;
    u32 BH_b = sbase + N_BH + (u32)(wn * 64 + b_r) * 272 + (u32)b_k * 2;
    u32 BL_b = sbase + N_BL + (u32)(wn * 64 + b_r) * 272 + (u32)b_k * 2;
    int r0base  = wm * 32 + (lane >> 2);
    int colbase = wn * 64 + (lane & 3) * 2;

    // ---- A <- split(agg); zero agg; B <- cw2 ----
    for (int i = tid; i < 128 * 32; i += 256) {
        int r = i >> 5, c4 = i & 31;
        int row = row0 + r;
        float4 v = make_float4(0.f, 0.f, 0.f, 0.f);
        if (row < NN) {
            float* ap = g_agg + (size_t)row * 128 + c4 * 4;
            v = *(const float4*)ap;
            *(float4*)ap = make_float4(0.f, 0.f, 0.f, 0.f);
        }
        u32 h0, l0, h1, l1;
        split2(v.x, v.y, h0, l0);
        split2(v.z, v.w, h1, l1);
        *(uint2*)(sp + N_AH + r * 272 + c4 * 8) = make_uint2(h0, h1);
        *(uint2*)(sp + N_AL + r * 272 + c4 * 8) = make_uint2(l0, l1);
    }
    {
        const uint4* bh = (const uint4*)(g_cw2tH + layer * 16384);
        const uint4* bl = (const uint4*)(g_cw2tL + layer * 16384);
        for (int i = tid; i < 2048; i += 256) {
            int n = i >> 4, ch = i & 15;
            *(uint4*)(sp + N_BH + n * 272 + ch * 16) = bh[i];
            *(uint4*)(sp + N_BL + n * 272 + ch * 16) = bl[i];
        }
    }
    __syncthreads();

    float acc[2][8][4];
    ZACC(acc);
    gemm_3p<8, 272>(acc, AH_b, AL_b, BH_b, BL_b);
    __syncthreads();   // A,B reads done

    // ---- epi1: A <- split(ssp(acc + cb2)); B <- iw ----
    epi_ssp_split(acc, cb2, sp + N_AH, sp + N_AL, r0base, colbase);
    {
        const uint4* bh = (const uint4*)(g_iwtH + layer * 16384);
        const uint4* bl = (const uint4*)(g_iwtL + layer * 16384);
        for (int i = tid; i < 2048; i += 256) {
            int n = i >> 4, ch = i & 15;
            *(uint4*)(sp + N_BH + n * 272 + ch * 16) = bh[i];
            *(uint4*)(sp + N_BL + n * 272 + ch * 16) = bl[i];
        }
    }
    __syncthreads();

    ZACC(acc);
    gemm_3p<8, 272>(acc, AH_b, AL_b, BH_b, BL_b);
    __syncthreads();

    // ---- epi2: h += acc + ib ; A <- split(h_new) ----
#pragma unroll
    for (int mi = 0; mi < 2; mi++) {
        int r0 = r0base + mi * 16;
#pragma unroll
        for (int rr = 0; rr < 2; rr++) {
            int r = r0 + rr * 8;
            int row = row0 + r;
#pragma unroll
            for (int ni = 0; ni < 8; ni++) {
                int c = colbase + ni * 8;
                float v0 = acc[mi][ni][2*rr]     + ib[c];
                float v1 = acc[mi][ni][2*rr + 1] + ib[c + 1];
                float2 hv = make_float2(0.f, 0.f);
                float* hp = g_h + (size_t)row * 128 + c;
                if (row < NN) hv = *(const float2*)hp;
                hv.x += v0; hv.y += v1;
                if (row < NN) *(float2*)hp = hv;
                u32 hi, lo;
                split2(hv.x, hv.y, hi, lo);
                *(u32*)(sp + N_AH + r * 272 + c * 2) = hi;
                *(u32*)(sp + N_AL + r * 272 + c * 2) = lo;
            }
        }
    }
    if (has_next) {
        const uint4* bh = (const uint4*)(g_cw1tH + (layer + 1) * 16384);
        const uint4* bl = (const uint4*)(g_cw1tL + (layer + 1) * 16384);
        for (int i = tid; i < 2048; i += 256) {
            int n = i >> 4, ch = i & 15;
            *(uint4*)(sp + N_BH + n * 272 + ch * 16) = bh[i];
            *(uint4*)(sp + N_BL + n * 272 + ch * 16) = bl[i];
        }
        __syncthreads();

        ZACC(acc);
        gemm_3p<8, 272>(acc, AH_b, AL_b, BH_b, BL_b);

        // write xl
#pragma unroll
        for (int mi = 0; mi < 2; mi++) {
            int r0 = r0base + mi * 16;
#pragma unroll
            for (int rr = 0; rr < 2; rr++) {
                int row = row0 + r0 + rr * 8;
                if (row >= NN) continue;
#pragma unroll
                for (int ni = 0; ni < 8; ni++) {
                    int c = colbase + ni * 8;
                    *(float2*)(g_xl + (size_t)row * 128 + c) =
                        make_float2(acc[mi][ni][2*rr], acc[mi][ni][2*rr + 1]);
                }
            }
        }
    }
}

// ---------------- readout ----------------
__global__ void __launch_bounds__(128) k_read(const int* __restrict__ batch,
        const float* __restrict__ lw, const float* __restrict__ lb,
        const float* __restrict__ ew, const float* __restrict__ ebp,
        const float* __restrict__ qw, const float* __restrict__ qbp,
        float* __restrict__ out) {
    extern __shared__ float sm[];
    float* Hs  = sm;
    float* Ws  = Hs + 128 * 129;
    float* sb  = Ws + 128 * 64;
    float* sew = sb + 64;
    float* sqw = sew + 64;
    int tid = threadIdx.x;
    int row0 = blockIdx.x * 128;
    for (int i = tid; i < 128 * 128; i += 128) {
        int r = i >> 7, c = i & 127;
        int row = row0 + r;
        Hs[r * 129 + c] = (row < NN) ? g_h[(size_t)row * 128 + c] : 0.f;
    }
    for (int i = tid; i < 128 * 64; i += 128) Ws[i] = lw[i];
    if (tid < 64) { sb[tid] = lb[tid]; sew[tid] = ew[tid]; sqw[tid] = qw[tid]; }
    __syncthreads();
    int row = row0 + tid;
    if (row >= NN) return;
    float e = ebp[0], q = qbp[0];
    const float* hr = Hs + tid * 129;
#pragma unroll 2
    for (int j = 0; j < 64; j++) {
        float a = sb[j];
#pragma unroll 8
        for (int k = 0; k < 128; k++) a += hr[k] * Ws[k * 64 + j];
        float hh = ssp(a);
        e += hh * sew[j];
        q += hh * sqw[j];
    }
    out[row] = e;
    out[NN + row] = q;
    int b = batch[row];
    atomicAdd(out + 2 * NN + b, e);
    atomicAdd(out + 2 * NN + GG + b, q);
}

// ---------------- host ----------------
extern "C" void kernel_launch(void* const* d_in, const int* in_sizes, int n_in,
                              void* d_out, int out_size) {
    const int*   atoms = (const int*)d_in[0];
    const float* pos   = (const float*)d_in[1];
    const int*   batch = (const int*)d_in[2];
    const int*   ei    = (const int*)d_in[3];
    const float* emb   = (const float*)d_in[4];
    const float* mw1   = (const float*)d_in[5];
    const float* mb1   = (const float*)d_in[6];
    const float* mw2   = (const float*)d_in[7];
    const float* mb2   = (const float*)d_in[8];
    const float* cw1   = (const float*)d_in[9];
    const float* cw2   = (const float*)d_in[10];
    const float* cb2   = (const float*)d_in[11];
    const float* iw    = (const float*)d_in[12];
    const float* ib    = (const float*)d_in[13];
    const float* l1w   = (const float*)d_in[14];
    const float* l1b   = (const float*)d_in[15];
    const float* ew    = (const float*)d_in[16];
    const float* eb    = (const float*)d_in[17];
    const float* qw    = (const float*)d_in[18];
    const float* qb    = (const float*)d_in[19];
    float* out = (float*)d_out;

    __nv_bfloat16 *null_b16 = nullptr; (void)null_b16;

    constexpr int SMEM_GEMM = (128 * 132 + 128 * 128) * 4;
    constexpr int SMEM_READ = (128 * 129 + 128 * 64 + 192) * 4;

    cudaFuncSetAttribute(k_xl,       cudaFuncAttributeMaxDynamicSharedMemorySize, SMEM_GEMM);
    cudaFuncSetAttribute(k_edge_mma, cudaFuncAttributeMaxDynamicSharedMemorySize, SMEM_EDGE);
    cudaFuncSetAttribute(k_node_mma, cudaFuncAttributeMaxDynamicSharedMemorySize, SMEM_NODEM);
    cudaFuncSetAttribute(k_read,     cudaFuncAttributeMaxDynamicSharedMemorySize, SMEM_READ);

    const int NODE_BLOCKS = (NN + 127) / 128;   // 391
    const int PT_BLOCKS = (NLAYER * 128 * 128 + 255) / 256;

    k_zero_tail<<<1, 256>>>(out);
    k_prep1<<<(NLAYER * 128 * 64 + 255) / 256, 256>>>(mw1);
    {
        // weight transposes to bf16 hi/lo
        __nv_bfloat16 *w2h, *w2l, *c2h, *c2l, *iwh, *iwl, *c1h, *c1l;
        cudaGetSymbolAddress((void**)&w2h, g_w2tH);  cudaGetSymbolAddress((void**)&w2l, g_w2tL);
        cudaGetSymbolAddress((void**)&c2h, g_cw2tH); cudaGetSymbolAddress((void**)&c2l, g_cw2tL);
        cudaGetSymbolAddress((void**)&iwh, g_iwtH);  cudaGetSymbolAddress((void**)&iwl, g_iwtL);
        cudaGetSymbolAddress((void**)&c1h, g_cw1tH); cudaGetSymbolAddress((void**)&c1l, g_cw1tL);
        k_prepT<<<PT_BLOCKS, 256>>>(mw2, w2h, w2l);
        k_prepT<<<PT_BLOCKS, 256>>>(cw2, c2h, c2l);
        k_prepT<<<PT_BLOCKS, 256>>>(iw,  iwh, iwl);
        k_prepT<<<PT_BLOCKS, 256>>>(cw1, c1h, c1l);
    }
    k_dist<<<(EE + 255) / 256, 256>>>(pos, ei);
    k_hinit<<<(NN * 32 + 255) / 256, 256>>>(atoms, emb);
    k_zero_agg<<<(NN * 32 + 255) / 256, 256>>>();
    k_xl<<<NODE_BLOCKS, 256, SMEM_GEMM>>>(cw1);   // layer-0 xl
    for (int l = 0; l < NLAYER; l++) {
        k_edge_mma<<<148, 256, SMEM_EDGE>>>(ei, l, mb1 + (size_t)l * FF, mb2 + (size_t)l * FF);
        k_node_mma<<<NODE_BLOCKS, 256, SMEM_NODEM>>>(cb2 + (size_t)l * HH, ib + (size_t)l * HH,
                                                     l, (l < NLAYER - 1) ? 1 : 0);
    }
    k_read<<<NODE_BLOCKS, 128, SMEM_READ>>>(batch, l1w, l1b, ew, eb, qw, qb, out);
}

// round 5
// speedup vs baseline: 2.5693x; 1.1331x over previous
#include <cuda_runtime.h>
#include <cuda_bf16.h>
#include <cstdint>

#define NN 50000
#define EE 800000
#define GG 100
#define HH 128
#define FF 128
#define NGAUSS 50
#define NLAYER 6
#define NTILES (EE / 128)   // 6250

typedef unsigned long long u64;
typedef unsigned int u32;

// ---------------- scratch (static device globals; no allocation) ----------------
__device__ float g_dist[EE];                       // edge distances (input order)
__device__ float g_C[EE];                          // cosine cutoff (input order)
__device__ int   g_cnt[NN];                        // per-dst histogram
__device__ int   g_cur[NN];                        // scan cursor
__device__ float g_sd[EE];                         // dist, dst-sorted
__device__ float g_sc[EE];                         // C, dst-sorted
__device__ int   g_ss[EE];                         // src, dst-sorted
__device__ int   g_sdt[EE];                        // dst, dst-sorted
__device__ float g_h[(size_t)NN * HH];             // node features
__device__ float g_xl[(size_t)NN * FF];            // h @ conv_w1
__device__ float g_agg[(size_t)NN * FF];           // scattered messages (kept zeroed)
// prepped transposed weights (per layer), bf16 hi/lo, [n][k] layout
__device__ __nv_bfloat16 g_w1tH[NLAYER * 128 * 64];
__device__ __nv_bfloat16 g_w1tL[NLAYER * 128 * 64];
__device__ __nv_bfloat16 g_w2tH[NLAYER * 128 * 128];
__device__ __nv_bfloat16 g_w2tL[NLAYER * 128 * 128];
__device__ __nv_bfloat16 g_cw2tH[NLAYER * 128 * 128];
__device__ __nv_bfloat16 g_cw2tL[NLAYER * 128 * 128];
__device__ __nv_bfloat16 g_iwtH[NLAYER * 128 * 128];
__device__ __nv_bfloat16 g_iwtL[NLAYER * 128 * 128];
__device__ __nv_bfloat16 g_cw1tH[NLAYER * 128 * 128];
__device__ __nv_bfloat16 g_cw1tL[NLAYER * 128 * 128];

// ---------------- generic helpers ----------------
__device__ __forceinline__ u64 pk2(float x, float y) {
    u64 r; asm("mov.b64 %0, {%1,%2};" : "=l"(r) : "f"(x), "f"(y)); return r;
}
__device__ __forceinline__ void fma2(u64& d, u64 a, u64 b) {
    asm("fma.rn.f32x2 %0, %1, %2, %0;" : "+l"(d) : "l"(a), "l"(b));
}
__device__ __forceinline__ float2 up2(u64 v) {
    float2 r; asm("mov.b64 {%0,%1}, %2;" : "=f"(r.x), "=f"(r.y) : "l"(v)); return r;
}
__device__ __forceinline__ void red4(float* p, float a, float b, float c, float d) {
    asm volatile("red.global.add.v4.f32 [%0], {%1,%2,%3,%4};"
                 :: "l"(p), "f"(a), "f"(b), "f"(c), "f"(d) : "memory");
}
__device__ __forceinline__ float ssp(float x) {
    return fmaxf(x, 0.0f) + __logf(1.0f + __expf(-fabsf(x))) - 0.69314718055994530942f;
}
__device__ __forceinline__ u32 smem_u32(const void* p) {
    u32 a; asm("{ .reg .u64 t; cvta.to.shared.u64 t, %1; cvt.u32.u64 %0, t; }" : "=r"(a) : "l"(p));
    return a;
}
__device__ __forceinline__ u32 pkbf(__nv_bfloat16 a, __nv_bfloat16 b) {
    __nv_bfloat162 t(a, b); return *(u32*)&t;
}
__device__ __forceinline__ void split2(float f0, float f1, u32& hi, u32& lo) {
    __nv_bfloat16 h0 = __float2bfloat16(f0), h1 = __float2bfloat16(f1);
    __nv_bfloat16 l0 = __float2bfloat16(f0 - __bfloat162float(h0));
    __nv_bfloat16 l1 = __float2bfloat16(f1 - __bfloat162float(h1));
    hi = pkbf(h0, h1); lo = pkbf(l0, l1);
}

// ---------------- mma.sync helpers ----------------
__device__ __forceinline__ void ldmx4(u32* r, u32 addr) {
    asm volatile("ldmatrix.sync.aligned.m8n8.x4.shared.b16 {%0,%1,%2,%3}, [%4];"
                 : "=r"(r[0]), "=r"(r[1]), "=r"(r[2]), "=r"(r[3]) : "r"(addr));
}
__device__ __forceinline__ void mma16816(float* c, const u32* a, const u32* b) {
    asm volatile("mma.sync.aligned.m16n8k16.row.col.f32.bf16.bf16.f32 "
                 "{%0,%1,%2,%3}, {%4,%5,%6,%7}, {%8,%9}, {%0,%1,%2,%3};"
                 : "+f"(c[0]), "+f"(c[1]), "+f"(c[2]), "+f"(c[3])
                 : "r"(a[0]), "r"(a[1]), "r"(a[2]), "r"(a[3]), "r"(b[0]), "r"(b[1]));
}

#define ZACC(acc) do { \
    _Pragma("unroll") for (int _m = 0; _m < 2; _m++) \
    _Pragma("unroll") for (int _n = 0; _n < 8; _n++) \
    _Pragma("unroll") for (int _q = 0; _q < 4; _q++) acc[_m][_n][_q] = 0.0f; } while (0)

// 3-pass (HH + HL + LH) bf16x3 GEMM over K with ldmatrix row stride STRIDE bytes
template<int KS, int STRIDE>
__device__ __forceinline__ void gemm_3p(float acc[2][8][4],
        u32 AHb, u32 ALb, u32 BHb, u32 BLb) {
#pragma unroll
    for (int ks = 0; ks < KS; ks++) {
        u32 ah[2][4], al[2][4], bh[4][4], bl[4][4];
        ldmx4(ah[0], AHb + ks * 32);
        ldmx4(ah[1], AHb + 16 * STRIDE + ks * 32);
        ldmx4(al[0], ALb + ks * 32);
        ldmx4(al[1], ALb + 16 * STRIDE + ks * 32);
#pragma unroll
        for (int nb = 0; nb < 4; nb++) {
            ldmx4(bh[nb], BHb + nb * 16 * STRIDE + ks * 32);
            ldmx4(bl[nb], BLb + nb * 16 * STRIDE + ks * 32);
        }
#pragma unroll
        for (int mi = 0; mi < 2; mi++)
#pragma unroll
            for (int nb = 0; nb < 4; nb++) {
                mma16816(acc[mi][2*nb],   ah[mi], &bh[nb][0]);
                mma16816(acc[mi][2*nb+1], ah[mi], &bh[nb][2]);
                mma16816(acc[mi][2*nb],   ah[mi], &bl[nb][0]);
                mma16816(acc[mi][2*nb+1], ah[mi], &bl[nb][2]);
                mma16816(acc[mi][2*nb],   al[mi], &bh[nb][0]);
                mma16816(acc[mi][2*nb+1], al[mi], &bh[nb][2]);
            }
    }
}

// epilogue: ssp(acc + bias) -> bf16 hi/lo into 272B-stride A buffers
__device__ __forceinline__ void epi_ssp_split(const float acc[2][8][4],
        const float* bias, char* aH, char* aL, int r0base, int colbase) {
#pragma unroll
    for (int mi = 0; mi < 2; mi++) {
        int r0 = r0base + mi * 16;
#pragma unroll
        for (int ni = 0; ni < 8; ni++) {
            int c = colbase + ni * 8;
            float bb0 = bias[c], bb1 = bias[c + 1];
            u32 hi, lo;
            split2(ssp(acc[mi][ni][0] + bb0), ssp(acc[mi][ni][1] + bb1), hi, lo);
            *(u32*)(aH + r0 * 272 + c * 2) = hi;
            *(u32*)(aL + r0 * 272 + c * 2) = lo;
            split2(ssp(acc[mi][ni][2] + bb0), ssp(acc[mi][ni][3] + bb1), hi, lo);
            *(u32*)(aH + (r0 + 8) * 272 + c * 2) = hi;
            *(u32*)(aL + (r0 + 8) * 272 + c * 2) = lo;
        }
    }
}

// ---------------- launch 1: all weight prep + zero counters ----------------
__global__ void __launch_bounds__(256) k_prep(const float* __restrict__ mw1,
        const float* __restrict__ mw2, const float* __restrict__ cw2,
        const float* __restrict__ iw, const float* __restrict__ cw1,
        float* __restrict__ out) {
    int idx = blockIdx.x * 256 + threadIdx.x;
    if (idx < NLAYER * 128 * 128) {
        int l = idx >> 14, r = idx & 16383, n = r >> 7, k = r & 127;
        int sidx = (l * 128 + k) * 128 + n;
        float v; __nv_bfloat16 hi;
        v = mw2[sidx]; hi = __float2bfloat16(v);
        g_w2tH[idx] = hi;  g_w2tL[idx] = __float2bfloat16(v - __bfloat162float(hi));
        v = cw2[sidx]; hi = __float2bfloat16(v);
        g_cw2tH[idx] = hi; g_cw2tL[idx] = __float2bfloat16(v - __bfloat162float(hi));
        v = iw[sidx]; hi = __float2bfloat16(v);
        g_iwtH[idx] = hi;  g_iwtL[idx] = __float2bfloat16(v - __bfloat162float(hi));
        v = cw1[sidx]; hi = __float2bfloat16(v);
        g_cw1tH[idx] = hi; g_cw1tL[idx] = __float2bfloat16(v - __bfloat162float(hi));
    }
    if (idx < NLAYER * 128 * 64) {
        int l = idx >> 13, r = idx & 8191, n = r >> 6, k = r & 63;
        float v = (k < NGAUSS) ? mw1[(l * NGAUSS + k) * 128 + n] : 0.0f;
        __nv_bfloat16 hi = __float2bfloat16(v);
        g_w1tH[idx] = hi;
        g_w1tL[idx] = __float2bfloat16(v - __bfloat162float(hi));
    }
    if (idx < NN) g_cnt[idx] = 0;
    if (idx < 2 * GG) out[2 * NN + idx] = 0.0f;
}

// ---------------- launch 2: dist/C/histogram + h init ----------------
__global__ void __launch_bounds__(256) k_init(const float* __restrict__ pos,
        const int* __restrict__ ei, const int* __restrict__ atoms,
        const float* __restrict__ emb) {
    int e = blockIdx.x * 256 + threadIdx.x;    // grid covers EE exactly
    int s = ei[e], d = ei[EE + e];
    float dx = pos[3*s]   - pos[3*d];
    float dy = pos[3*s+1] - pos[3*d+1];
    float dz = pos[3*s+2] - pos[3*d+2];
    float dist = sqrtf(dx*dx + dy*dy + dz*dz);
    g_dist[e] = dist;
    g_C[e] = 0.5f * (__cosf(dist * (3.14159265358979323846f / 10.0f)) + 1.0f);
    atomicAdd(&g_cnt[d], 1);
    for (int j = e; j < NN * 32; j += EE)
        ((float4*)g_h)[j] = ((const float4*)emb)[atoms[j >> 5] * 32 + (j & 31)];
}

// ---------------- launch 3: exclusive scan of g_cnt -> g_cur ----------------
__global__ void __launch_bounds__(1024) k_scan() {
    __shared__ int warp_sums[32];
    __shared__ int s_carry;
    int tid = threadIdx.x;
    if (tid == 0) s_carry = 0;
    __syncthreads();
    for (int base = 0; base < NN; base += 1024) {
        int i = base + tid;
        int v = (i < NN) ? g_cnt[i] : 0;
        int incl = v;
#pragma unroll
        for (int off = 1; off < 32; off <<= 1) {
            int n = __shfl_up_sync(0xffffffff, incl, off);
            if ((tid & 31) >= off) incl += n;
        }
        if ((tid & 31) == 31) warp_sums[tid >> 5] = incl;
        __syncthreads();
        if (tid < 32) {
            int ws = warp_sums[tid];
            int wi = ws;
#pragma unroll
            for (int off = 1; off < 32; off <<= 1) {
                int n = __shfl_up_sync(0xffffffff, wi, off);
                if (tid >= off) wi += n;
            }
            warp_sums[tid] = wi - ws;   // exclusive warp offset
        }
        __syncthreads();
        int excl = s_carry + warp_sums[tid >> 5] + incl - v;
        if (i < NN) g_cur[i] = excl;
        __syncthreads();
        if (tid == 1023) s_carry = excl + v;
        __syncthreads();
    }
}

// ---------------- launch 4: permute edges into dst-sorted order ----------------
__global__ void __launch_bounds__(256) k_permute(const int* __restrict__ ei) {
    int e = blockIdx.x * 256 + threadIdx.x;
    if (e >= EE) return;
    int d = ei[EE + e];
    int pos = atomicAdd(&g_cur[d], 1);
    g_sd[pos]  = g_dist[e];
    g_sc[pos]  = g_C[e];
    g_ss[pos]  = ei[e];
    g_sdt[pos] = d;
}

// ---------------- fp32 f32x2 GEMM (layer-0 xl only) ----------------
template<int K>
__device__ __forceinline__ void gemm_tile(const float* __restrict__ As,
                                          const float* __restrict__ Bs,
                                          int ty, int tx, u64 acc[8][4]) {
    const float* ap = As + ty * 8;
    const float* bp = Bs + tx * 8;
#pragma unroll 4
    for (int k = 0; k < K; k++) {
        float4 a0 = *(const float4*)(ap + k * 132);
        float4 a1 = *(const float4*)(ap + k * 132 + 4);
        float4 b0 = *(const float4*)(bp + k * 128);
        float4 b1 = *(const float4*)(bp + k * 128 + 4);
        u64 bb0 = pk2(b0.x, b0.y), bb1 = pk2(b0.z, b0.w);
        u64 bb2 = pk2(b1.x, b1.y), bb3 = pk2(b1.z, b1.w);
        float a[8] = {a0.x, a0.y, a0.z, a0.w, a1.x, a1.y, a1.z, a1.w};
#pragma unroll
        for (int i = 0; i < 8; i++) {
            u64 aa = pk2(a[i], a[i]);
            fma2(acc[i][0], aa, bb0);
            fma2(acc[i][1], aa, bb1);
            fma2(acc[i][2], aa, bb2);
            fma2(acc[i][3], aa, bb3);
        }
    }
}
#define ZERO_ACC8(acc) do { \
    _Pragma("unroll") for (int _i = 0; _i < 8; _i++) \
    _Pragma("unroll") for (int _j = 0; _j < 4; _j++) acc[_i][_j] = 0ull; } while (0)

__global__ void __launch_bounds__(256) k_xl(const float* __restrict__ W) {
    extern __shared__ float sm[];
    float* As = sm;
    float* Bs = As + 128 * 132;
    int tid = threadIdx.x, ty = tid >> 4, tx = tid & 15;
    int row0 = blockIdx.x * 128;
    for (int i = tid; i < 128 * 32; i += 256) {
        int r = i & 127, kq = i >> 7;
        float4 v = make_float4(0.f, 0.f, 0.f, 0.f);
        int row = row0 + r;
        if (row < NN) v = *(const float4*)(g_h + (size_t)row * 128 + kq * 4);
        As[(kq*4+0)*132 + r] = v.x;
        As[(kq*4+1)*132 + r] = v.y;
        As[(kq*4+2)*132 + r] = v.z;
        As[(kq*4+3)*132 + r] = v.w;
    }
    for (int i = tid; i < 128 * 32; i += 256)
        ((float4*)Bs)[i] = ((const float4*)W)[i];
    __syncthreads();
    u64 acc[8][4]; ZERO_ACC8(acc);
    gemm_tile<128>(As, Bs, ty, tx, acc);
#pragma unroll
    for (int i = 0; i < 8; i++) {
        int row = row0 + ty * 8 + i;
        if (row >= NN) continue;
        float v[8];
#pragma unroll
        for (int jp = 0; jp < 4; jp++) { float2 t2 = up2(acc[i][jp]); v[2*jp] = t2.x; v[2*jp+1] = t2.y; }
        *(float4*)(g_xl + (size_t)row * 128 + tx * 8)     = make_float4(v[0], v[1], v[2], v[3]);
        *(float4*)(g_xl + (size_t)row * 128 + tx * 8 + 4) = make_float4(v[4], v[5], v[6], v[7]);
    }
}

// ---------------- edge pipeline (persistent, dst-sorted, segmented scatter) ----------------
#define O_A1H 0
#define O_A1L 18432
#define O_A2H 36864            // stride 272B; aliased by msg after GEMM2
#define O_A2L 71680
#define O_B1H 106496
#define O_B1L 124928
#define O_B2H 143360
#define O_B2L 178176
#define O_SB1 212992
#define O_SB2 213504
#define O_SCT 214016
#define O_SRC 214528
#define O_SDST 215040
#define SMEM_EDGE 215552

__global__ void __launch_bounds__(256, 1) k_edge_mma(
        int layer, const float* __restrict__ b1, const float* __restrict__ b2) {
    extern __shared__ char sp[];
    const u32 sbase = smem_u32(sp);
    int tid = threadIdx.x, lane = tid & 31, wid = tid >> 5;
    int wm = wid & 3, wn = wid >> 2;

    float* sb1f = (float*)(sp + O_SB1);
    float* sb2f = (float*)(sp + O_SB2);
    float* sct  = (float*)(sp + O_SCT);
    int*   ssrc = (int*)(sp + O_SRC);
    int*   sdst = (int*)(sp + O_SDST);
    float* msg  = (float*)(sp + O_A2H);   // [128][132] f32, alias of A2 region

    // ---- weights to SMEM (once per launch) ----
    {
        const uint4* w1h = (const uint4*)(g_w1tH + layer * 8192);
        const uint4* w1l = (const uint4*)(g_w1tL + layer * 8192);
        for (int i = tid; i < 1024; i += 256) {
            int n = i >> 3, ch = i & 7;
            *(uint4*)(sp + O_B1H + n * 144 + ch * 16) = w1h[i];
            *(uint4*)(sp + O_B1L + n * 144 + ch * 16) = w1l[i];
        }
        const uint4* w2h = (const uint4*)(g_w2tH + layer * 16384);
        const uint4* w2l = (const uint4*)(g_w2tL + layer * 16384);
        for (int i = tid; i < 2048; i += 256) {
            int n = i >> 4, ch = i & 15;
            *(uint4*)(sp + O_B2H + n * 272 + ch * 16) = w2h[i];
            *(uint4*)(sp + O_B2L + n * 272 + ch * 16) = w2l[i];
        }
        if (tid < 128) { sb1f[tid] = b1[tid]; sb2f[tid] = b2[tid]; }
    }
    __syncthreads();

    int a_r = (lane & 7) + ((lane >> 3) & 1) * 8;
    int a_k = (lane >> 4) * 8;
    int b_r = (lane & 7) + (lane >> 4) * 8;
    int b_k = ((lane >> 3) & 1) * 8;

    u32 A1H_b = sbase + O_A1H + (u32)(wm * 32 + a_r) * 144 + (u32)a_k * 2;
    u32 A1L_b = sbase + O_A1L + (u32)(wm * 32 + a_r) * 144 + (u32)a_k * 2;
    u32 B1H_b = sbase + O_B1H + (u32)(wn * 64 + b_r) * 144 + (u32)b_k * 2;
    u32 B1L_b = sbase + O_B1L + (u32)(wn * 64 + b_r) * 144 + (u32)b_k * 2;
    u32 A2H_b = sbase + O_A2H + (u32)(wm * 32 + a_r) * 272 + (u32)a_k * 2;
    u32 A2L_b = sbase + O_A2L + (u32)(wm * 32 + a_r) * 272 + (u32)a_k * 2;
    u32 B2H_b = sbase + O_B2H + (u32)(wn * 64 + b_r) * 272 + (u32)b_k * 2;
    u32 B2L_b = sbase + O_B2L + (u32)(wn * 64 + b_r) * 272 + (u32)b_k * 2;

    int r0base  = wm * 32 + (lane >> 2);
    int colbase = wn * 64 + (lane & 3) * 2;

    const float spc = 10.0f / 49.0f;
    const float coeff = -0.5f / (spc * spc);

    for (int t = blockIdx.x; t < NTILES; t += gridDim.x) {
        int e0 = t * 128;
        // ---- compute gaussian expansion hi/lo directly into A1 ----
        {
            int r = tid >> 1, half = tid & 1;
            float dv = g_sd[e0 + r];
            u32 hi[16], lo[16];
#pragma unroll
            for (int jj = 0; jj < 16; jj++) {
                int g = half * 32 + 2 * jj;
                float t0 = dv - (float)g * spc;
                float t1 = dv - (float)(g + 1) * spc;
                float v0 = (g < NGAUSS)     ? __expf(coeff * t0 * t0) : 0.0f;
                float v1 = (g + 1 < NGAUSS) ? __expf(coeff * t1 * t1) : 0.0f;
                split2(v0, v1, hi[jj], lo[jj]);
            }
            char* rowH = sp + O_A1H + r * 144 + half * 64;
            char* rowL = sp + O_A1L + r * 144 + half * 64;
#pragma unroll
            for (int q = 0; q < 4; q++) {
                *(uint4*)(rowH + q * 16) = make_uint4(hi[4*q], hi[4*q+1], hi[4*q+2], hi[4*q+3]);
                *(uint4*)(rowL + q * 16) = make_uint4(lo[4*q], lo[4*q+1], lo[4*q+2], lo[4*q+3]);
            }
            if (tid < 128) {
                int e = e0 + tid;
                ssrc[tid] = g_ss[e];
                sdst[tid] = g_sdt[e];
                sct[tid]  = g_sc[e];
            }
        }
        __syncthreads();

        float acc[2][8][4];
        ZACC(acc);
        gemm_3p<4, 144>(acc, A1H_b, A1L_b, B1H_b, B1L_b);

        // T1 = ssp(acc + b1) -> A2
        epi_ssp_split(acc, sb1f, sp + O_A2H, sp + O_A2L, r0base, colbase);
        __syncthreads();

        ZACC(acc);
        gemm_3p<8, 272>(acc, A2H_b, A2L_b, B2H_b, B2L_b);
        __syncthreads();   // all warps done reading A2 before msg overwrites it

        // msg = (acc + b2) * C
#pragma unroll
        for (int mi = 0; mi < 2; mi++) {
            int r0 = r0base + mi * 16;
            float c0 = sct[r0], c1 = sct[r0 + 8];
#pragma unroll
            for (int ni = 0; ni < 8; ni++) {
                int c = colbase + ni * 8;
                float bb0 = sb2f[c], bb1 = sb2f[c + 1];
                *(float2*)(msg + r0 * 132 + c) =
                    make_float2((acc[mi][ni][0] + bb0) * c0, (acc[mi][ni][1] + bb1) * c0);
                *(float2*)(msg + (r0 + 8) * 132 + c) =
                    make_float2((acc[mi][ni][2] + bb0) * c1, (acc[mi][ni][3] + bb1) * c1);
            }
        }
        __syncthreads();

        // ---- segmented scatter: warp w owns rows 16w..16w+15, lane = col chunk ----
        {
            int rbeg = wid * 16;
            float4 acc4 = make_float4(0.f, 0.f, 0.f, 0.f);
            int cur = sdst[rbeg];
#pragma unroll
            for (int pb = 0; pb < 4; pb++) {
                int r0 = rbeg + pb * 4;
                int sr[4], sd[4];
#pragma unroll
                for (int j = 0; j < 4; j++) { sr[j] = ssrc[r0 + j]; sd[j] = sdst[r0 + j]; }
                float4 x[4];
#pragma unroll
                for (int j = 0; j < 4; j++)
                    x[j] = ((const float4*)(g_xl + (size_t)sr[j] * 128))[lane];
#pragma unroll
                for (int j = 0; j < 4; j++) {
                    if (sd[j] != cur) {   // warp-uniform branch (sorted dst)
                        red4(g_agg + (size_t)cur * 128 + lane * 4,
                             acc4.x, acc4.y, acc4.z, acc4.w);
                        acc4 = make_float4(0.f, 0.f, 0.f, 0.f);
                        cur = sd[j];
                    }
                    float4 m = *(const float4*)(msg + (r0 + j) * 132 + lane * 4);
                    acc4.x += m.x * x[j].x; acc4.y += m.y * x[j].y;
                    acc4.z += m.z * x[j].z; acc4.w += m.w * x[j].w;
                }
            }
            red4(g_agg + (size_t)cur * 128 + lane * 4, acc4.x, acc4.y, acc4.z, acc4.w);
        }
    }
}

// ---------------- fused node update on mma (agg->cw2->ssp->iw->h; xl = h@cw1[l+1]) ----------------
#define N_AH 0
#define N_AL 34816
#define N_BH 69632
#define N_BL 104448
#define SMEM_NODEM 139264

__global__ void __launch_bounds__(256, 1) k_node_mma(
        const float* __restrict__ cb2, const float* __restrict__ ib,
        int layer, int has_next) {
    extern __shared__ char sp[];
    const u32 sbase = smem_u32(sp);
    int tid = threadIdx.x, lane = tid & 31, wid = tid >> 5;
    int wm = wid & 3, wn = wid >> 2;
    int row0 = blockIdx.x * 128;

    int a_r = (lane & 7) + ((lane >> 3) & 1) * 8;
    int a_k = (lane >> 4) * 8;
    int b_r = (lane & 7) + (lane >> 4) * 8;
    int b_k = ((lane >> 3) & 1) * 8;
    u32 AH_b = sbase + N_AH + (u32)(wm * 32 + a_r) * 272 + (u32)a_k * 2;
    u32 AL_b = sbase + N_AL + (u32)(wm * 32 + a_r) * 272 + (u32)a_k * 2;
    u32 BH_b = sbase + N_BH + (u32)(wn * 64 + b_r) * 272 + (u32)b_k * 2;
    u32 BL_b = sbase + N_BL + (u32)(wn * 64 + b_r) * 272 + (u32)b_k * 2;
    int r0base  = wm * 32 + (lane >> 2);
    int colbase = wn * 64 + (lane & 3) * 2;

    // ---- A <- split(agg); zero agg; B <- cw2 ----
    for (int i = tid; i < 128 * 32; i += 256) {
        int r = i >> 5, c4 = i & 31;
        int row = row0 + r;
        float4 v = make_float4(0.f, 0.f, 0.f, 0.f);
        if (row < NN) {
            float* ap = g_agg + (size_t)row * 128 + c4 * 4;
            v = *(const float4*)ap;
            *(float4*)ap = make_float4(0.f, 0.f, 0.f, 0.f);
        }
        u32 h0, l0, h1, l1;
        split2(v.x, v.y, h0, l0);
        split2(v.z, v.w, h1, l1);
        *(uint2*)(sp + N_AH + r * 272 + c4 * 8) = make_uint2(h0, h1);
        *(uint2*)(sp + N_AL + r * 272 + c4 * 8) = make_uint2(l0, l1);
    }
    {
        const uint4* bh = (const uint4*)(g_cw2tH + layer * 16384);
        const uint4* bl = (const uint4*)(g_cw2tL + layer * 16384);
        for (int i = tid; i < 2048; i += 256) {
            int n = i >> 4, ch = i & 15;
            *(uint4*)(sp + N_BH + n * 272 + ch * 16) = bh[i];
            *(uint4*)(sp + N_BL + n * 272 + ch * 16) = bl[i];
        }
    }
    __syncthreads();

    float acc[2][8][4];
    ZACC(acc);
    gemm_3p<8, 272>(acc, AH_b, AL_b, BH_b, BL_b);
    __syncthreads();   // A,B reads done

    // ---- epi1: A <- split(ssp(acc + cb2)); B <- iw ----
    epi_ssp_split(acc, cb2, sp + N_AH, sp + N_AL, r0base, colbase);
    {
        const uint4* bh = (const uint4*)(g_iwtH + layer * 16384);
        const uint4* bl = (const uint4*)(g_iwtL + layer * 16384);
        for (int i = tid; i < 2048; i += 256) {
            int n = i >> 4, ch = i & 15;
            *(uint4*)(sp + N_BH + n * 272 + ch * 16) = bh[i];
            *(uint4*)(sp + N_BL + n * 272 + ch * 16) = bl[i];
        }
    }
    __syncthreads();

    ZACC(acc);
    gemm_3p<8, 272>(acc, AH_b, AL_b, BH_b, BL_b);
    __syncthreads();

    // ---- epi2: h += acc + ib ; A <- split(h_new) ----
#pragma unroll
    for (int mi = 0; mi < 2; mi++) {
        int r0 = r0base + mi * 16;
#pragma unroll
        for (int rr = 0; rr < 2; rr++) {
            int r = r0 + rr * 8;
            int row = row0 + r;
#pragma unroll
            for (int ni = 0; ni < 8; ni++) {
                int c = colbase + ni * 8;
                float v0 = acc[mi][ni][2*rr]     + ib[c];
                float v1 = acc[mi][ni][2*rr + 1] + ib[c + 1];
                float2 hv = make_float2(0.f, 0.f);
                float* hp = g_h + (size_t)row * 128 + c;
                if (row < NN) hv = *(const float2*)hp;
                hv.x += v0; hv.y += v1;
                if (row < NN) *(float2*)hp = hv;
                u32 hi, lo;
                split2(hv.x, hv.y, hi, lo);
                *(u32*)(sp + N_AH + r * 272 + c * 2) = hi;
                *(u32*)(sp + N_AL + r * 272 + c * 2) = lo;
            }
        }
    }
    if (has_next) {
        const uint4* bh = (const uint4*)(g_cw1tH + (layer + 1) * 16384);
        const uint4* bl = (const uint4*)(g_cw1tL + (layer + 1) * 16384);
        for (int i = tid; i < 2048; i += 256) {
            int n = i >> 4, ch = i & 15;
            *(uint4*)(sp + N_BH + n * 272 + ch * 16) = bh[i];
            *(uint4*)(sp + N_BL + n * 272 + ch * 16) = bl[i];
        }
        __syncthreads();

        ZACC(acc);
        gemm_3p<8, 272>(acc, AH_b, AL_b, BH_b, BL_b);

        // write xl
#pragma unroll
        for (int mi = 0; mi < 2; mi++) {
            int r0 = r0base + mi * 16;
#pragma unroll
            for (int rr = 0; rr < 2; rr++) {
                int row = row0 + r0 + rr * 8;
                if (row >= NN) continue;
#pragma unroll
                for (int ni = 0; ni < 8; ni++) {
                    int c = colbase + ni * 8;
                    *(float2*)(g_xl + (size_t)row * 128 + c) =
                        make_float2(acc[mi][ni][2*rr], acc[mi][ni][2*rr + 1]);
                }
            }
        }
    }
}

// ---------------- readout ----------------
__global__ void __launch_bounds__(128) k_read(const int* __restrict__ batch,
        const float* __restrict__ lw, const float* __restrict__ lb,
        const float* __restrict__ ew, const float* __restrict__ ebp,
        const float* __restrict__ qw, const float* __restrict__ qbp,
        float* __restrict__ out) {
    extern __shared__ float sm[];
    float* Hs  = sm;
    float* Ws  = Hs + 128 * 129;
    float* sb  = Ws + 128 * 64;
    float* sew = sb + 64;
    float* sqw = sew + 64;
    int tid = threadIdx.x;
    int row0 = blockIdx.x * 128;
    for (int i = tid; i < 128 * 128; i += 128) {
        int r = i >> 7, c = i & 127;
        int row = row0 + r;
        Hs[r * 129 + c] = (row < NN) ? g_h[(size_t)row * 128 + c] : 0.f;
    }
    for (int i = tid; i < 128 * 64; i += 128) Ws[i] = lw[i];
    if (tid < 64) { sb[tid] = lb[tid]; sew[tid] = ew[tid]; sqw[tid] = qw[tid]; }
    __syncthreads();
    int row = row0 + tid;
    if (row >= NN) return;
    float e = ebp[0], q = qbp[0];
    const float* hr = Hs + tid * 129;
#pragma unroll 2
    for (int j = 0; j < 64; j++) {
        float a = sb[j];
#pragma unroll 8
        for (int k = 0; k < 128; k++) a += hr[k] * Ws[k * 64 + j];
        float hh = ssp(a);
        e += hh * sew[j];
        q += hh * sqw[j];
    }
    out[row] = e;
    out[NN + row] = q;
    int b = batch[row];
    atomicAdd(out + 2 * NN + b, e);
    atomicAdd(out + 2 * NN + GG + b, q);
}

// ---------------- host ----------------
extern "C" void kernel_launch(void* const* d_in, const int* in_sizes, int n_in,
                              void* d_out, int out_size) {
    const int*   atoms = (const int*)d_in[0];
    const float* pos   = (const float*)d_in[1];
    const int*   batch = (const int*)d_in[2];
    const int*   ei    = (const int*)d_in[3];
    const float* emb   = (const float*)d_in[4];
    const float* mw1   = (const float*)d_in[5];
    const float* mb1   = (const float*)d_in[6];
    const float* mw2   = (const float*)d_in[7];
    const float* mb2   = (const float*)d_in[8];
    const float* cw1   = (const float*)d_in[9];
    const float* cw2   = (const float*)d_in[10];
    const float* cb2   = (const float*)d_in[11];
    const float* iw    = (const float*)d_in[12];
    const float* ib    = (const float*)d_in[13];
    const float* l1w   = (const float*)d_in[14];
    const float* l1b   = (const float*)d_in[15];
    const float* ew    = (const float*)d_in[16];
    const float* eb    = (const float*)d_in[17];
    const float* qw    = (const float*)d_in[18];
    const float* qb    = (const float*)d_in[19];
    float* out = (float*)d_out;

    constexpr int SMEM_GEMM = (128 * 132 + 128 * 128) * 4;
    constexpr int SMEM_READ = (128 * 129 + 128 * 64 + 192) * 4;

    cudaFuncSetAttribute(k_xl,       cudaFuncAttributeMaxDynamicSharedMemorySize, SMEM_GEMM);
    cudaFuncSetAttribute(k_edge_mma, cudaFuncAttributeMaxDynamicSharedMemorySize, SMEM_EDGE);
    cudaFuncSetAttribute(k_node_mma, cudaFuncAttributeMaxDynamicSharedMemorySize, SMEM_NODEM);
    cudaFuncSetAttribute(k_read,     cudaFuncAttributeMaxDynamicSharedMemorySize, SMEM_READ);

    const int NODE_BLOCKS = (NN + 127) / 128;   // 391
    const int PREP_BLOCKS = (NLAYER * 128 * 128 + 255) / 256;   // 384

    // launches 1-5 (so that launch 6 = k_edge_mma gets profiled by ncu -s 5 -c 1)
    k_prep<<<PREP_BLOCKS, 256>>>(mw1, mw2, cw2, iw, cw1, out);
    k_init<<<EE / 256, 256>>>(pos, ei, atoms, emb);
    k_scan<<<1, 1024>>>();
    k_permute<<<EE / 256, 256>>>(ei);
    k_xl<<<NODE_BLOCKS, 256, SMEM_GEMM>>>(cw1);   // layer-0 xl

    for (int l = 0; l < NLAYER; l++) {
        k_edge_mma<<<148, 256, SMEM_EDGE>>>(l, mb1 + (size_t)l * FF, mb2 + (size_t)l * FF);
        k_node_mma<<<NODE_BLOCKS, 256, SMEM_NODEM>>>(cb2 + (size_t)l * HH, ib + (size_t)l * HH,
                                                     l, (l < NLAYER - 1) ? 1 : 0);
    }
    k_read<<<NODE_BLOCKS, 128, SMEM_READ>>>(batch, l1w, l1b, ew, eb, qw, qb, out);
}

// round 6
// speedup vs baseline: 2.5732x; 1.0015x over previous
#include <cuda_runtime.h>
#include <cuda_bf16.h>
#include <cstdint>

#define NN 50000
#define EE 800000
#define GG 100
#define HH 128
#define FF 128
#define NGAUSS 50
#define NLAYER 6
#define NTILES (EE / 128)   // 6250
#define EGRID 148

typedef unsigned long long u64;
typedef unsigned int u32;

// ---------------- scratch (static device globals; no allocation) ----------------
__device__ float g_dist[EE];                       // edge distances (input order)
__device__ float g_C[EE];                          // cosine cutoff (input order)
__device__ int   g_cnt[NN];                        // per-dst histogram (re-zeroed by k_scan_xl each run)
__device__ int   g_cur[NN];                        // scan cursor
__device__ float g_sd[EE];                         // dist, dst-sorted
__device__ float g_sc[EE];                         // C, dst-sorted
__device__ int   g_ss[EE];                         // src, dst-sorted
__device__ int   g_sdt[EE];                        // dst, dst-sorted
__device__ float g_h[(size_t)NN * HH];             // node features
__device__ float g_xl[(size_t)NN * FF];            // h @ conv_w1
__device__ float g_agg[(size_t)NN * FF];           // scattered messages (kept zeroed)
// prepped transposed weights (per layer), bf16 hi/lo, [n][k] layout
__device__ __nv_bfloat16 g_w1tH[NLAYER * 128 * 64];
__device__ __nv_bfloat16 g_w1tL[NLAYER * 128 * 64];
__device__ __nv_bfloat16 g_w2tH[NLAYER * 128 * 128];
__device__ __nv_bfloat16 g_w2tL[NLAYER * 128 * 128];
__device__ __nv_bfloat16 g_cw2tH[NLAYER * 128 * 128];
__device__ __nv_bfloat16 g_cw2tL[NLAYER * 128 * 128];
__device__ __nv_bfloat16 g_iwtH[NLAYER * 128 * 128];
__device__ __nv_bfloat16 g_iwtL[NLAYER * 128 * 128];
__device__ __nv_bfloat16 g_cw1tH[NLAYER * 128 * 128];
__device__ __nv_bfloat16 g_cw1tL[NLAYER * 128 * 128];

// ---------------- generic helpers ----------------
__device__ __forceinline__ u64 pk2(float x, float y) {
    u64 r; asm("mov.b64 %0, {%1,%2};" : "=l"(r) : "f"(x), "f"(y)); return r;
}
__device__ __forceinline__ void fma2(u64& d, u64 a, u64 b) {
    asm("fma.rn.f32x2 %0, %1, %2, %0;" : "+l"(d) : "l"(a), "l"(b));
}
__device__ __forceinline__ float2 up2(u64 v) {
    float2 r; asm("mov.b64 {%0,%1}, %2;" : "=f"(r.x), "=f"(r.y) : "l"(v)); return r;
}
__device__ __forceinline__ void red4(float* p, float a, float b, float c, float d) {
    asm volatile("red.global.add.v4.f32 [%0], {%1,%2,%3,%4};"
                 :: "l"(p), "f"(a), "f"(b), "f"(c), "f"(d) : "memory");
}
__device__ __forceinline__ float ssp(float x) {
    return fmaxf(x, 0.0f) + __logf(1.0f + __expf(-fabsf(x))) - 0.69314718055994530942f;
}
__device__ __forceinline__ u32 smem_u32(const void* p) {
    u32 a; asm("{ .reg .u64 t; cvta.to.shared.u64 t, %1; cvt.u32.u64 %0, t; }" : "=r"(a) : "l"(p));
    return a;
}
__device__ __forceinline__ u32 pkbf(__nv_bfloat16 a, __nv_bfloat16 b) {
    __nv_bfloat162 t(a, b); return *(u32*)&t;
}
__device__ __forceinline__ void split2(float f0, float f1, u32& hi, u32& lo) {
    __nv_bfloat16 h0 = __float2bfloat16(f0), h1 = __float2bfloat16(f1);
    __nv_bfloat16 l0 = __float2bfloat16(f0 - __bfloat162float(h0));
    __nv_bfloat16 l1 = __float2bfloat16(f1 - __bfloat162float(h1));
    hi = pkbf(h0, h1); lo = pkbf(l0, l1);
}

// ---------------- mma.sync helpers ----------------
__device__ __forceinline__ void ldmx4(u32* r, u32 addr) {
    asm volatile("ldmatrix.sync.aligned.m8n8.x4.shared.b16 {%0,%1,%2,%3}, [%4];"
                 : "=r"(r[0]), "=r"(r[1]), "=r"(r[2]), "=r"(r[3]) : "r"(addr));
}
__device__ __forceinline__ void mma16816(float* c, const u32* a, const u32* b) {
    asm volatile("mma.sync.aligned.m16n8k16.row.col.f32.bf16.bf16.f32 "
                 "{%0,%1,%2,%3}, {%4,%5,%6,%7}, {%8,%9}, {%0,%1,%2,%3};"
                 : "+f"(c[0]), "+f"(c[1]), "+f"(c[2]), "+f"(c[3])
                 : "r"(a[0]), "r"(a[1]), "r"(a[2]), "r"(a[3]), "r"(b[0]), "r"(b[1]));
}

#define ZACC(acc) do { \
    _Pragma("unroll") for (int _m = 0; _m < 2; _m++) \
    _Pragma("unroll") for (int _n = 0; _n < 8; _n++) \
    _Pragma("unroll") for (int _q = 0; _q < 4; _q++) acc[_m][_n][_q] = 0.0f; } while (0)

template<int KS, int STRIDE>
__device__ __forceinline__ void gemm_3p(float acc[2][8][4],
        u32 AHb, u32 ALb, u32 BHb, u32 BLb) {
#pragma unroll
    for (int ks = 0; ks < KS; ks++) {
        u32 ah[2][4], al[2][4], bh[4][4], bl[4][4];
        ldmx4(ah[0], AHb + ks * 32);
        ldmx4(ah[1], AHb + 16 * STRIDE + ks * 32);
        ldmx4(al[0], ALb + ks * 32);
        ldmx4(al[1], ALb + 16 * STRIDE + ks * 32);
#pragma unroll
        for (int nb = 0; nb < 4; nb++) {
            ldmx4(bh[nb], BHb + nb * 16 * STRIDE + ks * 32);
            ldmx4(bl[nb], BLb + nb * 16 * STRIDE + ks * 32);
        }
#pragma unroll
        for (int mi = 0; mi < 2; mi++)
#pragma unroll
            for (int nb = 0; nb < 4; nb++) {
                mma16816(acc[mi][2*nb],   ah[mi], &bh[nb][0]);
                mma16816(acc[mi][2*nb+1], ah[mi], &bh[nb][2]);
                mma16816(acc[mi][2*nb],   ah[mi], &bl[nb][0]);
                mma16816(acc[mi][2*nb+1], ah[mi], &bl[nb][2]);
                mma16816(acc[mi][2*nb],   al[mi], &bh[nb][0]);
                mma16816(acc[mi][2*nb+1], al[mi], &bh[nb][2]);
            }
    }
}

// epilogue: ssp(acc + bias) -> bf16 hi/lo into 272B-stride A buffers (own subtile)
__device__ __forceinline__ void epi_ssp_split(const float acc[2][8][4],
        const float* bias, char* aH, char* aL, int r0base, int colbase) {
#pragma unroll
    for (int mi = 0; mi < 2; mi++) {
        int r0 = r0base + mi * 16;
#pragma unroll
        for (int ni = 0; ni < 8; ni++) {
            int c = colbase + ni * 8;
            float bb0 = bias[c], bb1 = bias[c + 1];
            u32 hi, lo;
            split2(ssp(acc[mi][ni][0] + bb0), ssp(acc[mi][ni][1] + bb1), hi, lo);
            *(u32*)(aH + r0 * 272 + c * 2) = hi;
            *(u32*)(aL + r0 * 272 + c * 2) = lo;
            split2(ssp(acc[mi][ni][2] + bb0), ssp(acc[mi][ni][3] + bb1), hi, lo);
            *(u32*)(aH + (r0 + 8) * 272 + c * 2) = hi;
            *(u32*)(aL + (r0 + 8) * 272 + c * 2) = lo;
        }
    }
}

// ---------------- launch 1: weights + dist/C/hist + h init + out tail ----------------
__global__ void __launch_bounds__(256) k_prep_init(
        const float* __restrict__ pos, const int* __restrict__ ei,
        const int* __restrict__ atoms, const float* __restrict__ emb,
        const float* __restrict__ mw1, const float* __restrict__ mw2,
        const float* __restrict__ cw2, const float* __restrict__ iw,
        const float* __restrict__ cw1, float* __restrict__ out) {
    int idx = blockIdx.x * 256 + threadIdx.x;   // 0..EE-1
    if (idx < NLAYER * 128 * 128) {
        int l = idx >> 14, r = idx & 16383, n = r >> 7, k = r & 127;
        int sidx = (l * 128 + k) * 128 + n;
        float v; __nv_bfloat16 hi;
        v = mw2[sidx]; hi = __float2bfloat16(v);
        g_w2tH[idx] = hi;  g_w2tL[idx] = __float2bfloat16(v - __bfloat162float(hi));
        v = cw2[sidx]; hi = __float2bfloat16(v);
        g_cw2tH[idx] = hi; g_cw2tL[idx] = __float2bfloat16(v - __bfloat162float(hi));
        v = iw[sidx]; hi = __float2bfloat16(v);
        g_iwtH[idx] = hi;  g_iwtL[idx] = __float2bfloat16(v - __bfloat162float(hi));
        v = cw1[sidx]; hi = __float2bfloat16(v);
        g_cw1tH[idx] = hi; g_cw1tL[idx] = __float2bfloat16(v - __bfloat162float(hi));
    }
    if (idx < NLAYER * 128 * 64) {
        int l = idx >> 13, r = idx & 8191, n = r >> 6, k = r & 63;
        float v = (k < NGAUSS) ? mw1[(l * NGAUSS + k) * 128 + n] : 0.0f;
        __nv_bfloat16 hi = __float2bfloat16(v);
        g_w1tH[idx] = hi;
        g_w1tL[idx] = __float2bfloat16(v - __bfloat162float(hi));
    }
    if (idx < 2 * GG) out[2 * NN + idx] = 0.0f;
    // per-edge: dist, C, dst histogram (g_cnt zeroed by previous run's k_scan_xl)
    {
        int e = idx;
        int s = ei[e], d = ei[EE + e];
        float dx = pos[3*s]   - pos[3*d];
        float dy = pos[3*s+1] - pos[3*d+1];
        float dz = pos[3*s+2] - pos[3*d+2];
        float dist = sqrtf(dx*dx + dy*dy + dz*dz);
        g_dist[e] = dist;
        g_C[e] = 0.5f * (__cosf(dist * (3.14159265358979323846f / 10.0f)) + 1.0f);
        atomicAdd(&g_cnt[d], 1);
    }
    for (int j = idx; j < NN * 32; j += EE)
        ((float4*)g_h)[j] = ((const float4*)emb)[atoms[j >> 5] * 32 + (j & 31)];
}

// ---------------- fp32 f32x2 GEMM (layer-0 xl inside k_scan_xl) ----------------
template<int K>
__device__ __forceinline__ void gemm_tile(const float* __restrict__ As,
                                          const float* __restrict__ Bs,
                                          int ty, int tx, u64 acc[8][4]) {
    const float* ap = As + ty * 8;
    const float* bp = Bs + tx * 8;
#pragma unroll 4
    for (int k = 0; k < K; k++) {
        float4 a0 = *(const float4*)(ap + k * 132);
        float4 a1 = *(const float4*)(ap + k * 132 + 4);
        float4 b0 = *(const float4*)(bp + k * 128);
        float4 b1 = *(const float4*)(bp + k * 128 + 4);
        u64 bb0 = pk2(b0.x, b0.y), bb1 = pk2(b0.z, b0.w);
        u64 bb2 = pk2(b1.x, b1.y), bb3 = pk2(b1.z, b1.w);
        float a[8] = {a0.x, a0.y, a0.z, a0.w, a1.x, a1.y, a1.z, a1.w};
#pragma unroll
        for (int i = 0; i < 8; i++) {
            u64 aa = pk2(a[i], a[i]);
            fma2(acc[i][0], aa, bb0);
            fma2(acc[i][1], aa, bb1);
            fma2(acc[i][2], aa, bb2);
            fma2(acc[i][3], aa, bb3);
        }
    }
}
#define ZERO_ACC8(acc) do { \
    _Pragma("unroll") for (int _i = 0; _i < 8; _i++) \
    _Pragma("unroll") for (int _j = 0; _j < 4; _j++) acc[_i][_j] = 0ull; } while (0)

// ---------------- launch 2: block 0 = scan (+ re-zero g_cnt), blocks 1.. = xl ----------------
__global__ void __launch_bounds__(256) k_scan_xl(const float* __restrict__ W) {
    if (blockIdx.x == 0) {
        __shared__ int warp_sums[8];
        __shared__ int s_carry;
        int tid = threadIdx.x;
        if (tid == 0) s_carry = 0;
        __syncthreads();
        for (int base = 0; base < NN; base += 256) {
            int i = base + tid;
            int v = (i < NN) ? g_cnt[i] : 0;
            int incl = v;
#pragma unroll
            for (int off = 1; off < 32; off <<= 1) {
                int n = __shfl_up_sync(0xffffffff, incl, off);
                if ((tid & 31) >= off) incl += n;
            }
            if ((tid & 31) == 31) warp_sums[tid >> 5] = incl;
            __syncthreads();
            if (tid < 8) {
                int ws = warp_sums[tid];
                int wi = ws;
#pragma unroll
                for (int off = 1; off < 8; off <<= 1) {
                    int n = __shfl_up_sync(0x000000ff, wi, off);
                    if (tid >= off) wi += n;
                }
                warp_sums[tid] = wi - ws;
            }
            __syncthreads();
            int excl = s_carry + warp_sums[tid >> 5] + incl - v;
            if (i < NN) g_cur[i] = excl;
            __syncthreads();
            if (tid == 255) s_carry = excl + v;
            __syncthreads();
        }
        for (int i = tid; i < NN; i += 256) g_cnt[i] = 0;   // reset for next run
        return;
    }
    // xl blocks
    extern __shared__ float sm[];
    float* As = sm;
    float* Bs = As + 128 * 132;
    int tid = threadIdx.x, ty = tid >> 4, tx = tid & 15;
    int row0 = (blockIdx.x - 1) * 128;
    for (int i = tid; i < 128 * 32; i += 256) {
        int r = i & 127, kq = i >> 7;
        float4 v = make_float4(0.f, 0.f, 0.f, 0.f);
        int row = row0 + r;
        if (row < NN) v = *(const float4*)(g_h + (size_t)row * 128 + kq * 4);
        As[(kq*4+0)*132 + r] = v.x;
        As[(kq*4+1)*132 + r] = v.y;
        As[(kq*4+2)*132 + r] = v.z;
        As[(kq*4+3)*132 + r] = v.w;
    }
    for (int i = tid; i < 128 * 32; i += 256)
        ((float4*)Bs)[i] = ((const float4*)W)[i];
    __syncthreads();
    u64 acc[8][4]; ZERO_ACC8(acc);
    gemm_tile<128>(As, Bs, ty, tx, acc);
#pragma unroll
    for (int i = 0; i < 8; i++) {
        int row = row0 + ty * 8 + i;
        if (row >= NN) continue;
        float v[8];
#pragma unroll
        for (int jp = 0; jp < 4; jp++) { float2 t2 = up2(acc[i][jp]); v[2*jp] = t2.x; v[2*jp+1] = t2.y; }
        *(float4*)(g_xl + (size_t)row * 128 + tx * 8)     = make_float4(v[0], v[1], v[2], v[3]);
        *(float4*)(g_xl + (size_t)row * 128 + tx * 8 + 4) = make_float4(v[4], v[5], v[6], v[7]);
    }
}

// ---------------- launch 3: permute edges into dst-sorted order ----------------
__global__ void __launch_bounds__(256) k_permute(const int* __restrict__ ei) {
    int e = blockIdx.x * 256 + threadIdx.x;
    if (e >= EE) return;
    int d = ei[EE + e];
    int pos = atomicAdd(&g_cur[d], 1);
    g_sd[pos]  = g_dist[e];
    g_sc[pos]  = g_C[e];
    g_ss[pos]  = ei[e];
    g_sdt[pos] = d;
}

// ---------------- edge pipeline: 2-sync software-pipelined tile loop ----------------
#define O_A1H 0
#define O_A1L 18432
#define O_A2H 36864            // stride 272B; per-warp msg fragment aliases OWN A2 bytes only
#define O_A2L 71680
#define O_B1H 106496
#define O_B1L 124928
#define O_B2H 143360
#define O_B2L 178176
#define O_SB1 212992
#define O_SB2 213504
#define O_SCT 214016           // [2][128] f32
#define O_SRC 215040           // [2][128] i32
#define O_SDST 216064          // [2][128] i32
#define SMEM_EDGE 217088

__global__ void __launch_bounds__(256, 1) k_edge_mma(
        int layer, const float* __restrict__ b1, const float* __restrict__ b2) {
    extern __shared__ char sp[];
    const u32 sbase = smem_u32(sp);
    int tid = threadIdx.x, lane = tid & 31, wid = tid >> 5;
    int wm = wid & 3, wn = wid >> 2;

    float* sb1f = (float*)(sp + O_SB1);
    float* sb2f = (float*)(sp + O_SB2);
    float* sct  = (float*)(sp + O_SCT);
    int*   ssrc = (int*)(sp + O_SRC);
    int*   sdst = (int*)(sp + O_SDST);

    // ---- weights to SMEM (once per launch) ----
    {
        const uint4* w1h = (const uint4*)(g_w1tH + layer * 8192);
        const uint4* w1l = (const uint4*)(g_w1tL + layer * 8192);
        for (int i = tid; i < 1024; i += 256) {
            int n = i >> 3, ch = i & 7;
            *(uint4*)(sp + O_B1H + n * 144 + ch * 16) = w1h[i];
            *(uint4*)(sp + O_B1L + n * 144 + ch * 16) = w1l[i];
        }
        const uint4* w2h = (const uint4*)(g_w2tH + layer * 16384);
        const uint4* w2l = (const uint4*)(g_w2tL + layer * 16384);
        for (int i = tid; i < 2048; i += 256) {
            int n = i >> 4, ch = i & 15;
            *(uint4*)(sp + O_B2H + n * 272 + ch * 16) = w2h[i];
            *(uint4*)(sp + O_B2L + n * 272 + ch * 16) = w2l[i];
        }
        if (tid < 128) { sb1f[tid] = b1[tid]; sb2f[tid] = b2[tid]; }
    }

    int a_r = (lane & 7) + ((lane >> 3) & 1) * 8;
    int a_k = (lane >> 4) * 8;
    int b_r = (lane & 7) + (lane >> 4) * 8;
    int b_k = ((lane >> 3) & 1) * 8;

    u32 A1H_b = sbase + O_A1H + (u32)(wm * 32 + a_r) * 144 + (u32)a_k * 2;
    u32 A1L_b = sbase + O_A1L + (u32)(wm * 32 + a_r) * 144 + (u32)a_k * 2;
    u32 B1H_b = sbase + O_B1H + (u32)(wn * 64 + b_r) * 144 + (u32)b_k * 2;
    u32 B1L_b = sbase + O_B1L + (u32)(wn * 64 + b_r) * 144 + (u32)b_k * 2;
    u32 A2H_b = sbase + O_A2H + (u32)(wm * 32 + a_r) * 272 + (u32)a_k * 2;
    u32 A2L_b = sbase + O_A2L + (u32)(wm * 32 + a_r) * 272 + (u32)a_k * 2;
    u32 B2H_b = sbase + O_B2H + (u32)(wn * 64 + b_r) * 272 + (u32)b_k * 2;
    u32 B2L_b = sbase + O_B2L + (u32)(wn * 64 + b_r) * 272 + (u32)b_k * 2;

    int r0base  = wm * 32 + (lane >> 2);
    int colbase = wn * 64 + (lane & 3) * 2;

    const float spc = 10.0f / 49.0f;
    const float coeff = -0.5f / (spc * spc);
    const int earow = tid >> 1, eahalf = tid & 1;

    // ---- prologue: EA + meta for first tile into buffer 0 ----
    {
        int e0 = blockIdx.x * 128;
        float dv = g_sd[e0 + earow];
        u32 hi[16], lo[16];
#pragma unroll
        for (int jj = 0; jj < 16; jj++) {
            int g = eahalf * 32 + 2 * jj;
            float t0 = dv - (float)g * spc;
            float t1 = dv - (float)(g + 1) * spc;
            float v0 = (g < NGAUSS)     ? __expf(coeff * t0 * t0) : 0.0f;
            float v1 = (g + 1 < NGAUSS) ? __expf(coeff * t1 * t1) : 0.0f;
            split2(v0, v1, hi[jj], lo[jj]);
        }
        char* rowH = sp + O_A1H + earow * 144 + eahalf * 64;
        char* rowL = sp + O_A1L + earow * 144 + eahalf * 64;
#pragma unroll
        for (int q = 0; q < 4; q++) {
            *(uint4*)(rowH + q * 16) = make_uint4(hi[4*q], hi[4*q+1], hi[4*q+2], hi[4*q+3]);
            *(uint4*)(rowL + q * 16) = make_uint4(lo[4*q], lo[4*q+1], lo[4*q+2], lo[4*q+3]);
        }
        if (tid < 128) {
            ssrc[tid] = g_ss[e0 + tid];
            sdst[tid] = g_sdt[e0 + tid];
            sct[tid]  = g_sc[e0 + tid];
        }
    }
    __syncthreads();

    int pb = 0;
    for (int t = blockIdx.x; t < NTILES; t += EGRID, pb ^= 1) {
        float acc[2][8][4];
        ZACC(acc);
        gemm_3p<4, 144>(acc, A1H_b, A1L_b, B1H_b, B1L_b);
        epi_ssp_split(acc, sb1f, sp + O_A2H, sp + O_A2L, r0base, colbase);
        __syncthreads();   // [A] A2 visible for GEMM2; A1 free for next EA

        // issue next tile's global loads early (latency hides under GEMM2)
        int nt = t + EGRID;
        bool hasnext = nt < NTILES;
        float dv = 0.f, pm_c = 0.f;
        int pm_s = 0, pm_d = 0;
        if (hasnext) {
            dv = g_sd[nt * 128 + earow];
            if (tid < 128) {
                pm_s = g_ss[nt * 128 + tid];
                pm_d = g_sdt[nt * 128 + tid];
                pm_c = g_sc[nt * 128 + tid];
            }
        }

        ZACC(acc);
        gemm_3p<8, 272>(acc, A2H_b, A2L_b, B2H_b, B2L_b);

        if (hasnext) {
            u32 hi[16], lo[16];
#pragma unroll
            for (int jj = 0; jj < 16; jj++) {
                int g = eahalf * 32 + 2 * jj;
                float t0 = dv - (float)g * spc;
                float t1 = dv - (float)(g + 1) * spc;
                float v0 = (g < NGAUSS)     ? __expf(coeff * t0 * t0) : 0.0f;
                float v1 = (g + 1 < NGAUSS) ? __expf(coeff * t1 * t1) : 0.0f;
                split2(v0, v1, hi[jj], lo[jj]);
            }
            char* rowH = sp + O_A1H + earow * 144 + eahalf * 64;
            char* rowL = sp + O_A1L + earow * 144 + eahalf * 64;
#pragma unroll
            for (int q = 0; q < 4; q++) {
                *(uint4*)(rowH + q * 16) = make_uint4(hi[4*q], hi[4*q+1], hi[4*q+2], hi[4*q+3]);
                *(uint4*)(rowL + q * 16) = make_uint4(lo[4*q], lo[4*q+1], lo[4*q+2], lo[4*q+3]);
            }
            int nb = (pb ^ 1) * 128;
            if (tid < 128) { ssrc[nb + tid] = pm_s; sdst[nb + tid] = pm_d; sct[nb + tid] = pm_c; }
        }
        __syncthreads();   // [B] GEMM2 A2-reads done; EA/meta visible for next iter

        // ---- epi2: msg = (acc+b2)*C into OWN A2 bytes (custom layout) ----
        const float* sctp = sct + pb * 128;
#pragma unroll
        for (int mi = 0; mi < 2; mi++) {
#pragma unroll
            for (int rr = 0; rr < 2; rr++) {
                int rt = r0base + mi * 16 + rr * 8;
                float ct = sctp[rt];
#pragma unroll
                for (int ni = 0; ni < 8; ni++) {
                    int cg = colbase + ni * 8;
                    float v0 = (acc[mi][ni][2*rr]     + sb2f[cg])     * ct;
                    float v1 = (acc[mi][ni][2*rr + 1] + sb2f[cg + 1]) * ct;
                    u32 off = (u32)((ni < 4) ? O_A2H : O_A2L)
                            + (u32)rt * 272 + (u32)(128 * wn)
                            + (u32)(((lane & 3) * 2 + (ni & 3) * 8) * 4);
                    *(float2*)(sp + off) = make_float2(v0, v1);
                }
            }
        }
        __syncwarp();

        // ---- scatter own 32 rows x 64 cols; runs over sorted dst ----
        {
            const int* sso = ssrc + pb * 128;
            const int* sdo = sdst + pb * 128;
            int half = lane >> 4, chunk = lane & 15;
            int rbeg = wm * 32 + half * 16;
            u32 moff = (u32)((chunk < 8) ? O_A2H : O_A2L)
                     + (u32)(128 * wn) + (u32)((chunk & 7) * 16);
            int coff = wn * 64 + chunk * 4;
            float4 a4 = make_float4(0.f, 0.f, 0.f, 0.f);
            int cur = sdo[rbeg];
#pragma unroll
            for (int p4 = 0; p4 < 4; p4++) {
                int r0 = rbeg + p4 * 4;
                int sr[4], sd[4];
#pragma unroll
                for (int j = 0; j < 4; j++) { sr[j] = sso[r0 + j]; sd[j] = sdo[r0 + j]; }
                float4 x[4];
#pragma unroll
                for (int j = 0; j < 4; j++)
                    x[j] = *(const float4*)(g_xl + (size_t)sr[j] * 128 + coff);
#pragma unroll
                for (int j = 0; j < 4; j++) {
                    if (sd[j] != cur) {
                        red4(g_agg + (size_t)cur * 128 + coff, a4.x, a4.y, a4.z, a4.w);
                        a4 = make_float4(0.f, 0.f, 0.f, 0.f);
                        cur = sd[j];
                    }
                    float4 m = *(const float4*)(sp + moff + (u32)(r0 + j) * 272);
                    a4.x += m.x * x[j].x; a4.y += m.y * x[j].y;
                    a4.z += m.z * x[j].z; a4.w += m.w * x[j].w;
                }
            }
            red4(g_agg + (size_t)cur * 128 + coff, a4.x, a4.y, a4.z, a4.w);
        }
    }
}

// ---------------- fused node update on mma ----------------
#define N_AH 0
#define N_AL 34816
#define N_BH 69632
#define N_BL 104448
#define SMEM_NODEM 139264

__global__ void __launch_bounds__(256, 1) k_node_mma(
        const float* __restrict__ cb2, const float* __restrict__ ib,
        int layer, int has_next) {
    extern __shared__ char sp[];
    const u32 sbase = smem_u32(sp);
    int tid = threadIdx.x, lane = tid & 31, wid = tid >> 5;
    int wm = wid & 3, wn = wid >> 2;
    int row0 = blockIdx.x * 128;

    int a_r = (lane & 7) + ((lane >> 3) & 1) * 8;
    int a_k = (lane >> 4) * 8;
    int b_r = (lane & 7) + (lane >> 4) * 8;
    int b_k = ((lane >> 3) & 1) * 8;
    u32 AH_b = sbase + N_AH + (u32)(wm * 32 + a_r) * 272 + (u32)a_k * 2;
    u32 AL_b = sbase + N_AL + (u32)(wm * 32 + a_r) * 272 + (u32)a_k * 2;
    u32 BH_b = sbase + N_BH + (u32)(wn * 64 + b_r) * 272 + (u32)b_k * 2;
    u32 BL_b = sbase + N_BL + (u32)(wn * 64 + b_r) * 272 + (u32)b_k * 2;
    int r0base  = wm * 32 + (lane >> 2);
    int colbase = wn * 64 + (lane & 3) * 2;

    for (int i = tid; i < 128 * 32; i += 256) {
        int r = i >> 5, c4 = i & 31;
        int row = row0 + r;
        float4 v = make_float4(0.f, 0.f, 0.f, 0.f);
        if (row < NN) {
            float* ap = g_agg + (size_t)row * 128 + c4 * 4;
            v = *(const float4*)ap;
            *(float4*)ap = make_float4(0.f, 0.f, 0.f, 0.f);
        }
        u32 h0, l0, h1, l1;
        split2(v.x, v.y, h0, l0);
        split2(v.z, v.w, h1, l1);
        *(uint2*)(sp + N_AH + r * 272 + c4 * 8) = make_uint2(h0, h1);
        *(uint2*)(sp + N_AL + r * 272 + c4 * 8) = make_uint2(l0, l1);
    }
    {
        const uint4* bh = (const uint4*)(g_cw2tH + layer * 16384);
        const uint4* bl = (const uint4*)(g_cw2tL + layer * 16384);
        for (int i = tid; i < 2048; i += 256) {
            int n = i >> 4, ch = i & 15;
            *(uint4*)(sp + N_BH + n * 272 + ch * 16) = bh[i];
            *(uint4*)(sp + N_BL + n * 272 + ch * 16) = bl[i];
        }
    }
    __syncthreads();

    float acc[2][8][4];
    ZACC(acc);
    gemm_3p<8, 272>(acc, AH_b, AL_b, BH_b, BL_b);
    __syncthreads();

    epi_ssp_split(acc, cb2, sp + N_AH, sp + N_AL, r0base, colbase);
    {
        const uint4* bh = (const uint4*)(g_iwtH + layer * 16384);
        const uint4* bl = (const uint4*)(g_iwtL + layer * 16384);
        for (int i = tid; i < 2048; i += 256) {
            int n = i >> 4, ch = i & 15;
            *(uint4*)(sp + N_BH + n * 272 + ch * 16) = bh[i];
            *(uint4*)(sp + N_BL + n * 272 + ch * 16) = bl[i];
        }
    }
    __syncthreads();

    ZACC(acc);
    gemm_3p<8, 272>(acc, AH_b, AL_b, BH_b, BL_b);
    __syncthreads();

#pragma unroll
    for (int mi = 0; mi < 2; mi++) {
        int r0 = r0base + mi * 16;
#pragma unroll
        for (int rr = 0; rr < 2; rr++) {
            int r = r0 + rr * 8;
            int row = row0 + r;
#pragma unroll
            for (int ni = 0; ni < 8; ni++) {
                int c = colbase + ni * 8;
                float v0 = acc[mi][ni][2*rr]     + ib[c];
                float v1 = acc[mi][ni][2*rr + 1] + ib[c + 1];
                float2 hv = make_float2(0.f, 0.f);
                float* hp = g_h + (size_t)row * 128 + c;
                if (row < NN) hv = *(const float2*)hp;
                hv.x += v0; hv.y += v1;
                if (row < NN) *(float2*)hp = hv;
                u32 hi, lo;
                split2(hv.x, hv.y, hi, lo);
                *(u32*)(sp + N_AH + r * 272 + c * 2) = hi;
                *(u32*)(sp + N_AL + r * 272 + c * 2) = lo;
            }
        }
    }
    if (has_next) {
        const uint4* bh = (const uint4*)(g_cw1tH + (layer + 1) * 16384);
        const uint4* bl = (const uint4*)(g_cw1tL + (layer + 1) * 16384);
        for (int i = tid; i < 2048; i += 256) {
            int n = i >> 4, ch = i & 15;
            *(uint4*)(sp + N_BH + n * 272 + ch * 16) = bh[i];
            *(uint4*)(sp + N_BL + n * 272 + ch * 16) = bl[i];
        }
        __syncthreads();

        ZACC(acc);
        gemm_3p<8, 272>(acc, AH_b, AL_b, BH_b, BL_b);

#pragma unroll
        for (int mi = 0; mi < 2; mi++) {
            int r0 = r0base + mi * 16;
#pragma unroll
            for (int rr = 0; rr < 2; rr++) {
                int row = row0 + r0 + rr * 8;
                if (row >= NN) continue;
#pragma unroll
                for (int ni = 0; ni < 8; ni++) {
                    int c = colbase + ni * 8;
                    *(float2*)(g_xl + (size_t)row * 128 + c) =
                        make_float2(acc[mi][ni][2*rr], acc[mi][ni][2*rr + 1]);
                }
            }
        }
    }
}

// ---------------- readout ----------------
__global__ void __launch_bounds__(128) k_read(const int* __restrict__ batch,
        const float* __restrict__ lw, const float* __restrict__ lb,
        const float* __restrict__ ew, const float* __restrict__ ebp,
        const float* __restrict__ qw, const float* __restrict__ qbp,
        float* __restrict__ out) {
    extern __shared__ float sm[];
    float* Hs  = sm;
    float* Ws  = Hs + 128 * 129;
    float* sb  = Ws + 128 * 64;
    float* sew = sb + 64;
    float* sqw = sew + 64;
    int tid = threadIdx.x;
    int row0 = blockIdx.x * 128;
    for (int i = tid; i < 128 * 128; i += 128) {
        int r = i >> 7, c = i & 127;
        int row = row0 + r;
        Hs[r * 129 + c] = (row < NN) ? g_h[(size_t)row * 128 + c] : 0.f;
    }
    for (int i = tid; i < 128 * 64; i += 128) Ws[i] = lw[i];
    if (tid < 64) { sb[tid] = lb[tid]; sew[tid] = ew[tid]; sqw[tid] = qw[tid]; }
    __syncthreads();
    int row = row0 + tid;
    if (row >= NN) return;
    float e = ebp[0], q = qbp[0];
    const float* hr = Hs + tid * 129;
#pragma unroll 2
    for (int j = 0; j < 64; j++) {
        float a = sb[j];
#pragma unroll 8
        for (int k = 0; k < 128; k++) a += hr[k] * Ws[k * 64 + j];
        float hh = ssp(a);
        e += hh * sew[j];
        q += hh * sqw[j];
    }
    out[row] = e;
    out[NN + row] = q;
    int b = batch[row];
    atomicAdd(out + 2 * NN + b, e);
    atomicAdd(out + 2 * NN + GG + b, q);
}

// ---------------- host ----------------
extern "C" void kernel_launch(void* const* d_in, const int* in_sizes, int n_in,
                              void* d_out, int out_size) {
    const int*   atoms = (const int*)d_in[0];
    const float* pos   = (const float*)d_in[1];
    const int*   batch = (const int*)d_in[2];
    const int*   ei    = (const int*)d_in[3];
    const float* emb   = (const float*)d_in[4];
    const float* mw1   = (const float*)d_in[5];
    const float* mb1   = (const float*)d_in[6];
    const float* mw2   = (const float*)d_in[7];
    const float* mb2   = (const float*)d_in[8];
    const float* cw1   = (const float*)d_in[9];
    const float* cw2   = (const float*)d_in[10];
    const float* cb2   = (const float*)d_in[11];
    const float* iw    = (const float*)d_in[12];
    const float* ib    = (const float*)d_in[13];
    const float* l1w   = (const float*)d_in[14];
    const float* l1b   = (const float*)d_in[15];
    const float* ew    = (const float*)d_in[16];
    const float* eb    = (const float*)d_in[17];
    const float* qw    = (const float*)d_in[18];
    const float* qb    = (const float*)d_in[19];
    float* out = (float*)d_out;

    constexpr int SMEM_GEMM = (128 * 132 + 128 * 128) * 4;
    constexpr int SMEM_READ = (128 * 129 + 128 * 64 + 192) * 4;

    cudaFuncSetAttribute(k_scan_xl,  cudaFuncAttributeMaxDynamicSharedMemorySize, SMEM_GEMM);
    cudaFuncSetAttribute(k_edge_mma, cudaFuncAttributeMaxDynamicSharedMemorySize, SMEM_EDGE);
    cudaFuncSetAttribute(k_node_mma, cudaFuncAttributeMaxDynamicSharedMemorySize, SMEM_NODEM);
    cudaFuncSetAttribute(k_read,     cudaFuncAttributeMaxDynamicSharedMemorySize, SMEM_READ);

    const int NODE_BLOCKS = (NN + 127) / 128;   // 391

    // launch 1..3 (edge of layer 0 is launch 4 -> gets the ncu profile)
    k_prep_init<<<EE / 256, 256>>>(pos, ei, atoms, emb, mw1, mw2, cw2, iw, cw1, out);
    k_scan_xl<<<NODE_BLOCKS + 1, 256, SMEM_GEMM>>>(cw1);
    k_permute<<<EE / 256, 256>>>(ei);

    for (int l = 0; l < NLAYER; l++) {
        k_edge_mma<<<EGRID, 256, SMEM_EDGE>>>(l, mb1 + (size_t)l * FF, mb2 + (size_t)l * FF);
        k_node_mma<<<NODE_BLOCKS, 256, SMEM_NODEM>>>(cb2 + (size_t)l * HH, ib + (size_t)l * HH,
                                                     l, (l < NLAYER - 1) ? 1 : 0);
    }
    k_read<<<NODE_BLOCKS, 128, SMEM_READ>>>(batch, l1w, l1b, ew, eb, qw, qb, out);
}

// round 7
// speedup vs baseline: 2.6593x; 1.0335x over previous
#include <cuda_runtime.h>
#include <cuda_bf16.h>
#include <cstdint>

#define NN 50000
#define EE 800000
#define GG 100
#define HH 128
#define FF 128
#define NGAUSS 50
#define NLAYER 6
#define NTILES (EE / 128)   // 6250
#define EGRID 148

typedef unsigned long long u64;
typedef unsigned int u32;

// ---------------- scratch (static device globals; no allocation) ----------------
__device__ float g_dist[EE];
__device__ float g_C[EE];
__device__ int   g_cnt[NN];     // re-zeroed by k_scan_xl each run
__device__ int   g_cur[NN];
__device__ float g_sd[EE];
__device__ float g_sc[EE];
__device__ int   g_ss[EE];
__device__ int   g_sdt[EE];
__device__ float g_h[(size_t)NN * HH];
__device__ float g_xl[(size_t)NN * FF];
__device__ float g_agg[(size_t)NN * FF];
__device__ __nv_bfloat16 g_w1tH[NLAYER * 128 * 64];
__device__ __nv_bfloat16 g_w1tL[NLAYER * 128 * 64];
__device__ __nv_bfloat16 g_w2tH[NLAYER * 128 * 128];
__device__ __nv_bfloat16 g_w2tL[NLAYER * 128 * 128];
__device__ __nv_bfloat16 g_cw2tH[NLAYER * 128 * 128];
__device__ __nv_bfloat16 g_cw2tL[NLAYER * 128 * 128];
__device__ __nv_bfloat16 g_iwtH[NLAYER * 128 * 128];
__device__ __nv_bfloat16 g_iwtL[NLAYER * 128 * 128];
__device__ __nv_bfloat16 g_cw1tH[NLAYER * 128 * 128];
__device__ __nv_bfloat16 g_cw1tL[NLAYER * 128 * 128];

// ---------------- generic helpers ----------------
__device__ __forceinline__ u64 pk2(float x, float y) {
    u64 r; asm("mov.b64 %0, {%1,%2};" : "=l"(r) : "f"(x), "f"(y)); return r;
}
__device__ __forceinline__ void fma2(u64& d, u64 a, u64 b) {
    asm("fma.rn.f32x2 %0, %1, %2, %0;" : "+l"(d) : "l"(a), "l"(b));
}
__device__ __forceinline__ float2 up2(u64 v) {
    float2 r; asm("mov.b64 {%0,%1}, %2;" : "=f"(r.x), "=f"(r.y) : "l"(v)); return r;
}
__device__ __forceinline__ void red4(float* p, float a, float b, float c, float d) {
    asm volatile("red.global.add.v4.f32 [%0], {%1,%2,%3,%4};"
                 :: "l"(p), "f"(a), "f"(b), "f"(c), "f"(d) : "memory");
}
__device__ __forceinline__ float ssp(float x) {
    return fmaxf(x, 0.0f) + __logf(1.0f + __expf(-fabsf(x))) - 0.69314718055994530942f;
}
__device__ __forceinline__ u32 smem_u32(const void* p) {
    u32 a; asm("{ .reg .u64 t; cvta.to.shared.u64 t, %1; cvt.u32.u64 %0, t; }" : "=r"(a) : "l"(p));
    return a;
}
__device__ __forceinline__ u32 pkbf(__nv_bfloat16 a, __nv_bfloat16 b) {
    __nv_bfloat162 t(a, b); return *(u32*)&t;
}
__device__ __forceinline__ void split2(float f0, float f1, u32& hi, u32& lo) {
    __nv_bfloat16 h0 = __float2bfloat16(f0), h1 = __float2bfloat16(f1);
    __nv_bfloat16 l0 = __float2bfloat16(f0 - __bfloat162float(h0));
    __nv_bfloat16 l1 = __float2bfloat16(f1 - __bfloat162float(h1));
    hi = pkbf(h0, h1); lo = pkbf(l0, l1);
}

// ---------------- mma.sync helpers ----------------
__device__ __forceinline__ void ldmx4(u32* r, u32 addr) {
    asm volatile("ldmatrix.sync.aligned.m8n8.x4.shared.b16 {%0,%1,%2,%3}, [%4];"
                 : "=r"(r[0]), "=r"(r[1]), "=r"(r[2]), "=r"(r[3]) : "r"(addr));
}
__device__ __forceinline__ void mma16816(float* c, const u32* a, const u32* b) {
    asm volatile("mma.sync.aligned.m16n8k16.row.col.f32.bf16.bf16.f32 "
                 "{%0,%1,%2,%3}, {%4,%5,%6,%7}, {%8,%9}, {%0,%1,%2,%3};"
                 : "+f"(c[0]), "+f"(c[1]), "+f"(c[2]), "+f"(c[3])
                 : "r"(a[0]), "r"(a[1]), "r"(a[2]), "r"(a[3]), "r"(b[0]), "r"(b[1]));
}

#define ZACC4(acc) do { \
    _Pragma("unroll") for (int _m = 0; _m < 2; _m++) \
    _Pragma("unroll") for (int _n = 0; _n < 4; _n++) \
    _Pragma("unroll") for (int _q = 0; _q < 4; _q++) acc[_m][_n][_q] = 0.0f; } while (0)

// 3-pass bf16x3 GEMM, warp tile 32x32 (2 m-frags x 2 n-frags)
template<int KS, int STRIDE>
__device__ __forceinline__ void gemm_3p(float acc[2][4][4],
        u32 AHb, u32 ALb, u32 BHb, u32 BLb) {
#pragma unroll
    for (int ks = 0; ks < KS; ks++) {
        u32 ah[2][4], al[2][4], bh[2][4], bl[2][4];
        ldmx4(ah[0], AHb + ks * 32);
        ldmx4(ah[1], AHb + 16 * STRIDE + ks * 32);
        ldmx4(al[0], ALb + ks * 32);
        ldmx4(al[1], ALb + 16 * STRIDE + ks * 32);
#pragma unroll
        for (int nb = 0; nb < 2; nb++) {
            ldmx4(bh[nb], BHb + nb * 16 * STRIDE + ks * 32);
            ldmx4(bl[nb], BLb + nb * 16 * STRIDE + ks * 32);
        }
#pragma unroll
        for (int mi = 0; mi < 2; mi++)
#pragma unroll
            for (int nb = 0; nb < 2; nb++) {
                mma16816(acc[mi][2*nb],   ah[mi], &bh[nb][0]);
                mma16816(acc[mi][2*nb+1], ah[mi], &bh[nb][2]);
                mma16816(acc[mi][2*nb],   ah[mi], &bl[nb][0]);
                mma16816(acc[mi][2*nb+1], ah[mi], &bl[nb][2]);
                mma16816(acc[mi][2*nb],   al[mi], &bh[nb][0]);
                mma16816(acc[mi][2*nb+1], al[mi], &bh[nb][2]);
            }
    }
}

// epilogue: ssp(acc + bias) -> bf16 hi/lo into 272B-stride A buffers (own 32x32 subtile)
__device__ __forceinline__ void epi_ssp_split(const float acc[2][4][4],
        const float* bias, char* aH, char* aL, int r0base, int colbase) {
#pragma unroll
    for (int mi = 0; mi < 2; mi++) {
        int r0 = r0base + mi * 16;
#pragma unroll
        for (int ni = 0; ni < 4; ni++) {
            int c = colbase + ni * 8;
            float bb0 = bias[c], bb1 = bias[c + 1];
            u32 hi, lo;
            split2(ssp(acc[mi][ni][0] + bb0), ssp(acc[mi][ni][1] + bb1), hi, lo);
            *(u32*)(aH + r0 * 272 + c * 2) = hi;
            *(u32*)(aL + r0 * 272 + c * 2) = lo;
            split2(ssp(acc[mi][ni][2] + bb0), ssp(acc[mi][ni][3] + bb1), hi, lo);
            *(u32*)(aH + (r0 + 8) * 272 + c * 2) = hi;
            *(u32*)(aL + (r0 + 8) * 272 + c * 2) = lo;
        }
    }
}

// ---------------- launch 1: weights + dist/C/hist + h init + out tail ----------------
__global__ void __launch_bounds__(256) k_prep_init(
        const float* __restrict__ pos, const int* __restrict__ ei,
        const int* __restrict__ atoms, const float* __restrict__ emb,
        const float* __restrict__ mw1, const float* __restrict__ mw2,
        const float* __restrict__ cw2, const float* __restrict__ iw,
        const float* __restrict__ cw1, float* __restrict__ out) {
    int idx = blockIdx.x * 256 + threadIdx.x;   // 0..EE-1
    if (idx < NLAYER * 128 * 128) {
        int l = idx >> 14, r = idx & 16383, n = r >> 7, k = r & 127;
        int sidx = (l * 128 + k) * 128 + n;
        float v; __nv_bfloat16 hi;
        v = mw2[sidx]; hi = __float2bfloat16(v);
        g_w2tH[idx] = hi;  g_w2tL[idx] = __float2bfloat16(v - __bfloat162float(hi));
        v = cw2[sidx]; hi = __float2bfloat16(v);
        g_cw2tH[idx] = hi; g_cw2tL[idx] = __float2bfloat16(v - __bfloat162float(hi));
        v = iw[sidx]; hi = __float2bfloat16(v);
        g_iwtH[idx] = hi;  g_iwtL[idx] = __float2bfloat16(v - __bfloat162float(hi));
        v = cw1[sidx]; hi = __float2bfloat16(v);
        g_cw1tH[idx] = hi; g_cw1tL[idx] = __float2bfloat16(v - __bfloat162float(hi));
    }
    if (idx < NLAYER * 128 * 64) {
        int l = idx >> 13, r = idx & 8191, n = r >> 6, k = r & 63;
        float v = (k < NGAUSS) ? mw1[(l * NGAUSS + k) * 128 + n] : 0.0f;
        __nv_bfloat16 hi = __float2bfloat16(v);
        g_w1tH[idx] = hi;
        g_w1tL[idx] = __float2bfloat16(v - __bfloat162float(hi));
    }
    if (idx < 2 * GG) out[2 * NN + idx] = 0.0f;
    {
        int e = idx;
        int s = ei[e], d = ei[EE + e];
        float dx = pos[3*s]   - pos[3*d];
        float dy = pos[3*s+1] - pos[3*d+1];
        float dz = pos[3*s+2] - pos[3*d+2];
        float dist = sqrtf(dx*dx + dy*dy + dz*dz);
        g_dist[e] = dist;
        g_C[e] = 0.5f * (__cosf(dist * (3.14159265358979323846f / 10.0f)) + 1.0f);
        atomicAdd(&g_cnt[d], 1);
    }
    for (int j = idx; j < NN * 32; j += EE)
        ((float4*)g_h)[j] = ((const float4*)emb)[atoms[j >> 5] * 32 + (j & 31)];
}

// ---------------- fp32 f32x2 GEMM (layer-0 xl inside k_scan_xl) ----------------
template<int K>
__device__ __forceinline__ void gemm_tile(const float* __restrict__ As,
                                          const float* __restrict__ Bs,
                                          int ty, int tx, u64 acc[8][4]) {
    const float* ap = As + ty * 8;
    const float* bp = Bs + tx * 8;
#pragma unroll 4
    for (int k = 0; k < K; k++) {
        float4 a0 = *(const float4*)(ap + k * 132);
        float4 a1 = *(const float4*)(ap + k * 132 + 4);
        float4 b0 = *(const float4*)(bp + k * 128);
        float4 b1 = *(const float4*)(bp + k * 128 + 4);
        u64 bb0 = pk2(b0.x, b0.y), bb1 = pk2(b0.z, b0.w);
        u64 bb2 = pk2(b1.x, b1.y), bb3 = pk2(b1.z, b1.w);
        float a[8] = {a0.x, a0.y, a0.z, a0.w, a1.x, a1.y, a1.z, a1.w};
#pragma unroll
        for (int i = 0; i < 8; i++) {
            u64 aa = pk2(a[i], a[i]);
            fma2(acc[i][0], aa, bb0);
            fma2(acc[i][1], aa, bb1);
            fma2(acc[i][2], aa, bb2);
            fma2(acc[i][3], aa, bb3);
        }
    }
}
#define ZERO_ACC8(acc) do { \
    _Pragma("unroll") for (int _i = 0; _i < 8; _i++) \
    _Pragma("unroll") for (int _j = 0; _j < 4; _j++) acc[_i][_j] = 0ull; } while (0)

// ---------------- launch 2: block 0 = scan (+ re-zero g_cnt), blocks 1.. = xl ----------------
__global__ void __launch_bounds__(256) k_scan_xl(const float* __restrict__ W) {
    if (blockIdx.x == 0) {
        __shared__ int warp_sums[8];
        __shared__ int s_carry;
        int tid = threadIdx.x;
        if (tid == 0) s_carry = 0;
        __syncthreads();
        for (int base = 0; base < NN; base += 256) {
            int i = base + tid;
            int v = (i < NN) ? g_cnt[i] : 0;
            int incl = v;
#pragma unroll
            for (int off = 1; off < 32; off <<= 1) {
                int n = __shfl_up_sync(0xffffffff, incl, off);
                if ((tid & 31) >= off) incl += n;
            }
            if ((tid & 31) == 31) warp_sums[tid >> 5] = incl;
            __syncthreads();
            if (tid < 8) {
                int ws = warp_sums[tid];
                int wi = ws;
#pragma unroll
                for (int off = 1; off < 8; off <<= 1) {
                    int n = __shfl_up_sync(0x000000ff, wi, off);
                    if (tid >= off) wi += n;
                }
                warp_sums[tid] = wi - ws;
            }
            __syncthreads();
            int excl = s_carry + warp_sums[tid >> 5] + incl - v;
            if (i < NN) g_cur[i] = excl;
            __syncthreads();
            if (tid == 255) s_carry = excl + v;
            __syncthreads();
        }
        for (int i = tid; i < NN; i += 256) g_cnt[i] = 0;
        return;
    }
    extern __shared__ float sm[];
    float* As = sm;
    float* Bs = As + 128 * 132;
    int tid = threadIdx.x, ty = tid >> 4, tx = tid & 15;
    int row0 = (blockIdx.x - 1) * 128;
    for (int i = tid; i < 128 * 32; i += 256) {
        int r = i & 127, kq = i >> 7;
        float4 v = make_float4(0.f, 0.f, 0.f, 0.f);
        int row = row0 + r;
        if (row < NN) v = *(const float4*)(g_h + (size_t)row * 128 + kq * 4);
        As[(kq*4+0)*132 + r] = v.x;
        As[(kq*4+1)*132 + r] = v.y;
        As[(kq*4+2)*132 + r] = v.z;
        As[(kq*4+3)*132 + r] = v.w;
    }
    for (int i = tid; i < 128 * 32; i += 256)
        ((float4*)Bs)[i] = ((const float4*)W)[i];
    __syncthreads();
    u64 acc[8][4]; ZERO_ACC8(acc);
    gemm_tile<128>(As, Bs, ty, tx, acc);
#pragma unroll
    for (int i = 0; i < 8; i++) {
        int row = row0 + ty * 8 + i;
        if (row >= NN) continue;
        float v[8];
#pragma unroll
        for (int jp = 0; jp < 4; jp++) { float2 t2 = up2(acc[i][jp]); v[2*jp] = t2.x; v[2*jp+1] = t2.y; }
        *(float4*)(g_xl + (size_t)row * 128 + tx * 8)     = make_float4(v[0], v[1], v[2], v[3]);
        *(float4*)(g_xl + (size_t)row * 128 + tx * 8 + 4) = make_float4(v[4], v[5], v[6], v[7]);
    }
}

// ---------------- launch 3: permute edges into dst-sorted order ----------------
__global__ void __launch_bounds__(256) k_permute(const int* __restrict__ ei) {
    int e = blockIdx.x * 256 + threadIdx.x;
    if (e >= EE) return;
    int d = ei[EE + e];
    int pos = atomicAdd(&g_cur[d], 1);
    g_sd[pos]  = g_dist[e];
    g_sc[pos]  = g_C[e];
    g_ss[pos]  = ei[e];
    g_sdt[pos] = d;
}

// ---------------- edge pipeline: 512 threads, 16 warps, 32x32 warp tiles ----------------
#define O_A1H 0
#define O_A1L 18432
#define O_A2H 36864            // stride 272B; per-warp msg fragment aliases OWN A2 bytes only
#define O_A2L 71680
#define O_B1H 106496
#define O_B1L 124928
#define O_B2H 143360
#define O_B2L 178176
#define O_SB1 212992
#define O_SB2 213504
#define O_SCT 214016           // [2][128] f32
#define O_SRC 215040           // [2][128] i32
#define O_SDST 216064          // [2][128] i32
#define SMEM_EDGE 217088

__global__ void __launch_bounds__(512, 1) k_edge_mma(
        int layer, const float* __restrict__ b1, const float* __restrict__ b2) {
    extern __shared__ char sp[];
    const u32 sbase = smem_u32(sp);
    int tid = threadIdx.x, lane = tid & 31, wid = tid >> 5;   // wid 0..15
    int wm = wid & 3, wn = wid >> 2;                           // wm 0..3 rows, wn 0..3 cols

    float* sb1f = (float*)(sp + O_SB1);
    float* sb2f = (float*)(sp + O_SB2);
    float* sct  = (float*)(sp + O_SCT);
    int*   ssrc = (int*)(sp + O_SRC);
    int*   sdst = (int*)(sp + O_SDST);

    // ---- weights to SMEM (once per launch) ----
    {
        const uint4* w1h = (const uint4*)(g_w1tH + layer * 8192);
        const uint4* w1l = (const uint4*)(g_w1tL + layer * 8192);
        for (int i = tid; i < 1024; i += 512) {
            int n = i >> 3, ch = i & 7;
            *(uint4*)(sp + O_B1H + n * 144 + ch * 16) = w1h[i];
            *(uint4*)(sp + O_B1L + n * 144 + ch * 16) = w1l[i];
        }
        const uint4* w2h = (const uint4*)(g_w2tH + layer * 16384);
        const uint4* w2l = (const uint4*)(g_w2tL + layer * 16384);
        for (int i = tid; i < 2048; i += 512) {
            int n = i >> 4, ch = i & 15;
            *(uint4*)(sp + O_B2H + n * 272 + ch * 16) = w2h[i];
            *(uint4*)(sp + O_B2L + n * 272 + ch * 16) = w2l[i];
        }
        if (tid < 128) { sb1f[tid] = b1[tid]; sb2f[tid] = b2[tid]; }
    }

    int a_r = (lane & 7) + ((lane >> 3) & 1) * 8;
    int a_k = (lane >> 4) * 8;
    int b_r = (lane & 7) + (lane >> 4) * 8;
    int b_k = ((lane >> 3) & 1) * 8;

    u32 A1H_b = sbase + O_A1H + (u32)(wm * 32 + a_r) * 144 + (u32)a_k * 2;
    u32 A1L_b = sbase + O_A1L + (u32)(wm * 32 + a_r) * 144 + (u32)a_k * 2;
    u32 B1H_b = sbase + O_B1H + (u32)(wn * 32 + b_r) * 144 + (u32)b_k * 2;
    u32 B1L_b = sbase + O_B1L + (u32)(wn * 32 + b_r) * 144 + (u32)b_k * 2;
    u32 A2H_b = sbase + O_A2H + (u32)(wm * 32 + a_r) * 272 + (u32)a_k * 2;
    u32 A2L_b = sbase + O_A2L + (u32)(wm * 32 + a_r) * 272 + (u32)a_k * 2;
    u32 B2H_b = sbase + O_B2H + (u32)(wn * 32 + b_r) * 272 + (u32)b_k * 2;
    u32 B2L_b = sbase + O_B2L + (u32)(wn * 32 + b_r) * 272 + (u32)b_k * 2;

    int r0base  = wm * 32 + (lane >> 2);
    int colbase = wn * 32 + (lane & 3) * 2;

    const float spc = 10.0f / 49.0f;
    const float coeff = -0.5f / (spc * spc);
    const int earow = tid >> 2, eaq = tid & 3;   // row 0..127, quarter 0..3 (16 gaussians)

    // ---- prologue: EA + meta for first tile ----
    {
        int e0 = blockIdx.x * 128;
        float dv = g_sd[e0 + earow];
        u32 hi[8], lo[8];
#pragma unroll
        for (int jj = 0; jj < 8; jj++) {
            int g = eaq * 16 + 2 * jj;
            float t0 = dv - (float)g * spc;
            float t1 = dv - (float)(g + 1) * spc;
            float v0 = (g < NGAUSS)     ? __expf(coeff * t0 * t0) : 0.0f;
            float v1 = (g + 1 < NGAUSS) ? __expf(coeff * t1 * t1) : 0.0f;
            split2(v0, v1, hi[jj], lo[jj]);
        }
        char* rowH = sp + O_A1H + earow * 144 + eaq * 32;
        char* rowL = sp + O_A1L + earow * 144 + eaq * 32;
        *(uint4*)(rowH)      = make_uint4(hi[0], hi[1], hi[2], hi[3]);
        *(uint4*)(rowH + 16) = make_uint4(hi[4], hi[5], hi[6], hi[7]);
        *(uint4*)(rowL)      = make_uint4(lo[0], lo[1], lo[2], lo[3]);
        *(uint4*)(rowL + 16) = make_uint4(lo[4], lo[5], lo[6], lo[7]);
        if (tid < 128) {
            ssrc[tid] = g_ss[e0 + tid];
            sdst[tid] = g_sdt[e0 + tid];
            sct[tid]  = g_sc[e0 + tid];
        }
    }
    __syncthreads();

    int pb = 0;
    for (int t = blockIdx.x; t < NTILES; t += EGRID, pb ^= 1) {
        float acc[2][4][4];
        ZACC4(acc);
        gemm_3p<4, 144>(acc, A1H_b, A1L_b, B1H_b, B1L_b);
        epi_ssp_split(acc, sb1f, sp + O_A2H, sp + O_A2L, r0base, colbase);
        __syncthreads();   // [A] A2 visible for GEMM2; A1 free for next EA

        int nt = t + EGRID;
        bool hasnext = nt < NTILES;
        float dv = 0.f, pm_c = 0.f;
        int pm_s = 0, pm_d = 0;
        if (hasnext) {
            dv = g_sd[nt * 128 + earow];
            if (tid < 128) {
                pm_s = g_ss[nt * 128 + tid];
                pm_d = g_sdt[nt * 128 + tid];
                pm_c = g_sc[nt * 128 + tid];
            }
        }

        ZACC4(acc);
        gemm_3p<8, 272>(acc, A2H_b, A2L_b, B2H_b, B2L_b);

        if (hasnext) {
            u32 hi[8], lo[8];
#pragma unroll
            for (int jj = 0; jj < 8; jj++) {
                int g = eaq * 16 + 2 * jj;
                float t0 = dv - (float)g * spc;
                float t1 = dv - (float)(g + 1) * spc;
                float v0 = (g < NGAUSS)     ? __expf(coeff * t0 * t0) : 0.0f;
                float v1 = (g + 1 < NGAUSS) ? __expf(coeff * t1 * t1) : 0.0f;
                split2(v0, v1, hi[jj], lo[jj]);
            }
            char* rowH = sp + O_A1H + earow * 144 + eaq * 32;
            char* rowL = sp + O_A1L + earow * 144 + eaq * 32;
            *(uint4*)(rowH)      = make_uint4(hi[0], hi[1], hi[2], hi[3]);
            *(uint4*)(rowH + 16) = make_uint4(hi[4], hi[5], hi[6], hi[7]);
            *(uint4*)(rowL)      = make_uint4(lo[0], lo[1], lo[2], lo[3]);
            *(uint4*)(rowL + 16) = make_uint4(lo[4], lo[5], lo[6], lo[7]);
            int nb = (pb ^ 1) * 128;
            if (tid < 128) { ssrc[nb + tid] = pm_s; sdst[nb + tid] = pm_d; sct[nb + tid] = pm_c; }
        }
        __syncthreads();   // [B] GEMM2 A2-reads done; EA/meta visible for next iter

        // ---- epi2: msg = (acc+b2)*C into OWN A2 bytes ----
        // layout per row: f32 local col lc = (lane&3)*2 + (ni&1)*8 (+16 if ni>=2 -> A2L)
        const float* sctp = sct + pb * 128;
#pragma unroll
        for (int mi = 0; mi < 2; mi++) {
#pragma unroll
            for (int rr = 0; rr < 2; rr++) {
                int rt = r0base + mi * 16 + rr * 8;
                float ct = sctp[rt];
#pragma unroll
                for (int ni = 0; ni < 4; ni++) {
                    int cg = colbase + ni * 8;
                    float v0 = (acc[mi][ni][2*rr]     + sb2f[cg])     * ct;
                    float v1 = (acc[mi][ni][2*rr + 1] + sb2f[cg + 1]) * ct;
                    u32 off = (u32)((ni < 2) ? O_A2H : O_A2L)
                            + (u32)rt * 272 + (u32)(64 * wn)
                            + (u32)(((lane & 3) * 2 + (ni & 1) * 8) * 4);
                    *(float2*)(sp + off) = make_float2(v0, v1);
                }
            }
        }
        __syncwarp();

        // ---- scatter own 32 rows x 32 cols; 4 row-groups of 8 per warp ----
        {
            const int* sso = ssrc + pb * 128;
            const int* sdo = sdst + pb * 128;
            int grp = lane >> 3, chunk = lane & 7;
            int rbeg = wm * 32 + grp * 8;
            u32 moff = (u32)((chunk < 4) ? O_A2H : O_A2L)
                     + (u32)(64 * wn) + (u32)((chunk & 3) * 16);
            int coff = wn * 32 + chunk * 4;
            float4 a4 = make_float4(0.f, 0.f, 0.f, 0.f);
            int cur = sdo[rbeg];
#pragma unroll
            for (int p4 = 0; p4 < 2; p4++) {
                int r0 = rbeg + p4 * 4;
                int sr[4], sd[4];
#pragma unroll
                for (int j = 0; j < 4; j++) { sr[j] = sso[r0 + j]; sd[j] = sdo[r0 + j]; }
                float4 x[4];
#pragma unroll
                for (int j = 0; j < 4; j++)
                    x[j] = *(const float4*)(g_xl + (size_t)sr[j] * 128 + coff);
#pragma unroll
                for (int j = 0; j < 4; j++) {
                    if (sd[j] != cur) {
                        red4(g_agg + (size_t)cur * 128 + coff, a4.x, a4.y, a4.z, a4.w);
                        a4 = make_float4(0.f, 0.f, 0.f, 0.f);
                        cur = sd[j];
                    }
                    float4 m = *(const float4*)(sp + moff + (u32)(r0 + j) * 272);
                    a4.x += m.x * x[j].x; a4.y += m.y * x[j].y;
                    a4.z += m.z * x[j].z; a4.w += m.w * x[j].w;
                }
            }
            red4(g_agg + (size_t)cur * 128 + coff, a4.x, a4.y, a4.z, a4.w);
        }
    }
}

// ---------------- fused node update: 512 threads, 32x32 warp tiles ----------------
#define N_AH 0
#define N_AL 34816
#define N_BH 69632
#define N_BL 104448
#define SMEM_NODEM 139264

__global__ void __launch_bounds__(512, 1) k_node_mma(
        const float* __restrict__ cb2, const float* __restrict__ ib,
        int layer, int has_next) {
    extern __shared__ char sp[];
    const u32 sbase = smem_u32(sp);
    int tid = threadIdx.x, lane = tid & 31, wid = tid >> 5;
    int wm = wid & 3, wn = wid >> 2;
    int row0 = blockIdx.x * 128;

    int a_r = (lane & 7) + ((lane >> 3) & 1) * 8;
    int a_k = (lane >> 4) * 8;
    int b_r = (lane & 7) + (lane >> 4) * 8;
    int b_k = ((lane >> 3) & 1) * 8;
    u32 AH_b = sbase + N_AH + (u32)(wm * 32 + a_r) * 272 + (u32)a_k * 2;
    u32 AL_b = sbase + N_AL + (u32)(wm * 32 + a_r) * 272 + (u32)a_k * 2;
    u32 BH_b = sbase + N_BH + (u32)(wn * 32 + b_r) * 272 + (u32)b_k * 2;
    u32 BL_b = sbase + N_BL + (u32)(wn * 32 + b_r) * 272 + (u32)b_k * 2;
    int r0base  = wm * 32 + (lane >> 2);
    int colbase = wn * 32 + (lane & 3) * 2;

    for (int i = tid; i < 128 * 32; i += 512) {
        int r = i >> 5, c4 = i & 31;
        int row = row0 + r;
        float4 v = make_float4(0.f, 0.f, 0.f, 0.f);
        if (row < NN) {
            float* ap = g_agg + (size_t)row * 128 + c4 * 4;
            v = *(const float4*)ap;
            *(float4*)ap = make_float4(0.f, 0.f, 0.f, 0.f);
        }
        u32 h0, l0, h1, l1;
        split2(v.x, v.y, h0, l0);
        split2(v.z, v.w, h1, l1);
        *(uint2*)(sp + N_AH + r * 272 + c4 * 8) = make_uint2(h0, h1);
        *(uint2*)(sp + N_AL + r * 272 + c4 * 8) = make_uint2(l0, l1);
    }
    {
        const uint4* bh = (const uint4*)(g_cw2tH + layer * 16384);
        const uint4* bl = (const uint4*)(g_cw2tL + layer * 16384);
        for (int i = tid; i < 2048; i += 512) {
            int n = i >> 4, ch = i & 15;
            *(uint4*)(sp + N_BH + n * 272 + ch * 16) = bh[i];
            *(uint4*)(sp + N_BL + n * 272 + ch * 16) = bl[i];
        }
    }
    __syncthreads();

    float acc[2][4][4];
    ZACC4(acc);
    gemm_3p<8, 272>(acc, AH_b, AL_b, BH_b, BL_b);
    __syncthreads();

    epi_ssp_split(acc, cb2, sp + N_AH, sp + N_AL, r0base, colbase);
    {
        const uint4* bh = (const uint4*)(g_iwtH + layer * 16384);
        const uint4* bl = (const uint4*)(g_iwtL + layer * 16384);
        for (int i = tid; i < 2048; i += 512) {
            int n = i >> 4, ch = i & 15;
            *(uint4*)(sp + N_BH + n * 272 + ch * 16) = bh[i];
            *(uint4*)(sp + N_BL + n * 272 + ch * 16) = bl[i];
        }
    }
    __syncthreads();

    ZACC4(acc);
    gemm_3p<8, 272>(acc, AH_b, AL_b, BH_b, BL_b);
    __syncthreads();

#pragma unroll
    for (int mi = 0; mi < 2; mi++) {
        int r0 = r0base + mi * 16;
#pragma unroll
        for (int rr = 0; rr < 2; rr++) {
            int r = r0 + rr * 8;
            int row = row0 + r;
#pragma unroll
            for (int ni = 0; ni < 4; ni++) {
                int c = colbase + ni * 8;
                float v0 = acc[mi][ni][2*rr]     + ib[c];
                float v1 = acc[mi][ni][2*rr + 1] + ib[c + 1];
                float2 hv = make_float2(0.f, 0.f);
                float* hp = g_h + (size_t)row * 128 + c;
                if (row < NN) hv = *(const float2*)hp;
                hv.x += v0; hv.y += v1;
                if (row < NN) *(float2*)hp = hv;
                u32 hi, lo;
                split2(hv.x, hv.y, hi, lo);
                *(u32*)(sp + N_AH + r * 272 + c * 2) = hi;
                *(u32*)(sp + N_AL + r * 272 + c * 2) = lo;
            }
        }
    }
    if (has_next) {
        const uint4* bh = (const uint4*)(g_cw1tH + (layer + 1) * 16384);
        const uint4* bl = (const uint4*)(g_cw1tL + (layer + 1) * 16384);
        for (int i = tid; i < 2048; i += 512) {
            int n = i >> 4, ch = i & 15;
            *(uint4*)(sp + N_BH + n * 272 + ch * 16) = bh[i];
            *(uint4*)(sp + N_BL + n * 272 + ch * 16) = bl[i];
        }
        __syncthreads();

        ZACC4(acc);
        gemm_3p<8, 272>(acc, AH_b, AL_b, BH_b, BL_b);

#pragma unroll
        for (int mi = 0; mi < 2; mi++) {
            int r0 = r0base + mi * 16;
#pragma unroll
            for (int rr = 0; rr < 2; rr++) {
                int row = row0 + r0 + rr * 8;
                if (row >= NN) continue;
#pragma unroll
                for (int ni = 0; ni < 4; ni++) {
                    int c = colbase + ni * 8;
                    *(float2*)(g_xl + (size_t)row * 128 + c) =
                        make_float2(acc[mi][ni][2*rr], acc[mi][ni][2*rr + 1]);
                }
            }
        }
    }
}

// ---------------- readout ----------------
__global__ void __launch_bounds__(128) k_read(const int* __restrict__ batch,
        const float* __restrict__ lw, const float* __restrict__ lb,
        const float* __restrict__ ew, const float* __restrict__ ebp,
        const float* __restrict__ qw, const float* __restrict__ qbp,
        float* __restrict__ out) {
    extern __shared__ float sm[];
    float* Hs  = sm;
    float* Ws  = Hs + 128 * 129;
    float* sb  = Ws + 128 * 64;
    float* sew = sb + 64;
    float* sqw = sew + 64;
    int tid = threadIdx.x;
    int row0 = blockIdx.x * 128;
    for (int i = tid; i < 128 * 128; i += 128) {
        int r = i >> 7, c = i & 127;
        int row = row0 + r;
        Hs[r * 129 + c] = (row < NN) ? g_h[(size_t)row * 128 + c] : 0.f;
    }
    for (int i = tid; i < 128 * 64; i += 128) Ws[i] = lw[i];
    if (tid < 64) { sb[tid] = lb[tid]; sew[tid] = ew[tid]; sqw[tid] = qw[tid]; }
    __syncthreads();
    int row = row0 + tid;
    if (row >= NN) return;
    float e = ebp[0], q = qbp[0];
    const float* hr = Hs + tid * 129;
#pragma unroll 2
    for (int j = 0; j < 64; j++) {
        float a = sb[j];
#pragma unroll 8
        for (int k = 0; k < 128; k++) a += hr[k] * Ws[k * 64 + j];
        float hh = ssp(a);
        e += hh * sew[j];
        q += hh * sqw[j];
    }
    out[row] = e;
    out[NN + row] = q;
    int b = batch[row];
    atomicAdd(out + 2 * NN + b, e);
    atomicAdd(out + 2 * NN + GG + b, q);
}

// ---------------- host ----------------
extern "C" void kernel_launch(void* const* d_in, const int* in_sizes, int n_in,
                              void* d_out, int out_size) {
    const int*   atoms = (const int*)d_in[0];
    const float* pos   = (const float*)d_in[1];
    const int*   batch = (const int*)d_in[2];
    const int*   ei    = (const int*)d_in[3];
    const float* emb   = (const float*)d_in[4];
    const float* mw1   = (const float*)d_in[5];
    const float* mb1   = (const float*)d_in[6];
    const float* mw2   = (const float*)d_in[7];
    const float* mb2   = (const float*)d_in[8];
    const float* cw1   = (const float*)d_in[9];
    const float* cw2   = (const float*)d_in[10];
    const float* cb2   = (const float*)d_in[11];
    const float* iw    = (const float*)d_in[12];
    const float* ib    = (const float*)d_in[13];
    const float* l1w   = (const float*)d_in[14];
    const float* l1b   = (const float*)d_in[15];
    const float* ew    = (const float*)d_in[16];
    const float* eb    = (const float*)d_in[17];
    const float* qw    = (const float*)d_in[18];
    const float* qb    = (const float*)d_in[19];
    float* out = (float*)d_out;

    constexpr int SMEM_GEMM = (128 * 132 + 128 * 128) * 4;
    constexpr int SMEM_READ = (128 * 129 + 128 * 64 + 192) * 4;

    cudaFuncSetAttribute(k_scan_xl,  cudaFuncAttributeMaxDynamicSharedMemorySize, SMEM_GEMM);
    cudaFuncSetAttribute(k_edge_mma, cudaFuncAttributeMaxDynamicSharedMemorySize, SMEM_EDGE);
    cudaFuncSetAttribute(k_node_mma, cudaFuncAttributeMaxDynamicSharedMemorySize, SMEM_NODEM);
    cudaFuncSetAttribute(k_read,     cudaFuncAttributeMaxDynamicSharedMemorySize, SMEM_READ);

    const int NODE_BLOCKS = (NN + 127) / 128;   // 391

    k_prep_init<<<EE / 256, 256>>>(pos, ei, atoms, emb, mw1, mw2, cw2, iw, cw1, out);
    k_scan_xl<<<NODE_BLOCKS + 1, 256, SMEM_GEMM>>>(cw1);
    k_permute<<<EE / 256, 256>>>(ei);

    for (int l = 0; l < NLAYER; l++) {
        k_edge_mma<<<EGRID, 512, SMEM_EDGE>>>(l, mb1 + (size_t)l * FF, mb2 + (size_t)l * FF);
        k_node_mma<<<NODE_BLOCKS, 512, SMEM_NODEM>>>(cb2 + (size_t)l * HH, ib + (size_t)l * HH,
                                                     l, (l < NLAYER - 1) ? 1 : 0);
    }
    k_read<<<NODE_BLOCKS, 128, SMEM_READ>>>(batch, l1w, l1b, ew, eb, qw, qb, out);
}

// round 8
// speedup vs baseline: 3.1568x; 1.1871x over previous
#include <cuda_runtime.h>
#include <cuda_fp16.h>
#include <cstdint>

#define NN 50000
#define EE 800000
#define GG 100
#define HH 128
#define FF 128
#define NGAUSS 50
#define NLAYER 6
#define NTILES (EE / 128)   // 6250
#define EGRID 148

typedef unsigned long long u64;
typedef unsigned int u32;

// ---------------- scratch (static device globals; no allocation) ----------------
__device__ float g_dist[EE];
__device__ float g_C[EE];
__device__ int   g_cnt[NN];     // re-zeroed by k_scan_xl each run
__device__ int   g_cur[NN];
__device__ float g_sd[EE];
__device__ float g_sc[EE];
__device__ int   g_ss[EE];
__device__ int   g_sdt[EE];
__device__ float g_h[(size_t)NN * HH];
__device__ float g_xl[(size_t)NN * FF];
__device__ float g_agg[(size_t)NN * FF];
// weights, fp16 hi/lo, [n][k] layout
__device__ __half g_w1tH[NLAYER * 128 * 64];
__device__ __half g_w1tL[NLAYER * 128 * 64];
__device__ __half g_w2tH[NLAYER * 128 * 128];
__device__ __half g_w2tL[NLAYER * 128 * 128];
__device__ __half g_cw2tH[NLAYER * 128 * 128];
__device__ __half g_cw2tL[NLAYER * 128 * 128];
__device__ __half g_iwtH[NLAYER * 128 * 128];
__device__ __half g_iwtL[NLAYER * 128 * 128];
__device__ __half g_cw1tH[NLAYER * 128 * 128];
__device__ __half g_cw1tL[NLAYER * 128 * 128];

// ---------------- generic helpers ----------------
__device__ __forceinline__ u64 pk2(float x, float y) {
    u64 r; asm("mov.b64 %0, {%1,%2};" : "=l"(r) : "f"(x), "f"(y)); return r;
}
__device__ __forceinline__ void fma2(u64& d, u64 a, u64 b) {
    asm("fma.rn.f32x2 %0, %1, %2, %0;" : "+l"(d) : "l"(a), "l"(b));
}
__device__ __forceinline__ float2 up2(u64 v) {
    float2 r; asm("mov.b64 {%0,%1}, %2;" : "=f"(r.x), "=f"(r.y) : "l"(v)); return r;
}
__device__ __forceinline__ void red4(float* p, float a, float b, float c, float d) {
    asm volatile("red.global.add.v4.f32 [%0], {%1,%2,%3,%4};"
                 :: "l"(p), "f"(a), "f"(b), "f"(c), "f"(d) : "memory");
}
__device__ __forceinline__ float ssp(float x) {
    return fmaxf(x, 0.0f) + __logf(1.0f + __expf(-fabsf(x))) - 0.69314718055994530942f;
}
__device__ __forceinline__ u32 smem_u32(const void* p) {
    u32 a; asm("{ .reg .u64 t; cvta.to.shared.u64 t, %1; cvt.u32.u64 %0, t; }" : "=r"(a) : "l"(p));
    return a;
}
__device__ __forceinline__ u32 pkh2(float x, float y) {
    __half2 t = __floats2half2_rn(x, y); return *(u32*)&t;
}

// ---------------- mma.sync fp16 helpers ----------------
__device__ __forceinline__ void ldmx4(u32* r, u32 addr) {
    asm volatile("ldmatrix.sync.aligned.m8n8.x4.shared.b16 {%0,%1,%2,%3}, [%4];"
                 : "=r"(r[0]), "=r"(r[1]), "=r"(r[2]), "=r"(r[3]) : "r"(addr));
}
__device__ __forceinline__ void mma16816(float* c, const u32* a, const u32* b) {
    asm volatile("mma.sync.aligned.m16n8k16.row.col.f32.f16.f16.f32 "
                 "{%0,%1,%2,%3}, {%4,%5,%6,%7}, {%8,%9}, {%0,%1,%2,%3};"
                 : "+f"(c[0]), "+f"(c[1]), "+f"(c[2]), "+f"(c[3])
                 : "r"(a[0]), "r"(a[1]), "r"(a[2]), "r"(a[3]), "r"(b[0]), "r"(b[1]));
}

#define ZACC4(acc) do { \
    _Pragma("unroll") for (int _m = 0; _m < 2; _m++) \
    _Pragma("unroll") for (int _n = 0; _n < 4; _n++) \
    _Pragma("unroll") for (int _q = 0; _q < 4; _q++) acc[_m][_n][_q] = 0.0f; } while (0)

// 2-pass fp16 GEMM (A single, B hi+lo), warp tile 32x32
template<int KS, int STRIDE>
__device__ __forceinline__ void gemm_2p(float acc[2][4][4],
        u32 Ab, u32 BHb, u32 BLb) {
#pragma unroll
    for (int ks = 0; ks < KS; ks++) {
        u32 ah[2][4], bh[2][4], bl[2][4];
        ldmx4(ah[0], Ab + ks * 32);
        ldmx4(ah[1], Ab + 16 * STRIDE + ks * 32);
#pragma unroll
        for (int nb = 0; nb < 2; nb++) {
            ldmx4(bh[nb], BHb + nb * 16 * STRIDE + ks * 32);
            ldmx4(bl[nb], BLb + nb * 16 * STRIDE + ks * 32);
        }
#pragma unroll
        for (int mi = 0; mi < 2; mi++)
#pragma unroll
            for (int nb = 0; nb < 2; nb++) {
                mma16816(acc[mi][2*nb],   ah[mi], &bh[nb][0]);
                mma16816(acc[mi][2*nb+1], ah[mi], &bh[nb][2]);
                mma16816(acc[mi][2*nb],   ah[mi], &bl[nb][0]);
                mma16816(acc[mi][2*nb+1], ah[mi], &bl[nb][2]);
            }
    }
}

// epilogue: ssp(acc + bias) -> single fp16 into 272B-stride A buffer (own 32x32 subtile)
__device__ __forceinline__ void epi_ssp_h(const float acc[2][4][4],
        const float* bias, char* aH, int r0base, int colbase) {
#pragma unroll
    for (int mi = 0; mi < 2; mi++) {
        int r0 = r0base + mi * 16;
#pragma unroll
        for (int ni = 0; ni < 4; ni++) {
            int c = colbase + ni * 8;
            float bb0 = bias[c], bb1 = bias[c + 1];
            *(u32*)(aH + r0 * 272 + c * 2) =
                pkh2(ssp(acc[mi][ni][0] + bb0), ssp(acc[mi][ni][1] + bb1));
            *(u32*)(aH + (r0 + 8) * 272 + c * 2) =
                pkh2(ssp(acc[mi][ni][2] + bb0), ssp(acc[mi][ni][3] + bb1));
        }
    }
}

// ---------------- launch 1: weights + dist/C/hist + h init + out tail ----------------
__global__ void __launch_bounds__(256) k_prep_init(
        const float* __restrict__ pos, const int* __restrict__ ei,
        const int* __restrict__ atoms, const float* __restrict__ emb,
        const float* __restrict__ mw1, const float* __restrict__ mw2,
        const float* __restrict__ cw2, const float* __restrict__ iw,
        const float* __restrict__ cw1, float* __restrict__ out) {
    int idx = blockIdx.x * 256 + threadIdx.x;   // 0..EE-1
    if (idx < NLAYER * 128 * 128) {
        int l = idx >> 14, r = idx & 16383, n = r >> 7, k = r & 127;
        int sidx = (l * 128 + k) * 128 + n;
        float v; __half hi;
        v = mw2[sidx]; hi = __float2half_rn(v);
        g_w2tH[idx] = hi;  g_w2tL[idx] = __float2half_rn(v - __half2float(hi));
        v = cw2[sidx]; hi = __float2half_rn(v);
        g_cw2tH[idx] = hi; g_cw2tL[idx] = __float2half_rn(v - __half2float(hi));
        v = iw[sidx]; hi = __float2half_rn(v);
        g_iwtH[idx] = hi;  g_iwtL[idx] = __float2half_rn(v - __half2float(hi));
        v = cw1[sidx]; hi = __float2half_rn(v);
        g_cw1tH[idx] = hi; g_cw1tL[idx] = __float2half_rn(v - __half2float(hi));
    }
    if (idx < NLAYER * 128 * 64) {
        int l = idx >> 13, r = idx & 8191, n = r >> 6, k = r & 63;
        float v = (k < NGAUSS) ? mw1[(l * NGAUSS + k) * 128 + n] : 0.0f;
        __half hi = __float2half_rn(v);
        g_w1tH[idx] = hi;
        g_w1tL[idx] = __float2half_rn(v - __half2float(hi));
    }
    if (idx < 2 * GG) out[2 * NN + idx] = 0.0f;
    {
        int e = idx;
        int s = ei[e], d = ei[EE + e];
        float dx = pos[3*s]   - pos[3*d];
        float dy = pos[3*s+1] - pos[3*d+1];
        float dz = pos[3*s+2] - pos[3*d+2];
        float dist = sqrtf(dx*dx + dy*dy + dz*dz);
        g_dist[e] = dist;
        g_C[e] = 0.5f * (__cosf(dist * (3.14159265358979323846f / 10.0f)) + 1.0f);
        atomicAdd(&g_cnt[d], 1);
    }
    for (int j = idx; j < NN * 32; j += EE)
        ((float4*)g_h)[j] = ((const float4*)emb)[atoms[j >> 5] * 32 + (j & 31)];
}

// ---------------- fp32 f32x2 GEMM (layer-0 xl inside k_scan_xl) ----------------
template<int K>
__device__ __forceinline__ void gemm_tile(const float* __restrict__ As,
                                          const float* __restrict__ Bs,
                                          int ty, int tx, u64 acc[8][4]) {
    const float* ap = As + ty * 8;
    const float* bp = Bs + tx * 8;
#pragma unroll 4
    for (int k = 0; k < K; k++) {
        float4 a0 = *(const float4*)(ap + k * 132);
        float4 a1 = *(const float4*)(ap + k * 132 + 4);
        float4 b0 = *(const float4*)(bp + k * 128);
        float4 b1 = *(const float4*)(bp + k * 128 + 4);
        u64 bb0 = pk2(b0.x, b0.y), bb1 = pk2(b0.z, b0.w);
        u64 bb2 = pk2(b1.x, b1.y), bb3 = pk2(b1.z, b1.w);
        float a[8] = {a0.x, a0.y, a0.z, a0.w, a1.x, a1.y, a1.z, a1.w};
#pragma unroll
        for (int i = 0; i < 8; i++) {
            u64 aa = pk2(a[i], a[i]);
            fma2(acc[i][0], aa, bb0);
            fma2(acc[i][1], aa, bb1);
            fma2(acc[i][2], aa, bb2);
            fma2(acc[i][3], aa, bb3);
        }
    }
}
#define ZERO_ACC8(acc) do { \
    _Pragma("unroll") for (int _i = 0; _i < 8; _i++) \
    _Pragma("unroll") for (int _j = 0; _j < 4; _j++) acc[_i][_j] = 0ull; } while (0)

// ---------------- launch 2: block 0 = scan (+ re-zero g_cnt), blocks 1.. = xl ----------------
__global__ void __launch_bounds__(256) k_scan_xl(const float* __restrict__ W) {
    if (blockIdx.x == 0) {
        __shared__ int warp_sums[8];
        __shared__ int s_carry;
        int tid = threadIdx.x;
        if (tid == 0) s_carry = 0;
        __syncthreads();
        for (int base = 0; base < NN; base += 256) {
            int i = base + tid;
            int v = (i < NN) ? g_cnt[i] : 0;
            int incl = v;
#pragma unroll
            for (int off = 1; off < 32; off <<= 1) {
                int n = __shfl_up_sync(0xffffffff, incl, off);
                if ((tid & 31) >= off) incl += n;
            }
            if ((tid & 31) == 31) warp_sums[tid >> 5] = incl;
            __syncthreads();
            if (tid < 8) {
                int ws = warp_sums[tid];
                int wi = ws;
#pragma unroll
                for (int off = 1; off < 8; off <<= 1) {
                    int n = __shfl_up_sync(0x000000ff, wi, off);
                    if (tid >= off) wi += n;
                }
                warp_sums[tid] = wi - ws;
            }
            __syncthreads();
            int excl = s_carry + warp_sums[tid >> 5] + incl - v;
            if (i < NN) g_cur[i] = excl;
            __syncthreads();
            if (tid == 255) s_carry = excl + v;
            __syncthreads();
        }
        for (int i = tid; i < NN; i += 256) g_cnt[i] = 0;
        return;
    }
    extern __shared__ float sm[];
    float* As = sm;
    float* Bs = As + 128 * 132;
    int tid = threadIdx.x, ty = tid >> 4, tx = tid & 15;
    int row0 = (blockIdx.x - 1) * 128;
    for (int i = tid; i < 128 * 32; i += 256) {
        int r = i & 127, kq = i >> 7;
        float4 v = make_float4(0.f, 0.f, 0.f, 0.f);
        int row = row0 + r;
        if (row < NN) v = *(const float4*)(g_h + (size_t)row * 128 + kq * 4);
        As[(kq*4+0)*132 + r] = v.x;
        As[(kq*4+1)*132 + r] = v.y;
        As[(kq*4+2)*132 + r] = v.z;
        As[(kq*4+3)*132 + r] = v.w;
    }
    for (int i = tid; i < 128 * 32; i += 256)
        ((float4*)Bs)[i] = ((const float4*)W)[i];
    __syncthreads();
    u64 acc[8][4]; ZERO_ACC8(acc);
    gemm_tile<128>(As, Bs, ty, tx, acc);
#pragma unroll
    for (int i = 0; i < 8; i++) {
        int row = row0 + ty * 8 + i;
        if (row >= NN) continue;
        float v[8];
#pragma unroll
        for (int jp = 0; jp < 4; jp++) { float2 t2 = up2(acc[i][jp]); v[2*jp] = t2.x; v[2*jp+1] = t2.y; }
        *(float4*)(g_xl + (size_t)row * 128 + tx * 8)     = make_float4(v[0], v[1], v[2], v[3]);
        *(float4*)(g_xl + (size_t)row * 128 + tx * 8 + 4) = make_float4(v[4], v[5], v[6], v[7]);
    }
}

// ---------------- launch 3: permute edges into dst-sorted order ----------------
__global__ void __launch_bounds__(256) k_permute(const int* __restrict__ ei) {
    int e = blockIdx.x * 256 + threadIdx.x;
    if (e >= EE) return;
    int d = ei[EE + e];
    int pos = atomicAdd(&g_cur[d], 1);
    g_sd[pos]  = g_dist[e];
    g_sc[pos]  = g_C[e];
    g_ss[pos]  = ei[e];
    g_sdt[pos] = d;
}

// ---------------- edge pipeline: fp16 2-pass, 512 threads, 32x32 warp tiles ----------------
#define O_A1H 0
#define O_B1H 18432
#define O_B1L 36864
#define O_A2H 55296
#define O_B2H 90112
#define O_B2L 124928
#define O_MSG 159744           // 128 rows x 512B (fp32 msg)
#define O_SB1 225280
#define O_SB2 225792
#define O_SCT 226304           // [2][128] f32
#define O_SRC 227328           // [2][128] i32
#define O_SDST 228352          // [2][128] i32
#define SMEM_EDGE 229376

__global__ void __launch_bounds__(512, 1) k_edge_mma(
        int layer, const float* __restrict__ b1, const float* __restrict__ b2) {
    extern __shared__ char sp[];
    const u32 sbase = smem_u32(sp);
    int tid = threadIdx.x, lane = tid & 31, wid = tid >> 5;   // wid 0..15
    int wm = wid & 3, wn = wid >> 2;

    float* sb1f = (float*)(sp + O_SB1);
    float* sb2f = (float*)(sp + O_SB2);
    float* sct  = (float*)(sp + O_SCT);
    int*   ssrc = (int*)(sp + O_SRC);
    int*   sdst = (int*)(sp + O_SDST);

    // ---- weights to SMEM (once per launch) ----
    {
        const uint4* w1h = (const uint4*)(g_w1tH + layer * 8192);
        const uint4* w1l = (const uint4*)(g_w1tL + layer * 8192);
        for (int i = tid; i < 1024; i += 512) {
            int n = i >> 3, ch = i & 7;
            *(uint4*)(sp + O_B1H + n * 144 + ch * 16) = w1h[i];
            *(uint4*)(sp + O_B1L + n * 144 + ch * 16) = w1l[i];
        }
        const uint4* w2h = (const uint4*)(g_w2tH + layer * 16384);
        const uint4* w2l = (const uint4*)(g_w2tL + layer * 16384);
        for (int i = tid; i < 2048; i += 512) {
            int n = i >> 4, ch = i & 15;
            *(uint4*)(sp + O_B2H + n * 272 + ch * 16) = w2h[i];
            *(uint4*)(sp + O_B2L + n * 272 + ch * 16) = w2l[i];
        }
        if (tid < 128) { sb1f[tid] = b1[tid]; sb2f[tid] = b2[tid]; }
    }

    int a_r = (lane & 7) + ((lane >> 3) & 1) * 8;
    int a_k = (lane >> 4) * 8;
    int b_r = (lane & 7) + (lane >> 4) * 8;
    int b_k = ((lane >> 3) & 1) * 8;

    u32 A1_b  = sbase + O_A1H + (u32)(wm * 32 + a_r) * 144 + (u32)a_k * 2;
    u32 B1H_b = sbase + O_B1H + (u32)(wn * 32 + b_r) * 144 + (u32)b_k * 2;
    u32 B1L_b = sbase + O_B1L + (u32)(wn * 32 + b_r) * 144 + (u32)b_k * 2;
    u32 A2_b  = sbase + O_A2H + (u32)(wm * 32 + a_r) * 272 + (u32)a_k * 2;
    u32 B2H_b = sbase + O_B2H + (u32)(wn * 32 + b_r) * 272 + (u32)b_k * 2;
    u32 B2L_b = sbase + O_B2L + (u32)(wn * 32 + b_r) * 272 + (u32)b_k * 2;

    int r0base  = wm * 32 + (lane >> 2);
    int colbase = wn * 32 + (lane & 3) * 2;

    const float spc = 10.0f / 49.0f;
    const float coeff = -0.5f / (spc * spc);
    const int earow = tid >> 2, eaq = tid & 3;   // row 0..127, 16 gaussians per quarter

    // ---- prologue: EA + meta for first tile ----
    {
        int e0 = blockIdx.x * 128;
        float dv = g_sd[e0 + earow];
        u32 h8[8];
#pragma unroll
        for (int jj = 0; jj < 8; jj++) {
            int g = eaq * 16 + 2 * jj;
            float t0 = dv - (float)g * spc;
            float t1 = dv - (float)(g + 1) * spc;
            float v0 = (g < NGAUSS)     ? __expf(coeff * t0 * t0) : 0.0f;
            float v1 = (g + 1 < NGAUSS) ? __expf(coeff * t1 * t1) : 0.0f;
            h8[jj] = pkh2(v0, v1);
        }
        char* rowH = sp + O_A1H + earow * 144 + eaq * 32;
        *(uint4*)(rowH)      = make_uint4(h8[0], h8[1], h8[2], h8[3]);
        *(uint4*)(rowH + 16) = make_uint4(h8[4], h8[5], h8[6], h8[7]);
        if (tid < 128) {
            ssrc[tid] = g_ss[e0 + tid];
            sdst[tid] = g_sdt[e0 + tid];
            sct[tid]  = g_sc[e0 + tid];
        }
    }
    __syncthreads();

    int pb = 0;
    for (int t = blockIdx.x; t < NTILES; t += EGRID, pb ^= 1) {
        float acc[2][4][4];
        ZACC4(acc);
        gemm_2p<4, 144>(acc, A1_b, B1H_b, B1L_b);
        epi_ssp_h(acc, sb1f, sp + O_A2H, r0base, colbase);
        __syncthreads();   // [A] A2 visible for GEMM2; A1 free for next EA

        int nt = t + EGRID;
        bool hasnext = nt < NTILES;
        float dv = 0.f, pm_c = 0.f;
        int pm_s = 0, pm_d = 0;
        if (hasnext) {
            dv = g_sd[nt * 128 + earow];
            if (tid < 128) {
                pm_s = g_ss[nt * 128 + tid];
                pm_d = g_sdt[nt * 128 + tid];
                pm_c = g_sc[nt * 128 + tid];
            }
        }

        ZACC4(acc);
        gemm_2p<8, 272>(acc, A2_b, B2H_b, B2L_b);

        if (hasnext) {
            u32 h8[8];
#pragma unroll
            for (int jj = 0; jj < 8; jj++) {
                int g = eaq * 16 + 2 * jj;
                float t0 = dv - (float)g * spc;
                float t1 = dv - (float)(g + 1) * spc;
                float v0 = (g < NGAUSS)     ? __expf(coeff * t0 * t0) : 0.0f;
                float v1 = (g + 1 < NGAUSS) ? __expf(coeff * t1 * t1) : 0.0f;
                h8[jj] = pkh2(v0, v1);
            }
            char* rowH = sp + O_A1H + earow * 144 + eaq * 32;
            *(uint4*)(rowH)      = make_uint4(h8[0], h8[1], h8[2], h8[3]);
            *(uint4*)(rowH + 16) = make_uint4(h8[4], h8[5], h8[6], h8[7]);
            int nb = (pb ^ 1) * 128;
            if (tid < 128) { ssrc[nb + tid] = pm_s; sdst[nb + tid] = pm_d; sct[nb + tid] = pm_c; }
        }
        __syncthreads();   // [B] GEMM2 A2-reads done; EA/meta visible for next iter

        // ---- epi2: msg = (acc+b2)*C into own MSG bytes ----
        const float* sctp = sct + pb * 128;
#pragma unroll
        for (int mi = 0; mi < 2; mi++) {
#pragma unroll
            for (int rr = 0; rr < 2; rr++) {
                int rt = r0base + mi * 16 + rr * 8;
                float ct = sctp[rt];
#pragma unroll
                for (int ni = 0; ni < 4; ni++) {
                    int cg = colbase + ni * 8;
                    float v0 = (acc[mi][ni][2*rr]     + sb2f[cg])     * ct;
                    float v1 = (acc[mi][ni][2*rr + 1] + sb2f[cg + 1]) * ct;
                    *(float2*)(sp + O_MSG + (u32)rt * 512 + (u32)cg * 4) = make_float2(v0, v1);
                }
            }
        }
        __syncwarp();

        // ---- scatter own 32 rows x 32 cols; 4 row-groups of 8 per warp ----
        {
            const int* sso = ssrc + pb * 128;
            const int* sdo = sdst + pb * 128;
            int grp = lane >> 3, chunk = lane & 7;
            int rbeg = wm * 32 + grp * 8;
            u32 moff = (u32)O_MSG + (u32)(wn * 128) + (u32)(chunk * 16);
            int coff = wn * 32 + chunk * 4;
            float4 a4 = make_float4(0.f, 0.f, 0.f, 0.f);
            int cur = sdo[rbeg];
#pragma unroll
            for (int p4 = 0; p4 < 2; p4++) {
                int r0 = rbeg + p4 * 4;
                int sr[4], sd[4];
#pragma unroll
                for (int j = 0; j < 4; j++) { sr[j] = sso[r0 + j]; sd[j] = sdo[r0 + j]; }
                float4 x[4];
#pragma unroll
                for (int j = 0; j < 4; j++)
                    x[j] = *(const float4*)(g_xl + (size_t)sr[j] * 128 + coff);
#pragma unroll
                for (int j = 0; j < 4; j++) {
                    if (sd[j] != cur) {
                        red4(g_agg + (size_t)cur * 128 + coff, a4.x, a4.y, a4.z, a4.w);
                        a4 = make_float4(0.f, 0.f, 0.f, 0.f);
                        cur = sd[j];
                    }
                    float4 m = *(const float4*)(sp + moff + (u32)(r0 + j) * 512);
                    a4.x += m.x * x[j].x; a4.y += m.y * x[j].y;
                    a4.z += m.z * x[j].z; a4.w += m.w * x[j].w;
                }
            }
            red4(g_agg + (size_t)cur * 128 + coff, a4.x, a4.y, a4.z, a4.w);
        }
    }
}

// ---------------- fused node update: fp16 2-pass, 512 threads ----------------
#define N_A  0
#define N_BH 34816
#define N_BL 69632
#define SMEM_NODEM 104448

__global__ void __launch_bounds__(512, 1) k_node_mma(
        const float* __restrict__ cb2, const float* __restrict__ ib,
        int layer, int has_next) {
    extern __shared__ char sp[];
    const u32 sbase = smem_u32(sp);
    int tid = threadIdx.x, lane = tid & 31, wid = tid >> 5;
    int wm = wid & 3, wn = wid >> 2;
    int row0 = blockIdx.x * 128;

    int a_r = (lane & 7) + ((lane >> 3) & 1) * 8;
    int a_k = (lane >> 4) * 8;
    int b_r = (lane & 7) + (lane >> 4) * 8;
    int b_k = ((lane >> 3) & 1) * 8;
    u32 A_b  = sbase + N_A  + (u32)(wm * 32 + a_r) * 272 + (u32)a_k * 2;
    u32 BH_b = sbase + N_BH + (u32)(wn * 32 + b_r) * 272 + (u32)b_k * 2;
    u32 BL_b = sbase + N_BL + (u32)(wn * 32 + b_r) * 272 + (u32)b_k * 2;
    int r0base  = wm * 32 + (lane >> 2);
    int colbase = wn * 32 + (lane & 3) * 2;

    // ---- A <- fp16(agg); zero agg; B <- cw2 ----
    for (int i = tid; i < 128 * 32; i += 512) {
        int r = i >> 5, c4 = i & 31;
        int row = row0 + r;
        float4 v = make_float4(0.f, 0.f, 0.f, 0.f);
        if (row < NN) {
            float* ap = g_agg + (size_t)row * 128 + c4 * 4;
            v = *(const float4*)ap;
            *(float4*)ap = make_float4(0.f, 0.f, 0.f, 0.f);
        }
        *(uint2*)(sp + N_A + r * 272 + c4 * 8) = make_uint2(pkh2(v.x, v.y), pkh2(v.z, v.w));
    }
    {
        const uint4* bh = (const uint4*)(g_cw2tH + layer * 16384);
        const uint4* bl = (const uint4*)(g_cw2tL + layer * 16384);
        for (int i = tid; i < 2048; i += 512) {
            int n = i >> 4, ch = i & 15;
            *(uint4*)(sp + N_BH + n * 272 + ch * 16) = bh[i];
            *(uint4*)(sp + N_BL + n * 272 + ch * 16) = bl[i];
        }
    }
    __syncthreads();

    float acc[2][4][4];
    ZACC4(acc);
    gemm_2p<8, 272>(acc, A_b, BH_b, BL_b);
    __syncthreads();

    epi_ssp_h(acc, cb2, sp + N_A, r0base, colbase);
    {
        const uint4* bh = (const uint4*)(g_iwtH + layer * 16384);
        const uint4* bl = (const uint4*)(g_iwtL + layer * 16384);
        for (int i = tid; i < 2048; i += 512) {
            int n = i >> 4, ch = i & 15;
            *(uint4*)(sp + N_BH + n * 272 + ch * 16) = bh[i];
            *(uint4*)(sp + N_BL + n * 272 + ch * 16) = bl[i];
        }
    }
    __syncthreads();

    ZACC4(acc);
    gemm_2p<8, 272>(acc, A_b, BH_b, BL_b);
    __syncthreads();

    // ---- epi2: h += acc + ib ; A <- fp16(h_new) ----
#pragma unroll
    for (int mi = 0; mi < 2; mi++) {
        int r0 = r0base + mi * 16;
#pragma unroll
        for (int rr = 0; rr < 2; rr++) {
            int r = r0 + rr * 8;
            int row = row0 + r;
#pragma unroll
            for (int ni = 0; ni < 4; ni++) {
                int c = colbase + ni * 8;
                float v0 = acc[mi][ni][2*rr]     + ib[c];
                float v1 = acc[mi][ni][2*rr + 1] + ib[c + 1];
                float2 hv = make_float2(0.f, 0.f);
                float* hp = g_h + (size_t)row * 128 + c;
                if (row < NN) hv = *(const float2*)hp;
                hv.x += v0; hv.y += v1;
                if (row < NN) *(float2*)hp = hv;
                *(u32*)(sp + N_A + r * 272 + c * 2) = pkh2(hv.x, hv.y);
            }
        }
    }
    if (has_next) {
        const uint4* bh = (const uint4*)(g_cw1tH + (layer + 1) * 16384);
        const uint4* bl = (const uint4*)(g_cw1tL + (layer + 1) * 16384);
        for (int i = tid; i < 2048; i += 512) {
            int n = i >> 4, ch = i & 15;
            *(uint4*)(sp + N_BH + n * 272 + ch * 16) = bh[i];
            *(uint4*)(sp + N_BL + n * 272 + ch * 16) = bl[i];
        }
        __syncthreads();

        ZACC4(acc);
        gemm_2p<8, 272>(acc, A_b, BH_b, BL_b);

#pragma unroll
        for (int mi = 0; mi < 2; mi++) {
            int r0 = r0base + mi * 16;
#pragma unroll
            for (int rr = 0; rr < 2; rr++) {
                int row = row0 + r0 + rr * 8;
                if (row >= NN) continue;
#pragma unroll
                for (int ni = 0; ni < 4; ni++) {
                    int c = colbase + ni * 8;
                    *(float2*)(g_xl + (size_t)row * 128 + c) =
                        make_float2(acc[mi][ni][2*rr], acc[mi][ni][2*rr + 1]);
                }
            }
        }
    }
}

// ---------------- readout ----------------
__global__ void __launch_bounds__(128) k_read(const int* __restrict__ batch,
        const float* __restrict__ lw, const float* __restrict__ lb,
        const float* __restrict__ ew, const float* __restrict__ ebp,
        const float* __restrict__ qw, const float* __restrict__ qbp,
        float* __restrict__ out) {
    extern __shared__ float sm[];
    float* Hs  = sm;
    float* Ws  = Hs + 128 * 129;
    float* sb  = Ws + 128 * 64;
    float* sew = sb + 64;
    float* sqw = sew + 64;
    int tid = threadIdx.x;
    int row0 = blockIdx.x * 128;
    for (int i = tid; i < 128 * 128; i += 128) {
        int r = i >> 7, c = i & 127;
        int row = row0 + r;
        Hs[r * 129 + c] = (row < NN) ? g_h[(size_t)row * 128 + c] : 0.f;
    }
    for (int i = tid; i < 128 * 64; i += 128) Ws[i] = lw[i];
    if (tid < 64) { sb[tid] = lb[tid]; sew[tid] = ew[tid]; sqw[tid] = qw[tid]; }
    __syncthreads();
    int row = row0 + tid;
    if (row >= NN) return;
    float e = ebp[0], q = qbp[0];
    const float* hr = Hs + tid * 129;
#pragma unroll 2
    for (int j = 0; j < 64; j++) {
        float a = sb[j];
#pragma unroll 8
        for (int k = 0; k < 128; k++) a += hr[k] * Ws[k * 64 + j];
        float hh = ssp(a);
        e += hh * sew[j];
        q += hh * sqw[j];
    }
    out[row] = e;
    out[NN + row] = q;
    int b = batch[row];
    atomicAdd(out + 2 * NN + b, e);
    atomicAdd(out + 2 * NN + GG + b, q);
}

// ---------------- host ----------------
extern "C" void kernel_launch(void* const* d_in, const int* in_sizes, int n_in,
                              void* d_out, int out_size) {
    const int*   atoms = (const int*)d_in[0];
    const float* pos   = (const float*)d_in[1];
    const int*   batch = (const int*)d_in[2];
    const int*   ei    = (const int*)d_in[3];
    const float* emb   = (const float*)d_in[4];
    const float* mw1   = (const float*)d_in[5];
    const float* mb1   = (const float*)d_in[6];
    const float* mw2   = (const float*)d_in[7];
    const float* mb2   = (const float*)d_in[8];
    const float* cw1   = (const float*)d_in[9];
    const float* cw2   = (const float*)d_in[10];
    const float* cb2   = (const float*)d_in[11];
    const float* iw    = (const float*)d_in[12];
    const float* ib    = (const float*)d_in[13];
    const float* l1w   = (const float*)d_in[14];
    const float* l1b   = (const float*)d_in[15];
    const float* ew    = (const float*)d_in[16];
    const float* eb    = (const float*)d_in[17];
    const float* qw    = (const float*)d_in[18];
    const float* qb    = (const float*)d_in[19];
    float* out = (float*)d_out;

    constexpr int SMEM_GEMM = (128 * 132 + 128 * 128) * 4;
    constexpr int SMEM_READ = (128 * 129 + 128 * 64 + 192) * 4;

    cudaFuncSetAttribute(k_scan_xl,  cudaFuncAttributeMaxDynamicSharedMemorySize, SMEM_GEMM);
    cudaFuncSetAttribute(k_edge_mma, cudaFuncAttributeMaxDynamicSharedMemorySize, SMEM_EDGE);
    cudaFuncSetAttribute(k_node_mma, cudaFuncAttributeMaxDynamicSharedMemorySize, SMEM_NODEM);
    cudaFuncSetAttribute(k_read,     cudaFuncAttributeMaxDynamicSharedMemorySize, SMEM_READ);

    const int NODE_BLOCKS = (NN + 127) / 128;   // 391

    k_prep_init<<<EE / 256, 256>>>(pos, ei, atoms, emb, mw1, mw2, cw2, iw, cw1, out);
    k_scan_xl<<<NODE_BLOCKS + 1, 256, SMEM_GEMM>>>(cw1);
    k_permute<<<EE / 256, 256>>>(ei);

    for (int l = 0; l < NLAYER; l++) {
        k_edge_mma<<<EGRID, 512, SMEM_EDGE>>>(l, mb1 + (size_t)l * FF, mb2 + (size_t)l * FF);
        k_node_mma<<<NODE_BLOCKS, 512, SMEM_NODEM>>>(cb2 + (size_t)l * HH, ib + (size_t)l * HH,
                                                     l, (l < NLAYER - 1) ? 1 : 0);
    }
    k_read<<<NODE_BLOCKS, 128, SMEM_READ>>>(batch, l1w, l1b, ew, eb, qw, qb, out);
}

// round 9
// speedup vs baseline: 3.8255x; 1.2118x over previous
#include <cuda_runtime.h>
#include <cuda_fp16.h>
#include <cstdint>

#define NN 50000
#define EE 800000
#define GG 100
#define HH 128
#define FF 128
#define NGAUSS 50
#define NLAYER 6
#define NTILES (EE / 128)   // 6250
#define EGRID 148

typedef unsigned long long u64;
typedef unsigned int u32;

// ---------------- scratch (static device globals; no allocation) ----------------
__device__ float g_dist[EE];
__device__ float g_C[EE];
__device__ int   g_cnt[NN];     // re-zeroed by k_scan_xl each run
__device__ int   g_cur[NN];
__device__ float g_sd[EE];
__device__ float g_sc[EE];
__device__ int   g_ss[EE];
__device__ int   g_sdt[EE];
__device__ float g_h[(size_t)NN * HH];
__device__ float g_xl[(size_t)NN * FF];
__device__ float g_agg[(size_t)NN * FF];
// weights, fp16, [n][k] layout
__device__ __half g_w1t[NLAYER * 128 * 64];
__device__ __half g_w2t[NLAYER * 128 * 128];
__device__ __half g_cw2t[NLAYER * 128 * 128];
__device__ __half g_iwt[NLAYER * 128 * 128];
__device__ __half g_cw1t[NLAYER * 128 * 128];

// ---------------- generic helpers ----------------
__device__ __forceinline__ u64 pk2(float x, float y) {
    u64 r; asm("mov.b64 %0, {%1,%2};" : "=l"(r) : "f"(x), "f"(y)); return r;
}
__device__ __forceinline__ void fma2(u64& d, u64 a, u64 b) {
    asm("fma.rn.f32x2 %0, %1, %2, %0;" : "+l"(d) : "l"(a), "l"(b));
}
__device__ __forceinline__ float2 up2(u64 v) {
    float2 r; asm("mov.b64 {%0,%1}, %2;" : "=f"(r.x), "=f"(r.y) : "l"(v)); return r;
}
__device__ __forceinline__ void red4(float* p, float a, float b, float c, float d) {
    asm volatile("red.global.add.v4.f32 [%0], {%1,%2,%3,%4};"
                 :: "l"(p), "f"(a), "f"(b), "f"(c), "f"(d) : "memory");
}
__device__ __forceinline__ float ssp(float x) {
    return fmaxf(x, 0.0f) + __logf(1.0f + __expf(-fabsf(x))) - 0.69314718055994530942f;
}
__device__ __forceinline__ u32 smem_u32(const void* p) {
    u32 a; asm("{ .reg .u64 t; cvta.to.shared.u64 t, %1; cvt.u32.u64 %0, t; }" : "=r"(a) : "l"(p));
    return a;
}
__device__ __forceinline__ u32 pkh2(float x, float y) {
    __half2 t = __floats2half2_rn(x, y); return *(u32*)&t;
}

// ---------------- mma.sync fp16 helpers ----------------
__device__ __forceinline__ void ldmx4(u32* r, u32 addr) {
    asm volatile("ldmatrix.sync.aligned.m8n8.x4.shared.b16 {%0,%1,%2,%3}, [%4];"
                 : "=r"(r[0]), "=r"(r[1]), "=r"(r[2]), "=r"(r[3]) : "r"(addr));
}
__device__ __forceinline__ void mma16816(float* c, const u32* a, const u32* b) {
    asm volatile("mma.sync.aligned.m16n8k16.row.col.f32.f16.f16.f32 "
                 "{%0,%1,%2,%3}, {%4,%5,%6,%7}, {%8,%9}, {%0,%1,%2,%3};"
                 : "+f"(c[0]), "+f"(c[1]), "+f"(c[2]), "+f"(c[3])
                 : "r"(a[0]), "r"(a[1]), "r"(a[2]), "r"(a[3]), "r"(b[0]), "r"(b[1]));
}

#define ZACC4(acc) do { \
    _Pragma("unroll") for (int _m = 0; _m < 2; _m++) \
    _Pragma("unroll") for (int _n = 0; _n < 4; _n++) \
    _Pragma("unroll") for (int _q = 0; _q < 4; _q++) acc[_m][_n][_q] = 0.0f; } while (0)

// single-pass fp16 GEMM, warp tile 32x32 (2 m-frags x 2 n-frags)
template<int KS, int STRIDE>
__device__ __forceinline__ void gemm_1p(float acc[2][4][4], u32 Ab, u32 Bb) {
#pragma unroll
    for (int ks = 0; ks < KS; ks++) {
        u32 ah[2][4], bh[2][4];
        ldmx4(ah[0], Ab + ks * 32);
        ldmx4(ah[1], Ab + 16 * STRIDE + ks * 32);
        ldmx4(bh[0], Bb + ks * 32);
        ldmx4(bh[1], Bb + 16 * STRIDE + ks * 32);
#pragma unroll
        for (int mi = 0; mi < 2; mi++)
#pragma unroll
            for (int nb = 0; nb < 2; nb++) {
                mma16816(acc[mi][2*nb],   ah[mi], &bh[nb][0]);
                mma16816(acc[mi][2*nb+1], ah[mi], &bh[nb][2]);
            }
    }
}

// epilogue: ssp(acc + bias) -> fp16 into 272B-stride A buffer (own 32x32 subtile)
__device__ __forceinline__ void epi_ssp_h(const float acc[2][4][4],
        const float* bias, char* aH, int r0base, int colbase) {
#pragma unroll
    for (int mi = 0; mi < 2; mi++) {
        int r0 = r0base + mi * 16;
#pragma unroll
        for (int ni = 0; ni < 4; ni++) {
            int c = colbase + ni * 8;
            float bb0 = bias[c], bb1 = bias[c + 1];
            *(u32*)(aH + r0 * 272 + c * 2) =
                pkh2(ssp(acc[mi][ni][0] + bb0), ssp(acc[mi][ni][1] + bb1));
            *(u32*)(aH + (r0 + 8) * 272 + c * 2) =
                pkh2(ssp(acc[mi][ni][2] + bb0), ssp(acc[mi][ni][3] + bb1));
        }
    }
}

// ---------------- launch 1: weights + dist/C/hist + h init + out tail ----------------
__global__ void __launch_bounds__(256) k_prep_init(
        const float* __restrict__ pos, const int* __restrict__ ei,
        const int* __restrict__ atoms, const float* __restrict__ emb,
        const float* __restrict__ mw1, const float* __restrict__ mw2,
        const float* __restrict__ cw2, const float* __restrict__ iw,
        const float* __restrict__ cw1, float* __restrict__ out) {
    int idx = blockIdx.x * 256 + threadIdx.x;   // 0..EE-1
    if (idx < NLAYER * 128 * 128) {
        int l = idx >> 14, r = idx & 16383, n = r >> 7, k = r & 127;
        int sidx = (l * 128 + k) * 128 + n;
        g_w2t[idx]  = __float2half_rn(mw2[sidx]);
        g_cw2t[idx] = __float2half_rn(cw2[sidx]);
        g_iwt[idx]  = __float2half_rn(iw[sidx]);
        g_cw1t[idx] = __float2half_rn(cw1[sidx]);
    }
    if (idx < NLAYER * 128 * 64) {
        int l = idx >> 13, r = idx & 8191, n = r >> 6, k = r & 63;
        float v = (k < NGAUSS) ? mw1[(l * NGAUSS + k) * 128 + n] : 0.0f;
        g_w1t[idx] = __float2half_rn(v);
    }
    if (idx < 2 * GG) out[2 * NN + idx] = 0.0f;
    {
        int e = idx;
        int s = ei[e], d = ei[EE + e];
        float dx = pos[3*s]   - pos[3*d];
        float dy = pos[3*s+1] - pos[3*d+1];
        float dz = pos[3*s+2] - pos[3*d+2];
        float dist = sqrtf(dx*dx + dy*dy + dz*dz);
        g_dist[e] = dist;
        g_C[e] = 0.5f * (__cosf(dist * (3.14159265358979323846f / 10.0f)) + 1.0f);
        atomicAdd(&g_cnt[d], 1);
    }
    for (int j = idx; j < NN * 32; j += EE)
        ((float4*)g_h)[j] = ((const float4*)emb)[atoms[j >> 5] * 32 + (j & 31)];
}

// ---------------- fp32 f32x2 GEMM (layer-0 xl inside k_scan_xl) ----------------
template<int K>
__device__ __forceinline__ void gemm_tile(const float* __restrict__ As,
                                          const float* __restrict__ Bs,
                                          int ty, int tx, u64 acc[8][4]) {
    const float* ap = As + ty * 8;
    const float* bp = Bs + tx * 8;
#pragma unroll 4
    for (int k = 0; k < K; k++) {
        float4 a0 = *(const float4*)(ap + k * 132);
        float4 a1 = *(const float4*)(ap + k * 132 + 4);
        float4 b0 = *(const float4*)(bp + k * 128);
        float4 b1 = *(const float4*)(bp + k * 128 + 4);
        u64 bb0 = pk2(b0.x, b0.y), bb1 = pk2(b0.z, b0.w);
        u64 bb2 = pk2(b1.x, b1.y), bb3 = pk2(b1.z, b1.w);
        float a[8] = {a0.x, a0.y, a0.z, a0.w, a1.x, a1.y, a1.z, a1.w};
#pragma unroll
        for (int i = 0; i < 8; i++) {
            u64 aa = pk2(a[i], a[i]);
            fma2(acc[i][0], aa, bb0);
            fma2(acc[i][1], aa, bb1);
            fma2(acc[i][2], aa, bb2);
            fma2(acc[i][3], aa, bb3);
        }
    }
}
#define ZERO_ACC8(acc) do { \
    _Pragma("unroll") for (int _i = 0; _i < 8; _i++) \
    _Pragma("unroll") for (int _j = 0; _j < 4; _j++) acc[_i][_j] = 0ull; } while (0)

// ---------------- launch 2: block 0 = scan (+ re-zero g_cnt), blocks 1.. = xl ----------------
__global__ void __launch_bounds__(256) k_scan_xl(const float* __restrict__ W) {
    if (blockIdx.x == 0) {
        __shared__ int warp_sums[8];
        __shared__ int s_carry;
        int tid = threadIdx.x;
        if (tid == 0) s_carry = 0;
        __syncthreads();
        for (int base = 0; base < NN; base += 256) {
            int i = base + tid;
            int v = (i < NN) ? g_cnt[i] : 0;
            int incl = v;
#pragma unroll
            for (int off = 1; off < 32; off <<= 1) {
                int n = __shfl_up_sync(0xffffffff, incl, off);
                if ((tid & 31) >= off) incl += n;
            }
            if ((tid & 31) == 31) warp_sums[tid >> 5] = incl;
            __syncthreads();
            if (tid < 8) {
                int ws = warp_sums[tid];
                int wi = ws;
#pragma unroll
                for (int off = 1; off < 8; off <<= 1) {
                    int n = __shfl_up_sync(0x000000ff, wi, off);
                    if (tid >= off) wi += n;
                }
                warp_sums[tid] = wi - ws;
            }
            __syncthreads();
            int excl = s_carry + warp_sums[tid >> 5] + incl - v;
            if (i < NN) g_cur[i] = excl;
            __syncthreads();
            if (tid == 255) s_carry = excl + v;
            __syncthreads();
        }
        for (int i = tid; i < NN; i += 256) g_cnt[i] = 0;
        return;
    }
    extern __shared__ float sm[];
    float* As = sm;
    float* Bs = As + 128 * 132;
    int tid = threadIdx.x, ty = tid >> 4, tx = tid & 15;
    int row0 = (blockIdx.x - 1) * 128;
    for (int i = tid; i < 128 * 32; i += 256) {
        int r = i & 127, kq = i >> 7;
        float4 v = make_float4(0.f, 0.f, 0.f, 0.f);
        int row = row0 + r;
        if (row < NN) v = *(const float4*)(g_h + (size_t)row * 128 + kq * 4);
        As[(kq*4+0)*132 + r] = v.x;
        As[(kq*4+1)*132 + r] = v.y;
        As[(kq*4+2)*132 + r] = v.z;
        As[(kq*4+3)*132 + r] = v.w;
    }
    for (int i = tid; i < 128 * 32; i += 256)
        ((float4*)Bs)[i] = ((const float4*)W)[i];
    __syncthreads();
    u64 acc[8][4]; ZERO_ACC8(acc);
    gemm_tile<128>(As, Bs, ty, tx, acc);
#pragma unroll
    for (int i = 0; i < 8; i++) {
        int row = row0 + ty * 8 + i;
        if (row >= NN) continue;
        float v[8];
#pragma unroll
        for (int jp = 0; jp < 4; jp++) { float2 t2 = up2(acc[i][jp]); v[2*jp] = t2.x; v[2*jp+1] = t2.y; }
        *(float4*)(g_xl + (size_t)row * 128 + tx * 8)     = make_float4(v[0], v[1], v[2], v[3]);
        *(float4*)(g_xl + (size_t)row * 128 + tx * 8 + 4) = make_float4(v[4], v[5], v[6], v[7]);
    }
}

// ---------------- launch 3: permute edges into dst-sorted order ----------------
__global__ void __launch_bounds__(256) k_permute(const int* __restrict__ ei) {
    int e = blockIdx.x * 256 + threadIdx.x;
    if (e >= EE) return;
    int d = ei[EE + e];
    int pos = atomicAdd(&g_cur[d], 1);
    g_sd[pos]  = g_dist[e];
    g_sc[pos]  = g_C[e];
    g_ss[pos]  = ei[e];
    g_sdt[pos] = d;
}

// ---------------- edge pipeline: fp16 1-pass, windowed EA, 512 threads ----------------
#define O_A1  0
#define O_B1  18432
#define O_A2  36864            // stride 272B
#define O_B2  71680
#define O_MSG 106496           // 128 rows x 512B (fp32 msg)
#define O_SB1 172032
#define O_SB2 172544
#define O_SCT 173056           // [2][128] f32
#define O_SRC 174080           // [2][128] i32
#define O_SDST 175104          // [2][128] i32
#define SMEM_EDGE 176128

// windowed gaussian row fill: values with |d-g*sp| > 6.5*sp round to 0 in fp16
__device__ __forceinline__ void ea_row_fill(char* rowH, float dv) {
    const float spc = 10.0f / 49.0f;
    const float coeff = -0.5f / (spc * spc);
#pragma unroll
    for (int q = 0; q < 8; q++) *(uint4*)(rowH + q * 16) = make_uint4(0, 0, 0, 0);
    float gf = dv * (49.0f / 10.0f);
    int gbeg = (int)(gf - 6.5f) + 1;   // ceil for positive; negative clamped below
    if (gbeg < 0) gbeg = 0;
    int gend = (int)(gf + 6.5f);
    if (gend > NGAUSS - 1) gend = NGAUSS - 1;
    for (int g = gbeg; g <= gend; g++) {
        float t = dv - (float)g * spc;
        *(__half*)(rowH + g * 2) = __float2half_rn(__expf(coeff * t * t));
    }
}

__global__ void __launch_bounds__(512, 1) k_edge_mma(
        int layer, const float* __restrict__ b1, const float* __restrict__ b2) {
    extern __shared__ char sp[];
    const u32 sbase = smem_u32(sp);
    int tid = threadIdx.x, lane = tid & 31, wid = tid >> 5;   // wid 0..15
    int wm = wid & 3, wn = wid >> 2;

    float* sb1f = (float*)(sp + O_SB1);
    float* sb2f = (float*)(sp + O_SB2);
    float* sct  = (float*)(sp + O_SCT);
    int*   ssrc = (int*)(sp + O_SRC);
    int*   sdst = (int*)(sp + O_SDST);

    // ---- weights to SMEM (once per launch) ----
    {
        const uint4* w1 = (const uint4*)(g_w1t + layer * 8192);
        for (int i = tid; i < 1024; i += 512) {
            int n = i >> 3, ch = i & 7;
            *(uint4*)(sp + O_B1 + n * 144 + ch * 16) = w1[i];
        }
        const uint4* w2 = (const uint4*)(g_w2t + layer * 16384);
        for (int i = tid; i < 2048; i += 512) {
            int n = i >> 4, ch = i & 15;
            *(uint4*)(sp + O_B2 + n * 272 + ch * 16) = w2[i];
        }
        if (tid < 128) { sb1f[tid] = b1[tid]; sb2f[tid] = b2[tid]; }
    }

    int a_r = (lane & 7) + ((lane >> 3) & 1) * 8;
    int a_k = (lane >> 4) * 8;
    int b_r = (lane & 7) + (lane >> 4) * 8;
    int b_k = ((lane >> 3) & 1) * 8;

    u32 A1_b = sbase + O_A1 + (u32)(wm * 32 + a_r) * 144 + (u32)a_k * 2;
    u32 B1_b = sbase + O_B1 + (u32)(wn * 32 + b_r) * 144 + (u32)b_k * 2;
    u32 A2_b = sbase + O_A2 + (u32)(wm * 32 + a_r) * 272 + (u32)a_k * 2;
    u32 B2_b = sbase + O_B2 + (u32)(wn * 32 + b_r) * 272 + (u32)b_k * 2;

    int r0base  = wm * 32 + (lane >> 2);
    int colbase = wn * 32 + (lane & 3) * 2;

    // ---- prologue: EA + meta for first tile ----
    if (tid < 128) {
        int e0 = blockIdx.x * 128;
        ea_row_fill(sp + O_A1 + tid * 144, g_sd[e0 + tid]);
        ssrc[tid] = g_ss[e0 + tid];
        sdst[tid] = g_sdt[e0 + tid];
        sct[tid]  = g_sc[e0 + tid];
    }
    __syncthreads();

    int pb = 0;
    for (int t = blockIdx.x; t < NTILES; t += EGRID, pb ^= 1) {
        float acc[2][4][4];
        ZACC4(acc);
        gemm_1p<4, 144>(acc, A1_b, B1_b);
        epi_ssp_h(acc, sb1f, sp + O_A2, r0base, colbase);
        __syncthreads();   // [A] A2 visible for GEMM2; A1 free for next EA

        int nt = t + EGRID;
        bool hasnext = nt < NTILES;
        float dv = 0.f, pm_c = 0.f;
        int pm_s = 0, pm_d = 0;
        if (hasnext && tid < 128) {
            dv   = g_sd[nt * 128 + tid];
            pm_s = g_ss[nt * 128 + tid];
            pm_d = g_sdt[nt * 128 + tid];
            pm_c = g_sc[nt * 128 + tid];
        }

        ZACC4(acc);
        gemm_1p<8, 272>(acc, A2_b, B2_b);

        if (hasnext && tid < 128) {
            ea_row_fill(sp + O_A1 + tid * 144, dv);
            int nb = (pb ^ 1) * 128;
            ssrc[nb + tid] = pm_s; sdst[nb + tid] = pm_d; sct[nb + tid] = pm_c;
        }
        __syncthreads();   // [B] GEMM2 A2-reads done; EA/meta visible for next iter

        // ---- epi2: msg = (acc+b2)*C into own MSG bytes ----
        const float* sctp = sct + pb * 128;
#pragma unroll
        for (int mi = 0; mi < 2; mi++) {
#pragma unroll
            for (int rr = 0; rr < 2; rr++) {
                int rt = r0base + mi * 16 + rr * 8;
                float ct = sctp[rt];
#pragma unroll
                for (int ni = 0; ni < 4; ni++) {
                    int cg = colbase + ni * 8;
                    float v0 = (acc[mi][ni][2*rr]     + sb2f[cg])     * ct;
                    float v1 = (acc[mi][ni][2*rr + 1] + sb2f[cg + 1]) * ct;
                    *(float2*)(sp + O_MSG + (u32)rt * 512 + (u32)cg * 4) = make_float2(v0, v1);
                }
            }
        }
        __syncwarp();

        // ---- scatter own 32 rows x 32 cols; 4 row-groups of 8 per warp ----
        {
            const int* sso = ssrc + pb * 128;
            const int* sdo = sdst + pb * 128;
            int grp = lane >> 3, chunk = lane & 7;
            int rbeg = wm * 32 + grp * 8;
            u32 moff = (u32)O_MSG + (u32)(wn * 128) + (u32)(chunk * 16);
            int coff = wn * 32 + chunk * 4;
            float4 a4 = make_float4(0.f, 0.f, 0.f, 0.f);
            int cur = sdo[rbeg];
#pragma unroll
            for (int p4 = 0; p4 < 2; p4++) {
                int r0 = rbeg + p4 * 4;
                int sr[4], sd[4];
#pragma unroll
                for (int j = 0; j < 4; j++) { sr[j] = sso[r0 + j]; sd[j] = sdo[r0 + j]; }
                float4 x[4];
#pragma unroll
                for (int j = 0; j < 4; j++)
                    x[j] = *(const float4*)(g_xl + (size_t)sr[j] * 128 + coff);
#pragma unroll
                for (int j = 0; j < 4; j++) {
                    if (sd[j] != cur) {
                        red4(g_agg + (size_t)cur * 128 + coff, a4.x, a4.y, a4.z, a4.w);
                        a4 = make_float4(0.f, 0.f, 0.f, 0.f);
                        cur = sd[j];
                    }
                    float4 m = *(const float4*)(sp + moff + (u32)(r0 + j) * 512);
                    a4.x += m.x * x[j].x; a4.y += m.y * x[j].y;
                    a4.z += m.z * x[j].z; a4.w += m.w * x[j].w;
                }
            }
            red4(g_agg + (size_t)cur * 128 + coff, a4.x, a4.y, a4.z, a4.w);
        }
    }
}

// ---------------- fused node update: fp16 1-pass, 512 threads ----------------
#define N_A  0
#define N_B  34816
#define SMEM_NODEM 69632

__global__ void __launch_bounds__(512, 1) k_node_mma(
        const float* __restrict__ cb2, const float* __restrict__ ib,
        int layer, int has_next) {
    extern __shared__ char sp[];
    const u32 sbase = smem_u32(sp);
    int tid = threadIdx.x, lane = tid & 31, wid = tid >> 5;
    int wm = wid & 3, wn = wid >> 2;
    int row0 = blockIdx.x * 128;

    int a_r = (lane & 7) + ((lane >> 3) & 1) * 8;
    int a_k = (lane >> 4) * 8;
    int b_r = (lane & 7) + (lane >> 4) * 8;
    int b_k = ((lane >> 3) & 1) * 8;
    u32 A_b = sbase + N_A + (u32)(wm * 32 + a_r) * 272 + (u32)a_k * 2;
    u32 B_b = sbase + N_B + (u32)(wn * 32 + b_r) * 272 + (u32)b_k * 2;
    int r0base  = wm * 32 + (lane >> 2);
    int colbase = wn * 32 + (lane & 3) * 2;

    // ---- A <- fp16(agg); zero agg; B <- cw2 ----
    for (int i = tid; i < 128 * 32; i += 512) {
        int r = i >> 5, c4 = i & 31;
        int row = row0 + r;
        float4 v = make_float4(0.f, 0.f, 0.f, 0.f);
        if (row < NN) {
            float* ap = g_agg + (size_t)row * 128 + c4 * 4;
            v = *(const float4*)ap;
            *(float4*)ap = make_float4(0.f, 0.f, 0.f, 0.f);
        }
        *(uint2*)(sp + N_A + r * 272 + c4 * 8) = make_uint2(pkh2(v.x, v.y), pkh2(v.z, v.w));
    }
    {
        const uint4* bh = (const uint4*)(g_cw2t + layer * 16384);
        for (int i = tid; i < 2048; i += 512) {
            int n = i >> 4, ch = i & 15;
            *(uint4*)(sp + N_B + n * 272 + ch * 16) = bh[i];
        }
    }
    __syncthreads();

    float acc[2][4][4];
    ZACC4(acc);
    gemm_1p<8, 272>(acc, A_b, B_b);
    __syncthreads();

    epi_ssp_h(acc, cb2, sp + N_A, r0base, colbase);
    {
        const uint4* bh = (const uint4*)(g_iwt + layer * 16384);
        for (int i = tid; i < 2048; i += 512) {
            int n = i >> 4, ch = i & 15;
            *(uint4*)(sp + N_B + n * 272 + ch * 16) = bh[i];
        }
    }
    __syncthreads();

    ZACC4(acc);
    gemm_1p<8, 272>(acc, A_b, B_b);
    __syncthreads();

    // ---- epi2: h += acc + ib ; A <- fp16(h_new) ----
#pragma unroll
    for (int mi = 0; mi < 2; mi++) {
        int r0 = r0base + mi * 16;
#pragma unroll
        for (int rr = 0; rr < 2; rr++) {
            int r = r0 + rr * 8;
            int row = row0 + r;
#pragma unroll
            for (int ni = 0; ni < 4; ni++) {
                int c = colbase + ni * 8;
                float v0 = acc[mi][ni][2*rr]     + ib[c];
                float v1 = acc[mi][ni][2*rr + 1] + ib[c + 1];
                float2 hv = make_float2(0.f, 0.f);
                float* hp = g_h + (size_t)row * 128 + c;
                if (row < NN) hv = *(const float2*)hp;
                hv.x += v0; hv.y += v1;
                if (row < NN) *(float2*)hp = hv;
                *(u32*)(sp + N_A + r * 272 + c * 2) = pkh2(hv.x, hv.y);
            }
        }
    }
    if (has_next) {
        const uint4* bh = (const uint4*)(g_cw1t + (layer + 1) * 16384);
        for (int i = tid; i < 2048; i += 512) {
            int n = i >> 4, ch = i & 15;
            *(uint4*)(sp + N_B + n * 272 + ch * 16) = bh[i];
        }
        __syncthreads();

        ZACC4(acc);
        gemm_1p<8, 272>(acc, A_b, B_b);

#pragma unroll
        for (int mi = 0; mi < 2; mi++) {
            int r0 = r0base + mi * 16;
#pragma unroll
            for (int rr = 0; rr < 2; rr++) {
                int row = row0 + r0 + rr * 8;
                if (row >= NN) continue;
#pragma unroll
                for (int ni = 0; ni < 4; ni++) {
                    int c = colbase + ni * 8;
                    *(float2*)(g_xl + (size_t)row * 128 + c) =
                        make_float2(acc[mi][ni][2*rr], acc[mi][ni][2*rr + 1]);
                }
            }
        }
    }
}

// ---------------- readout ----------------
__global__ void __launch_bounds__(128) k_read(const int* __restrict__ batch,
        const float* __restrict__ lw, const float* __restrict__ lb,
        const float* __restrict__ ew, const float* __restrict__ ebp,
        const float* __restrict__ qw, const float* __restrict__ qbp,
        float* __restrict__ out) {
    extern __shared__ float sm[];
    float* Hs  = sm;
    float* Ws  = Hs + 128 * 129;
    float* sb  = Ws + 128 * 64;
    float* sew = sb + 64;
    float* sqw = sew + 64;
    int tid = threadIdx.x;
    int row0 = blockIdx.x * 128;
    for (int i = tid; i < 128 * 128; i += 128) {
        int r = i >> 7, c = i & 127;
        int row = row0 + r;
        Hs[r * 129 + c] = (row < NN) ? g_h[(size_t)row * 128 + c] : 0.f;
    }
    for (int i = tid; i < 128 * 64; i += 128) Ws[i] = lw[i];
    if (tid < 64) { sb[tid] = lb[tid]; sew[tid] = ew[tid]; sqw[tid] = qw[tid]; }
    __syncthreads();
    int row = row0 + tid;
    if (row >= NN) return;
    float e = ebp[0], q = qbp[0];
    const float* hr = Hs + tid * 129;
#pragma unroll 2
    for (int j = 0; j < 64; j++) {
        float a = sb[j];
#pragma unroll 8
        for (int k = 0; k < 128; k++) a += hr[k] * Ws[k * 64 + j];
        float hh = ssp(a);
        e += hh * sew[j];
        q += hh * sqw[j];
    }
    out[row] = e;
    out[NN + row] = q;
    int b = batch[row];
    atomicAdd(out + 2 * NN + b, e);
    atomicAdd(out + 2 * NN + GG + b, q);
}

// ---------------- host ----------------
extern "C" void kernel_launch(void* const* d_in, const int* in_sizes, int n_in,
                              void* d_out, int out_size) {
    const int*   atoms = (const int*)d_in[0];
    const float* pos   = (const float*)d_in[1];
    const int*   batch = (const int*)d_in[2];
    const int*   ei    = (const int*)d_in[3];
    const float* emb   = (const float*)d_in[4];
    const float* mw1   = (const float*)d_in[5];
    const float* mb1   = (const float*)d_in[6];
    const float* mw2   = (const float*)d_in[7];
    const float* mb2   = (const float*)d_in[8];
    const float* cw1   = (const float*)d_in[9];
    const float* cw2   = (const float*)d_in[10];
    const float* cb2   = (const float*)d_in[11];
    const float* iw    = (const float*)d_in[12];
    const float* ib    = (const float*)d_in[13];
    const float* l1w   = (const float*)d_in[14];
    const float* l1b   = (const float*)d_in[15];
    const float* ew    = (const float*)d_in[16];
    const float* eb    = (const float*)d_in[17];
    const float* qw    = (const float*)d_in[18];
    const float* qb    = (const float*)d_in[19];
    float* out = (float*)d_out;

    constexpr int SMEM_GEMM = (128 * 132 + 128 * 128) * 4;
    constexpr int SMEM_READ = (128 * 129 + 128 * 64 + 192) * 4;

    cudaFuncSetAttribute(k_scan_xl,  cudaFuncAttributeMaxDynamicSharedMemorySize, SMEM_GEMM);
    cudaFuncSetAttribute(k_edge_mma, cudaFuncAttributeMaxDynamicSharedMemorySize, SMEM_EDGE);
    cudaFuncSetAttribute(k_node_mma, cudaFuncAttributeMaxDynamicSharedMemorySize, SMEM_NODEM);
    cudaFuncSetAttribute(k_read,     cudaFuncAttributeMaxDynamicSharedMemorySize, SMEM_READ);

    const int NODE_BLOCKS = (NN + 127) / 128;   // 391

    k_prep_init<<<EE / 256, 256>>>(pos, ei, atoms, emb, mw1, mw2, cw2, iw, cw1, out);
    k_scan_xl<<<NODE_BLOCKS + 1, 256, SMEM_GEMM>>>(cw1);
    k_permute<<<EE / 256, 256>>>(ei);

    for (int l = 0; l < NLAYER; l++) {
        k_edge_mma<<<EGRID, 512, SMEM_EDGE>>>(l, mb1 + (size_t)l * FF, mb2 + (size_t)l * FF);
        k_node_mma<<<NODE_BLOCKS, 512, SMEM_NODEM>>>(cb2 + (size_t)l * HH, ib + (size_t)l * HH,
                                                     l, (l < NLAYER - 1) ? 1 : 0);
    }
    k_read<<<NODE_BLOCKS, 128, SMEM_READ>>>(batch, l1w, l1b, ew, eb, qw, qb, out);
}